// round 1
// baseline (speedup 1.0000x reference)
#include <cuda_runtime.h>
#include <cuda_bf16.h>
#include <math.h>

// ---------------------------------------------------------------------------
// TGN_GAT: 2-layer GAT (N=50000, E=800000, F=64, HID=64, HEADS=4)
// Pipeline:
//   x   = nf @ projW + proj_b + type_emb[types]
//   CSR build over (edges + self loops), grouped by dst
//   xp0 = x @ W0;  a_s0/a_d0;  agg0 (online segment softmax, concat heads)
//   h0  = relu(LN(agg0 + bias0))
//   xp1 = h0 @ W1; a_s1/a_d1;  agg1;  out = relu(LN(mean_heads(agg1)+bias1))
// ---------------------------------------------------------------------------

#define MAXN 50000
#define MAXE 800000
#define MAXTOT (MAXE + MAXN)

// scratch (global memory, zero-init at load; we fully overwrite what we read)
__device__ float g_x[(size_t)MAXN * 64];
__device__ float g_xp[(size_t)MAXN * 256];
__device__ float g_h[(size_t)MAXN * 256];
__device__ float g_hraw[(size_t)MAXN * 256];
__device__ float g_as[(size_t)MAXN * 4];
__device__ float g_ad[(size_t)MAXN * 4];
__device__ int   g_rowptr[MAXN + 1];
__device__ int   g_cursor[MAXN];
__device__ int   g_counts[MAXN];
__device__ int   g_col[MAXTOT];

// ---------------------------------------------------------------------------
// Tiled SGEMM: C[M,Nc] = A[M,K] @ B[K,Nc].  K % 16 == 0, Nc % 64 == 0.
// Block tile 64x64, BK=16, 256 threads, 4x4 per thread.
// ---------------------------------------------------------------------------
__global__ __launch_bounds__(256) void sgemm_kernel(
    const float* __restrict__ A, const float* __restrict__ B,
    float* __restrict__ C, int M, int K, int Nc)
{
    __shared__ float As[16][65];
    __shared__ float Bs[16][64];

    const int tid = threadIdx.x;
    const int tx = tid & 15;        // 0..15 -> col group
    const int ty = tid >> 4;        // 0..15 -> row group
    const int rowBase = blockIdx.y * 64;
    const int colBase = blockIdx.x * 64;

    // A load map: thread -> row ar (0..63), k-offset ak (0,4,8,12), float4
    const int ar = tid >> 2;
    const int ak = (tid & 3) << 2;
    // B load map: thread -> k-row bk (0..15), col offset bn (0..60 step 4)
    const int bk = tid >> 4;
    const int bn = (tid & 15) << 2;

    float4 acc0 = make_float4(0.f, 0.f, 0.f, 0.f);
    float4 acc1 = acc0, acc2 = acc0, acc3 = acc0;

    for (int k0 = 0; k0 < K; k0 += 16) {
        float4 av;
        const int arow = rowBase + ar;
        if (arow < M)
            av = *(const float4*)(A + (size_t)arow * K + k0 + ak);
        else
            av = make_float4(0.f, 0.f, 0.f, 0.f);
        As[ak + 0][ar] = av.x;
        As[ak + 1][ar] = av.y;
        As[ak + 2][ar] = av.z;
        As[ak + 3][ar] = av.w;

        float4 bv = *(const float4*)(B + (size_t)(k0 + bk) * Nc + colBase + bn);
        *(float4*)&Bs[bk][bn] = bv;

        __syncthreads();

        #pragma unroll
        for (int kk = 0; kk < 16; ++kk) {
            const float4 b4 = *(const float4*)&Bs[kk][tx << 2];
            const float a0 = As[kk][(ty << 2) + 0];
            const float a1 = As[kk][(ty << 2) + 1];
            const float a2 = As[kk][(ty << 2) + 2];
            const float a3 = As[kk][(ty << 2) + 3];
            acc0.x = fmaf(a0, b4.x, acc0.x); acc0.y = fmaf(a0, b4.y, acc0.y);
            acc0.z = fmaf(a0, b4.z, acc0.z); acc0.w = fmaf(a0, b4.w, acc0.w);
            acc1.x = fmaf(a1, b4.x, acc1.x); acc1.y = fmaf(a1, b4.y, acc1.y);
            acc1.z = fmaf(a1, b4.z, acc1.z); acc1.w = fmaf(a1, b4.w, acc1.w);
            acc2.x = fmaf(a2, b4.x, acc2.x); acc2.y = fmaf(a2, b4.y, acc2.y);
            acc2.z = fmaf(a2, b4.z, acc2.z); acc2.w = fmaf(a2, b4.w, acc2.w);
            acc3.x = fmaf(a3, b4.x, acc3.x); acc3.y = fmaf(a3, b4.y, acc3.y);
            acc3.z = fmaf(a3, b4.z, acc3.z); acc3.w = fmaf(a3, b4.w, acc3.w);
        }
        __syncthreads();
    }

    const int col = colBase + (tx << 2);
    const int row0 = rowBase + (ty << 2);
    if (row0 + 0 < M) *(float4*)(C + (size_t)(row0 + 0) * Nc + col) = acc0;
    if (row0 + 1 < M) *(float4*)(C + (size_t)(row0 + 1) * Nc + col) = acc1;
    if (row0 + 2 < M) *(float4*)(C + (size_t)(row0 + 2) * Nc + col) = acc2;
    if (row0 + 3 < M) *(float4*)(C + (size_t)(row0 + 3) * Nc + col) = acc3;
}

// ---------------------------------------------------------------------------
// x += proj_b[c] + type_emb[types[n]][c]
// ---------------------------------------------------------------------------
__global__ void add_bias_emb_kernel(float* __restrict__ x,
                                    const float* __restrict__ pb,
                                    const float* __restrict__ emb,
                                    const int* __restrict__ types, int Nn)
{
    const int i = blockIdx.x * blockDim.x + threadIdx.x;
    if (i >= Nn * 64) return;
    const int n = i >> 6;
    const int c = i & 63;
    x[i] += pb[c] + emb[types[n] * 64 + c];
}

// ---------------------------------------------------------------------------
// CSR build
// ---------------------------------------------------------------------------
__global__ void init_counts_kernel(int Nn)
{
    const int i = blockIdx.x * blockDim.x + threadIdx.x;
    if (i < Nn) g_counts[i] = 1;   // self loop pre-counted
}

__global__ void hist_kernel(const int* __restrict__ dst, int E)
{
    const int i = blockIdx.x * blockDim.x + threadIdx.x;
    if (i < E) atomicAdd(&g_counts[dst[i]], 1);
}

__global__ __launch_bounds__(1024) void scan_kernel(int Nn)
{
    __shared__ int sums[1024];
    const int tid = threadIdx.x;
    const int chunk = (Nn + 1023) / 1024;
    const int lo = tid * chunk;
    const int hi = min(lo + chunk, Nn);

    int s = 0;
    for (int i = lo; i < hi; ++i) s += g_counts[i];
    sums[tid] = s;
    __syncthreads();

    #pragma unroll
    for (int off = 1; off < 1024; off <<= 1) {
        int v = (tid >= off) ? sums[tid - off] : 0;
        __syncthreads();
        sums[tid] += v;
        __syncthreads();
    }

    int run = (tid > 0) ? sums[tid - 1] : 0;
    for (int i = lo; i < hi; ++i) {
        g_rowptr[i] = run;
        g_cursor[i] = run;
        run += g_counts[i];
    }
    if (tid == 0) g_rowptr[Nn] = sums[1023];
}

__global__ void scatter_kernel(const int* __restrict__ ei, int E, int Nn)
{
    const int i = blockIdx.x * blockDim.x + threadIdx.x;
    if (i >= E + Nn) return;
    int s, d;
    if (i < E) { s = ei[i]; d = ei[E + i]; }
    else       { s = i - E; d = i - E; }
    const int pos = atomicAdd(&g_cursor[d], 1);
    g_col[pos] = s;
}

// ---------------------------------------------------------------------------
// a_s[n][h] = sum_c xp[n][h][c]*att_src[h][c];  a_d analogous. Warp per node.
// ---------------------------------------------------------------------------
__global__ void attn_coef_kernel(const float* __restrict__ xp,
                                 const float* __restrict__ att_src,
                                 const float* __restrict__ att_dst,
                                 float* __restrict__ a_s,
                                 float* __restrict__ a_d, int Nn)
{
    const int w = (blockIdx.x * blockDim.x + threadIdx.x) >> 5;
    const int lane = threadIdx.x & 31;
    if (w >= Nn) return;
    const float* row = xp + (size_t)w * 256;
    #pragma unroll
    for (int h = 0; h < 4; ++h) {
        const float2 v  = *(const float2*)(row + h * 64 + lane * 2);
        const float2 cs = *(const float2*)(att_src + h * 64 + lane * 2);
        const float2 cd = *(const float2*)(att_dst + h * 64 + lane * 2);
        float s = v.x * cs.x + v.y * cs.y;
        float d = v.x * cd.x + v.y * cd.y;
        #pragma unroll
        for (int o = 16; o; o >>= 1) {
            s += __shfl_xor_sync(0xffffffffu, s, o);
            d += __shfl_xor_sync(0xffffffffu, d, o);
        }
        if (lane == 0) { a_s[w * 4 + h] = s; a_d[w * 4 + h] = d; }
    }
}

// ---------------------------------------------------------------------------
// GAT aggregation: warp per (node, head). Online segment softmax + weighted sum.
// out[n][h*64+c] = sum_j alpha_j * xp[src_j][h*64+c]
// ---------------------------------------------------------------------------
__global__ void gat_agg_kernel(const float* __restrict__ xp,
                               const float* __restrict__ a_s,
                               const float* __restrict__ a_d,
                               float* __restrict__ out, int Nn)
{
    const int g = (blockIdx.x * blockDim.x + threadIdx.x) >> 5;
    const int lane = threadIdx.x & 31;
    if (g >= Nn * 4) return;
    const int node = g >> 2;
    const int head = g & 3;

    const int beg = __ldg(&g_rowptr[node]);
    const int end = __ldg(&g_rowptr[node + 1]);
    const float adh = __ldg(&a_d[node * 4 + head]);

    float m = -INFINITY;
    float dsum = 0.f;
    float accx = 0.f, accy = 0.f;

    for (int j = beg; j < end; ++j) {
        const int s = __ldg(&g_col[j]);
        float e = __ldg(&a_s[s * 4 + head]) + adh;
        e = (e > 0.f) ? e : 0.2f * e;                     // leaky_relu 0.2
        const float2 v = *(const float2*)(xp + (size_t)s * 256 + head * 64 + lane * 2);
        const float nm = fmaxf(m, e);
        const float p  = __expf(e - nm);
        const float sc = __expf(m - nm);                  // exp(-inf)=0 on first edge
        dsum = dsum * sc + p;
        accx = fmaf(p, v.x, accx * sc);
        accy = fmaf(p, v.y, accy * sc);
        m = nm;
    }
    const float inv = 1.f / (dsum + 1e-16f);
    *(float2*)(out + (size_t)node * 256 + head * 64 + lane * 2) =
        make_float2(accx * inv, accy * inv);
}

// ---------------------------------------------------------------------------
// out = relu(LN(in + bias; g, b)) over 256 features. Warp per node.
// ---------------------------------------------------------------------------
__global__ void ln_relu_256_kernel(const float* __restrict__ in,
                                   const float* __restrict__ bias,
                                   const float* __restrict__ lg,
                                   const float* __restrict__ lb,
                                   float* __restrict__ out, int Nn)
{
    const int w = (blockIdx.x * blockDim.x + threadIdx.x) >> 5;
    const int lane = threadIdx.x & 31;
    if (w >= Nn) return;
    const float* row = in + (size_t)w * 256;

    float v[8];
    float s = 0.f;
    #pragma unroll
    for (int i = 0; i < 2; ++i) {
        const float4 x4 = *(const float4*)(row + i * 128 + lane * 4);
        const float4 b4 = *(const float4*)(bias + i * 128 + lane * 4);
        v[i * 4 + 0] = x4.x + b4.x; v[i * 4 + 1] = x4.y + b4.y;
        v[i * 4 + 2] = x4.z + b4.z; v[i * 4 + 3] = x4.w + b4.w;
        s += v[i * 4 + 0] + v[i * 4 + 1] + v[i * 4 + 2] + v[i * 4 + 3];
    }
    #pragma unroll
    for (int o = 16; o; o >>= 1) s += __shfl_xor_sync(0xffffffffu, s, o);
    const float mu = s * (1.f / 256.f);

    float q = 0.f;
    #pragma unroll
    for (int i = 0; i < 8; ++i) { const float d = v[i] - mu; q += d * d; }
    #pragma unroll
    for (int o = 16; o; o >>= 1) q += __shfl_xor_sync(0xffffffffu, q, o);
    const float rinv = rsqrtf(q * (1.f / 256.f) + 1e-5f);

    float* orow = out + (size_t)w * 256;
    #pragma unroll
    for (int i = 0; i < 2; ++i) {
        const float4 g4 = *(const float4*)(lg + i * 128 + lane * 4);
        const float4 b4 = *(const float4*)(lb + i * 128 + lane * 4);
        float4 y;
        y.x = fmaxf(fmaf((v[i * 4 + 0] - mu) * rinv, g4.x, b4.x), 0.f);
        y.y = fmaxf(fmaf((v[i * 4 + 1] - mu) * rinv, g4.y, b4.y), 0.f);
        y.z = fmaxf(fmaf((v[i * 4 + 2] - mu) * rinv, g4.z, b4.z), 0.f);
        y.w = fmaxf(fmaf((v[i * 4 + 3] - mu) * rinv, g4.w, b4.w), 0.f);
        *(float4*)(orow + i * 128 + lane * 4) = y;
    }
}

// ---------------------------------------------------------------------------
// out[n][c] = relu(LN(mean_h(hraw[n][h*64+c]) + bias1[c]; g, b)) over 64 feats.
// Warp per node, 2 features per lane.
// ---------------------------------------------------------------------------
__global__ void combine_ln1_kernel(const float* __restrict__ hraw,
                                   const float* __restrict__ bias,
                                   const float* __restrict__ lg,
                                   const float* __restrict__ lb,
                                   float* __restrict__ out, int Nn)
{
    const int w = (blockIdx.x * blockDim.x + threadIdx.x) >> 5;
    const int lane = threadIdx.x & 31;
    if (w >= Nn) return;
    const float* base = hraw + (size_t)w * 256;
    const int c = lane * 2;

    const float2 h0 = *(const float2*)(base + c);
    const float2 h1 = *(const float2*)(base + 64 + c);
    const float2 h2 = *(const float2*)(base + 128 + c);
    const float2 h3 = *(const float2*)(base + 192 + c);
    float tx = (h0.x + h1.x + h2.x + h3.x) * 0.25f + bias[c];
    float ty = (h0.y + h1.y + h2.y + h3.y) * 0.25f + bias[c + 1];

    float s = tx + ty;
    #pragma unroll
    for (int o = 16; o; o >>= 1) s += __shfl_xor_sync(0xffffffffu, s, o);
    const float mu = s * (1.f / 64.f);

    float q = (tx - mu) * (tx - mu) + (ty - mu) * (ty - mu);
    #pragma unroll
    for (int o = 16; o; o >>= 1) q += __shfl_xor_sync(0xffffffffu, q, o);
    const float rinv = rsqrtf(q * (1.f / 64.f) + 1e-5f);

    float2 y;
    y.x = fmaxf(fmaf((tx - mu) * rinv, lg[c], lb[c]), 0.f);
    y.y = fmaxf(fmaf((ty - mu) * rinv, lg[c + 1], lb[c + 1]), 0.f);
    *(float2*)(out + (size_t)w * 64 + c) = y;
}

// ---------------------------------------------------------------------------
// Launch
// ---------------------------------------------------------------------------
extern "C" void kernel_launch(void* const* d_in, const int* in_sizes, int n_in,
                              void* d_out, int out_size)
{
    const float* nf       = (const float*)d_in[0];
    const int*   types    = (const int*)  d_in[1];
    const int*   ei       = (const int*)  d_in[2];
    const float* type_emb = (const float*)d_in[3];
    const float* proj_W   = (const float*)d_in[4];
    const float* proj_b   = (const float*)d_in[5];
    const float* W0       = (const float*)d_in[6];
    const float* att_s0   = (const float*)d_in[7];
    const float* att_d0   = (const float*)d_in[8];
    const float* bias0    = (const float*)d_in[9];
    const float* ln0_g    = (const float*)d_in[10];
    const float* ln0_b    = (const float*)d_in[11];
    const float* W1       = (const float*)d_in[12];
    const float* att_s1   = (const float*)d_in[13];
    const float* att_d1   = (const float*)d_in[14];
    const float* bias1    = (const float*)d_in[15];
    const float* ln1_g    = (const float*)d_in[16];
    const float* ln1_b    = (const float*)d_in[17];
    float* out = (float*)d_out;

    const int Nn = in_sizes[1];        // node count (node_types)
    const int E  = in_sizes[2] / 2;

    float *x_p, *xp_p, *h_p, *hraw_p, *as_p, *ad_p;
    cudaGetSymbolAddress((void**)&x_p,    g_x);
    cudaGetSymbolAddress((void**)&xp_p,   g_xp);
    cudaGetSymbolAddress((void**)&h_p,    g_h);
    cudaGetSymbolAddress((void**)&hraw_p, g_hraw);
    cudaGetSymbolAddress((void**)&as_p,   g_as);
    cudaGetSymbolAddress((void**)&ad_p,   g_ad);

    const int nodeWarpBlocks = (Nn + 7) / 8;          // 8 warps / 256-thread block
    const int aggBlocks      = (Nn * 4 + 7) / 8;

    // --- input projection ---
    {
        dim3 grid(64 / 64, (Nn + 63) / 64);
        sgemm_kernel<<<grid, 256>>>(nf, proj_W, x_p, Nn, 64, 64);
        add_bias_emb_kernel<<<(Nn * 64 + 255) / 256, 256>>>(x_p, proj_b, type_emb, types, Nn);
    }

    // --- CSR build ---
    init_counts_kernel<<<(Nn + 255) / 256, 256>>>(Nn);
    hist_kernel<<<(E + 255) / 256, 256>>>(ei + E, E);
    scan_kernel<<<1, 1024>>>(Nn);
    scatter_kernel<<<(E + Nn + 255) / 256, 256>>>(ei, E, Nn);

    // --- layer 0 ---
    {
        dim3 grid(256 / 64, (Nn + 63) / 64);
        sgemm_kernel<<<grid, 256>>>(x_p, W0, xp_p, Nn, 64, 256);
    }
    attn_coef_kernel<<<nodeWarpBlocks, 256>>>(xp_p, att_s0, att_d0, as_p, ad_p, Nn);
    gat_agg_kernel<<<aggBlocks, 256>>>(xp_p, as_p, ad_p, hraw_p, Nn);
    ln_relu_256_kernel<<<nodeWarpBlocks, 256>>>(hraw_p, bias0, ln0_g, ln0_b, h_p, Nn);

    // --- layer 1 ---
    {
        dim3 grid(256 / 64, (Nn + 63) / 64);
        sgemm_kernel<<<grid, 256>>>(h_p, W1, xp_p, Nn, 256, 256);
    }
    attn_coef_kernel<<<nodeWarpBlocks, 256>>>(xp_p, att_s1, att_d1, as_p, ad_p, Nn);
    gat_agg_kernel<<<aggBlocks, 256>>>(xp_p, as_p, ad_p, hraw_p, Nn);
    combine_ln1_kernel<<<nodeWarpBlocks, 256>>>(hraw_p, bias1, ln1_g, ln1_b, out, Nn);
}

// round 2
// speedup vs baseline: 1.2602x; 1.2602x over previous
#include <cuda_runtime.h>
#include <cuda_bf16.h>
#include <math.h>

// ---------------------------------------------------------------------------
// TGN_GAT: 2-layer GAT (N=50000, E=800000, F=64, HID=64, HEADS=4)
// ---------------------------------------------------------------------------

#define MAXN 50000
#define MAXE 800000
#define MAXTOT (MAXE + MAXN)

__device__ float g_x[(size_t)MAXN * 64];
__device__ float g_xp[(size_t)MAXN * 256];
__device__ float g_h[(size_t)MAXN * 256];
__device__ float g_hraw[(size_t)MAXN * 256];
__device__ float g_as[(size_t)MAXN * 4];
__device__ float g_ad[(size_t)MAXN * 4];
__device__ int   g_rowptr[MAXN + 1];
__device__ int   g_cursor[MAXN];
__device__ int   g_counts[MAXN];
__device__ int   g_col[MAXTOT];

// ---------------------------------------------------------------------------
// Small tiled SGEMM (64x64 tile) for the input projection (Nc=64).
// ---------------------------------------------------------------------------
__global__ __launch_bounds__(256) void sgemm_kernel(
    const float* __restrict__ A, const float* __restrict__ B,
    float* __restrict__ C, int M, int K, int Nc)
{
    __shared__ float As[16][65];
    __shared__ float Bs[16][64];

    const int tid = threadIdx.x;
    const int tx = tid & 15;
    const int ty = tid >> 4;
    const int rowBase = blockIdx.y * 64;
    const int colBase = blockIdx.x * 64;

    const int ar = tid >> 2;
    const int ak = (tid & 3) << 2;
    const int bk = tid >> 4;
    const int bn = (tid & 15) << 2;

    float4 acc0 = make_float4(0.f, 0.f, 0.f, 0.f);
    float4 acc1 = acc0, acc2 = acc0, acc3 = acc0;

    for (int k0 = 0; k0 < K; k0 += 16) {
        float4 av;
        const int arow = rowBase + ar;
        if (arow < M)
            av = *(const float4*)(A + (size_t)arow * K + k0 + ak);
        else
            av = make_float4(0.f, 0.f, 0.f, 0.f);
        As[ak + 0][ar] = av.x;
        As[ak + 1][ar] = av.y;
        As[ak + 2][ar] = av.z;
        As[ak + 3][ar] = av.w;

        float4 bv = *(const float4*)(B + (size_t)(k0 + bk) * Nc + colBase + bn);
        *(float4*)&Bs[bk][bn] = bv;

        __syncthreads();

        #pragma unroll
        for (int kk = 0; kk < 16; ++kk) {
            const float4 b4 = *(const float4*)&Bs[kk][tx << 2];
            const float a0 = As[kk][(ty << 2) + 0];
            const float a1 = As[kk][(ty << 2) + 1];
            const float a2 = As[kk][(ty << 2) + 2];
            const float a3 = As[kk][(ty << 2) + 3];
            acc0.x = fmaf(a0, b4.x, acc0.x); acc0.y = fmaf(a0, b4.y, acc0.y);
            acc0.z = fmaf(a0, b4.z, acc0.z); acc0.w = fmaf(a0, b4.w, acc0.w);
            acc1.x = fmaf(a1, b4.x, acc1.x); acc1.y = fmaf(a1, b4.y, acc1.y);
            acc1.z = fmaf(a1, b4.z, acc1.z); acc1.w = fmaf(a1, b4.w, acc1.w);
            acc2.x = fmaf(a2, b4.x, acc2.x); acc2.y = fmaf(a2, b4.y, acc2.y);
            acc2.z = fmaf(a2, b4.z, acc2.z); acc2.w = fmaf(a2, b4.w, acc2.w);
            acc3.x = fmaf(a3, b4.x, acc3.x); acc3.y = fmaf(a3, b4.y, acc3.y);
            acc3.z = fmaf(a3, b4.z, acc3.z); acc3.w = fmaf(a3, b4.w, acc3.w);
        }
        __syncthreads();
    }

    const int col = colBase + (tx << 2);
    const int row0 = rowBase + (ty << 2);
    if (row0 + 0 < M) *(float4*)(C + (size_t)(row0 + 0) * Nc + col) = acc0;
    if (row0 + 1 < M) *(float4*)(C + (size_t)(row0 + 1) * Nc + col) = acc1;
    if (row0 + 2 < M) *(float4*)(C + (size_t)(row0 + 2) * Nc + col) = acc2;
    if (row0 + 3 < M) *(float4*)(C + (size_t)(row0 + 3) * Nc + col) = acc3;
}

// ---------------------------------------------------------------------------
// Big SGEMM: 128x128 block tile, BK=16, 256 threads, 8x8 per thread.
// Requires Nc % 128 == 0, K % 16 == 0. Row-bounds-checked on A/C.
// ---------------------------------------------------------------------------
__global__ __launch_bounds__(256) void sgemm128_kernel(
    const float* __restrict__ A, const float* __restrict__ B,
    float* __restrict__ C, int M, int K, int Nc)
{
    __shared__ float As[16][128];
    __shared__ float Bs[16][128];

    const int tid = threadIdx.x;
    const int tx = tid & 15;        // col group 0..15
    const int ty = tid >> 4;        // row group 0..15
    const int rowBase = blockIdx.y * 128;
    const int colBase = blockIdx.x * 128;

    // A load map: 2 float4 per thread (rows ar, ar+64; k-offset ak)
    const int ar = tid >> 2;            // 0..63
    const int ak = (tid & 3) << 2;      // 0,4,8,12
    // B load map: 2 float4 per thread (k-rows bk, bk+8; col offset bn)
    const int bk = tid >> 5;            // 0..7
    const int bn = (tid & 31) << 2;     // 0..124

    float acc[8][8];
    #pragma unroll
    for (int i = 0; i < 8; ++i)
        #pragma unroll
        for (int j = 0; j < 8; ++j) acc[i][j] = 0.f;

    for (int k0 = 0; k0 < K; k0 += 16) {
        #pragma unroll
        for (int h = 0; h < 2; ++h) {
            const int r = ar + h * 64;
            const int grow = rowBase + r;
            float4 av = (grow < M)
                ? *(const float4*)(A + (size_t)grow * K + k0 + ak)
                : make_float4(0.f, 0.f, 0.f, 0.f);
            As[ak + 0][r] = av.x;
            As[ak + 1][r] = av.y;
            As[ak + 2][r] = av.z;
            As[ak + 3][r] = av.w;
        }
        #pragma unroll
        for (int h = 0; h < 2; ++h) {
            const int kr = bk + h * 8;
            *(float4*)&Bs[kr][bn] =
                *(const float4*)(B + (size_t)(k0 + kr) * Nc + colBase + bn);
        }
        __syncthreads();

        #pragma unroll
        for (int kk = 0; kk < 16; ++kk) {
            float a[8], b[8];
            *(float4*)&a[0] = *(const float4*)&As[kk][ty * 4];
            *(float4*)&a[4] = *(const float4*)&As[kk][ty * 4 + 64];
            *(float4*)&b[0] = *(const float4*)&Bs[kk][tx * 4];
            *(float4*)&b[4] = *(const float4*)&Bs[kk][tx * 4 + 64];
            #pragma unroll
            for (int i = 0; i < 8; ++i)
                #pragma unroll
                for (int j = 0; j < 8; ++j)
                    acc[i][j] = fmaf(a[i], b[j], acc[i][j]);
        }
        __syncthreads();
    }

    #pragma unroll
    for (int i = 0; i < 8; ++i) {
        const int grow = rowBase + ty * 4 + (i & 3) + (i >> 2) * 64;
        if (grow < M) {
            float* crow = C + (size_t)grow * Nc + colBase;
            *(float4*)(crow + tx * 4)      = *(float4*)&acc[i][0];
            *(float4*)(crow + tx * 4 + 64) = *(float4*)&acc[i][4];
        }
    }
}

// ---------------------------------------------------------------------------
__global__ void add_bias_emb_kernel(float* __restrict__ x,
                                    const float* __restrict__ pb,
                                    const float* __restrict__ emb,
                                    const int* __restrict__ types, int Nn)
{
    const int i = blockIdx.x * blockDim.x + threadIdx.x;
    if (i >= Nn * 64) return;
    const int n = i >> 6;
    const int c = i & 63;
    x[i] += pb[c] + emb[types[n] * 64 + c];
}

// ---------------------------------------------------------------------------
// CSR build
// ---------------------------------------------------------------------------
__global__ void init_counts_kernel(int Nn)
{
    const int i = blockIdx.x * blockDim.x + threadIdx.x;
    if (i < Nn) g_counts[i] = 1;   // self loop pre-counted
}

__global__ void hist_kernel(const int* __restrict__ dst, int E)
{
    const int i = blockIdx.x * blockDim.x + threadIdx.x;
    if (i < E) atomicAdd(&g_counts[dst[i]], 1);
}

__global__ __launch_bounds__(1024) void scan_kernel(int Nn)
{
    __shared__ int sums[1024];
    const int tid = threadIdx.x;
    const int chunk = (Nn + 1023) / 1024;
    const int lo = tid * chunk;
    const int hi = min(lo + chunk, Nn);

    int s = 0;
    for (int i = lo; i < hi; ++i) s += g_counts[i];
    sums[tid] = s;
    __syncthreads();

    #pragma unroll
    for (int off = 1; off < 1024; off <<= 1) {
        int v = (tid >= off) ? sums[tid - off] : 0;
        __syncthreads();
        sums[tid] += v;
        __syncthreads();
    }

    int run = (tid > 0) ? sums[tid - 1] : 0;
    for (int i = lo; i < hi; ++i) {
        g_rowptr[i] = run;
        g_cursor[i] = run;
        run += g_counts[i];
    }
    if (tid == 0) g_rowptr[Nn] = sums[1023];
}

__global__ void scatter_kernel(const int* __restrict__ ei, int E, int Nn)
{
    const int i = blockIdx.x * blockDim.x + threadIdx.x;
    if (i >= E + Nn) return;
    int s, d;
    if (i < E) { s = ei[i]; d = ei[E + i]; }
    else       { s = i - E; d = i - E; }
    const int pos = atomicAdd(&g_cursor[d], 1);
    g_col[pos] = s;
}

// ---------------------------------------------------------------------------
// a_s[n][h] = <xp[n][h], att_src[h]>, a_d analogous. Warp per node.
// ---------------------------------------------------------------------------
__global__ void attn_coef_kernel(const float* __restrict__ xp,
                                 const float* __restrict__ att_src,
                                 const float* __restrict__ att_dst,
                                 float* __restrict__ a_s,
                                 float* __restrict__ a_d, int Nn)
{
    const int w = (blockIdx.x * blockDim.x + threadIdx.x) >> 5;
    const int lane = threadIdx.x & 31;
    if (w >= Nn) return;
    const float* row = xp + (size_t)w * 256;
    #pragma unroll
    for (int h = 0; h < 4; ++h) {
        const float2 v  = *(const float2*)(row + h * 64 + lane * 2);
        const float2 cs = *(const float2*)(att_src + h * 64 + lane * 2);
        const float2 cd = *(const float2*)(att_dst + h * 64 + lane * 2);
        float s = v.x * cs.x + v.y * cs.y;
        float d = v.x * cd.x + v.y * cd.y;
        #pragma unroll
        for (int o = 16; o; o >>= 1) {
            s += __shfl_xor_sync(0xffffffffu, s, o);
            d += __shfl_xor_sync(0xffffffffu, d, o);
        }
        if (lane == 0) { a_s[w * 4 + h] = s; a_d[w * 4 + h] = d; }
    }
}

// ---------------------------------------------------------------------------
// GAT aggregation, ALL 4 heads per warp. lane -> head = lane>>3.
// Each lane owns 8 consecutive features (one head's 8-float slice).
// Online segment softmax per head (state replicated across the head's 8 lanes).
// ---------------------------------------------------------------------------
__global__ void gat_agg4_kernel(const float* __restrict__ xp,
                                const float* __restrict__ a_s,
                                const float* __restrict__ a_d,
                                float* __restrict__ out, int Nn)
{
    const int node = (blockIdx.x * blockDim.x + threadIdx.x) >> 5;
    const int lane = threadIdx.x & 31;
    if (node >= Nn) return;
    const int head = lane >> 3;

    const int beg = __ldg(&g_rowptr[node]);
    const int end = __ldg(&g_rowptr[node + 1]);
    const float adh = __ldg(&a_d[node * 4 + head]);

    float m = -INFINITY;
    float dsum = 0.f;
    float4 acc0 = make_float4(0.f, 0.f, 0.f, 0.f);
    float4 acc1 = acc0;

    const size_t fo = (size_t)lane * 8;

    for (int j = beg; j < end; ++j) {
        const int s = __ldg(&g_col[j]);
        float e = __ldg(&a_s[s * 4 + head]) + adh;
        e = (e > 0.f) ? e : 0.2f * e;                      // leaky_relu 0.2
        const float* row = xp + (size_t)s * 256 + fo;
        const float4 v0 = *(const float4*)(row);
        const float4 v1 = *(const float4*)(row + 4);

        const float nm = fmaxf(m, e);
        const float p  = __expf(e - nm);
        const float sc = __expf(m - nm);                   // first edge: exp(-inf)=0
        dsum = dsum * sc + p;
        acc0.x = fmaf(p, v0.x, acc0.x * sc);
        acc0.y = fmaf(p, v0.y, acc0.y * sc);
        acc0.z = fmaf(p, v0.z, acc0.z * sc);
        acc0.w = fmaf(p, v0.w, acc0.w * sc);
        acc1.x = fmaf(p, v1.x, acc1.x * sc);
        acc1.y = fmaf(p, v1.y, acc1.y * sc);
        acc1.z = fmaf(p, v1.z, acc1.z * sc);
        acc1.w = fmaf(p, v1.w, acc1.w * sc);
        m = nm;
    }

    const float inv = 1.f / (dsum + 1e-16f);
    float* orow = out + (size_t)node * 256 + fo;
    *(float4*)(orow)     = make_float4(acc0.x * inv, acc0.y * inv, acc0.z * inv, acc0.w * inv);
    *(float4*)(orow + 4) = make_float4(acc1.x * inv, acc1.y * inv, acc1.z * inv, acc1.w * inv);
}

// ---------------------------------------------------------------------------
// out = relu(LN(in + bias; g, b)) over 256 features. Warp per node.
// ---------------------------------------------------------------------------
__global__ void ln_relu_256_kernel(const float* __restrict__ in,
                                   const float* __restrict__ bias,
                                   const float* __restrict__ lg,
                                   const float* __restrict__ lb,
                                   float* __restrict__ out, int Nn)
{
    const int w = (blockIdx.x * blockDim.x + threadIdx.x) >> 5;
    const int lane = threadIdx.x & 31;
    if (w >= Nn) return;
    const float* row = in + (size_t)w * 256;

    float v[8];
    float s = 0.f;
    #pragma unroll
    for (int i = 0; i < 2; ++i) {
        const float4 x4 = *(const float4*)(row + i * 128 + lane * 4);
        const float4 b4 = *(const float4*)(bias + i * 128 + lane * 4);
        v[i * 4 + 0] = x4.x + b4.x; v[i * 4 + 1] = x4.y + b4.y;
        v[i * 4 + 2] = x4.z + b4.z; v[i * 4 + 3] = x4.w + b4.w;
        s += v[i * 4 + 0] + v[i * 4 + 1] + v[i * 4 + 2] + v[i * 4 + 3];
    }
    #pragma unroll
    for (int o = 16; o; o >>= 1) s += __shfl_xor_sync(0xffffffffu, s, o);
    const float mu = s * (1.f / 256.f);

    float q = 0.f;
    #pragma unroll
    for (int i = 0; i < 8; ++i) { const float d = v[i] - mu; q += d * d; }
    #pragma unroll
    for (int o = 16; o; o >>= 1) q += __shfl_xor_sync(0xffffffffu, q, o);
    const float rinv = rsqrtf(q * (1.f / 256.f) + 1e-5f);

    float* orow = out + (size_t)w * 256;
    #pragma unroll
    for (int i = 0; i < 2; ++i) {
        const float4 g4 = *(const float4*)(lg + i * 128 + lane * 4);
        const float4 b4 = *(const float4*)(lb + i * 128 + lane * 4);
        float4 y;
        y.x = fmaxf(fmaf((v[i * 4 + 0] - mu) * rinv, g4.x, b4.x), 0.f);
        y.y = fmaxf(fmaf((v[i * 4 + 1] - mu) * rinv, g4.y, b4.y), 0.f);
        y.z = fmaxf(fmaf((v[i * 4 + 2] - mu) * rinv, g4.z, b4.z), 0.f);
        y.w = fmaxf(fmaf((v[i * 4 + 3] - mu) * rinv, g4.w, b4.w), 0.f);
        *(float4*)(orow + i * 128 + lane * 4) = y;
    }
}

// ---------------------------------------------------------------------------
// out[n][c] = relu(LN(mean_h(hraw) + bias1)) over 64 feats. Warp per node.
// ---------------------------------------------------------------------------
__global__ void combine_ln1_kernel(const float* __restrict__ hraw,
                                   const float* __restrict__ bias,
                                   const float* __restrict__ lg,
                                   const float* __restrict__ lb,
                                   float* __restrict__ out, int Nn)
{
    const int w = (blockIdx.x * blockDim.x + threadIdx.x) >> 5;
    const int lane = threadIdx.x & 31;
    if (w >= Nn) return;
    const float* base = hraw + (size_t)w * 256;
    const int c = lane * 2;

    const float2 h0 = *(const float2*)(base + c);
    const float2 h1 = *(const float2*)(base + 64 + c);
    const float2 h2 = *(const float2*)(base + 128 + c);
    const float2 h3 = *(const float2*)(base + 192 + c);
    float tx = (h0.x + h1.x + h2.x + h3.x) * 0.25f + bias[c];
    float ty = (h0.y + h1.y + h2.y + h3.y) * 0.25f + bias[c + 1];

    float s = tx + ty;
    #pragma unroll
    for (int o = 16; o; o >>= 1) s += __shfl_xor_sync(0xffffffffu, s, o);
    const float mu = s * (1.f / 64.f);

    float q = (tx - mu) * (tx - mu) + (ty - mu) * (ty - mu);
    #pragma unroll
    for (int o = 16; o; o >>= 1) q += __shfl_xor_sync(0xffffffffu, q, o);
    const float rinv = rsqrtf(q * (1.f / 64.f) + 1e-5f);

    float2 y;
    y.x = fmaxf(fmaf((tx - mu) * rinv, lg[c], lb[c]), 0.f);
    y.y = fmaxf(fmaf((ty - mu) * rinv, lg[c + 1], lb[c + 1]), 0.f);
    *(float2*)(out + (size_t)w * 64 + c) = y;
}

// ---------------------------------------------------------------------------
extern "C" void kernel_launch(void* const* d_in, const int* in_sizes, int n_in,
                              void* d_out, int out_size)
{
    const float* nf       = (const float*)d_in[0];
    const int*   types    = (const int*)  d_in[1];
    const int*   ei       = (const int*)  d_in[2];
    const float* type_emb = (const float*)d_in[3];
    const float* proj_W   = (const float*)d_in[4];
    const float* proj_b   = (const float*)d_in[5];
    const float* W0       = (const float*)d_in[6];
    const float* att_s0   = (const float*)d_in[7];
    const float* att_d0   = (const float*)d_in[8];
    const float* bias0    = (const float*)d_in[9];
    const float* ln0_g    = (const float*)d_in[10];
    const float* ln0_b    = (const float*)d_in[11];
    const float* W1       = (const float*)d_in[12];
    const float* att_s1   = (const float*)d_in[13];
    const float* att_d1   = (const float*)d_in[14];
    const float* bias1    = (const float*)d_in[15];
    const float* ln1_g    = (const float*)d_in[16];
    const float* ln1_b    = (const float*)d_in[17];
    float* out = (float*)d_out;

    const int Nn = in_sizes[1];
    const int E  = in_sizes[2] / 2;

    float *x_p, *xp_p, *h_p, *hraw_p, *as_p, *ad_p;
    cudaGetSymbolAddress((void**)&x_p,    g_x);
    cudaGetSymbolAddress((void**)&xp_p,   g_xp);
    cudaGetSymbolAddress((void**)&h_p,    g_h);
    cudaGetSymbolAddress((void**)&hraw_p, g_hraw);
    cudaGetSymbolAddress((void**)&as_p,   g_as);
    cudaGetSymbolAddress((void**)&ad_p,   g_ad);

    const int nodeWarpBlocks = (Nn + 7) / 8;   // 8 warps per 256-thread block

    // --- input projection ---
    {
        dim3 grid(1, (Nn + 63) / 64);
        sgemm_kernel<<<grid, 256>>>(nf, proj_W, x_p, Nn, 64, 64);
        add_bias_emb_kernel<<<(Nn * 64 + 255) / 256, 256>>>(x_p, proj_b, type_emb, types, Nn);
    }

    // --- CSR build ---
    init_counts_kernel<<<(Nn + 255) / 256, 256>>>(Nn);
    hist_kernel<<<(E + 255) / 256, 256>>>(ei + E, E);
    scan_kernel<<<1, 1024>>>(Nn);
    scatter_kernel<<<(E + Nn + 255) / 256, 256>>>(ei, E, Nn);

    // --- layer 0 ---
    {
        dim3 grid(256 / 128, (Nn + 127) / 128);
        sgemm128_kernel<<<grid, 256>>>(x_p, W0, xp_p, Nn, 64, 256);
    }
    attn_coef_kernel<<<nodeWarpBlocks, 256>>>(xp_p, att_s0, att_d0, as_p, ad_p, Nn);
    gat_agg4_kernel<<<nodeWarpBlocks, 256>>>(xp_p, as_p, ad_p, hraw_p, Nn);
    ln_relu_256_kernel<<<nodeWarpBlocks, 256>>>(hraw_p, bias0, ln0_g, ln0_b, h_p, Nn);

    // --- layer 1 ---
    {
        dim3 grid(256 / 128, (Nn + 127) / 128);
        sgemm128_kernel<<<grid, 256>>>(h_p, W1, xp_p, Nn, 256, 256);
    }
    attn_coef_kernel<<<nodeWarpBlocks, 256>>>(xp_p, att_s1, att_d1, as_p, ad_p, Nn);
    gat_agg4_kernel<<<nodeWarpBlocks, 256>>>(xp_p, as_p, ad_p, hraw_p, Nn);
    combine_ln1_kernel<<<nodeWarpBlocks, 256>>>(hraw_p, bias1, ln1_g, ln1_b, out, Nn);
}

// round 3
// speedup vs baseline: 1.3894x; 1.1025x over previous
#include <cuda_runtime.h>
#include <cuda_fp16.h>
#include <cuda_bf16.h>
#include <math.h>

// ---------------------------------------------------------------------------
// TGN_GAT: 2-layer GAT (N=50000, E=800000, F=64, HID=64, HEADS=4)
// ---------------------------------------------------------------------------

#define MAXN 50000
#define MAXE 800000
#define MAXTOT (MAXE + MAXN)

__device__ float  g_x[(size_t)MAXN * 64];
__device__ float  g_xp[(size_t)MAXN * 256];
__device__ __half g_xp16[(size_t)MAXN * 256];
__device__ float  g_h[(size_t)MAXN * 256];
__device__ float  g_hraw[(size_t)MAXN * 256];
__device__ float  g_as[(size_t)MAXN * 4];
__device__ float  g_ad[(size_t)MAXN * 4];
__device__ int    g_rowptr[MAXN + 1];
__device__ int    g_cursor[MAXN];
__device__ int    g_counts[MAXN];
__device__ int    g_col[MAXTOT];

// ---------------------------------------------------------------------------
// Projection SGEMM (64x64 tile) with fused bias + type-embedding epilogue.
// C[r][c] = (A@B)[r][c] + pb[c] + emb[types[r]*64 + c]     (Nc == 64)
// ---------------------------------------------------------------------------
__global__ __launch_bounds__(256) void sgemm_proj_kernel(
    const float* __restrict__ A, const float* __restrict__ B,
    float* __restrict__ C, int M, int K, int Nc,
    const float* __restrict__ pb, const float* __restrict__ emb,
    const int* __restrict__ types)
{
    __shared__ float As[16][65];
    __shared__ float Bs[16][64];

    const int tid = threadIdx.x;
    const int tx = tid & 15;
    const int ty = tid >> 4;
    const int rowBase = blockIdx.y * 64;
    const int colBase = blockIdx.x * 64;

    const int ar = tid >> 2;
    const int ak = (tid & 3) << 2;
    const int bk = tid >> 4;
    const int bn = (tid & 15) << 2;

    float4 acc0 = make_float4(0.f, 0.f, 0.f, 0.f);
    float4 acc1 = acc0, acc2 = acc0, acc3 = acc0;

    for (int k0 = 0; k0 < K; k0 += 16) {
        float4 av;
        const int arow = rowBase + ar;
        if (arow < M)
            av = *(const float4*)(A + (size_t)arow * K + k0 + ak);
        else
            av = make_float4(0.f, 0.f, 0.f, 0.f);
        As[ak + 0][ar] = av.x;
        As[ak + 1][ar] = av.y;
        As[ak + 2][ar] = av.z;
        As[ak + 3][ar] = av.w;

        float4 bv = *(const float4*)(B + (size_t)(k0 + bk) * Nc + colBase + bn);
        *(float4*)&Bs[bk][bn] = bv;

        __syncthreads();

        #pragma unroll
        for (int kk = 0; kk < 16; ++kk) {
            const float4 b4 = *(const float4*)&Bs[kk][tx << 2];
            const float a0 = As[kk][(ty << 2) + 0];
            const float a1 = As[kk][(ty << 2) + 1];
            const float a2 = As[kk][(ty << 2) + 2];
            const float a3 = As[kk][(ty << 2) + 3];
            acc0.x = fmaf(a0, b4.x, acc0.x); acc0.y = fmaf(a0, b4.y, acc0.y);
            acc0.z = fmaf(a0, b4.z, acc0.z); acc0.w = fmaf(a0, b4.w, acc0.w);
            acc1.x = fmaf(a1, b4.x, acc1.x); acc1.y = fmaf(a1, b4.y, acc1.y);
            acc1.z = fmaf(a1, b4.z, acc1.z); acc1.w = fmaf(a1, b4.w, acc1.w);
            acc2.x = fmaf(a2, b4.x, acc2.x); acc2.y = fmaf(a2, b4.y, acc2.y);
            acc2.z = fmaf(a2, b4.z, acc2.z); acc2.w = fmaf(a2, b4.w, acc2.w);
            acc3.x = fmaf(a3, b4.x, acc3.x); acc3.y = fmaf(a3, b4.y, acc3.y);
            acc3.z = fmaf(a3, b4.z, acc3.z); acc3.w = fmaf(a3, b4.w, acc3.w);
        }
        __syncthreads();
    }

    const int col = colBase + (tx << 2);
    const float4 pb4 = *(const float4*)(pb + col);
    const int row0 = rowBase + (ty << 2);
    #pragma unroll
    for (int i = 0; i < 4; ++i) {
        const int r = row0 + i;
        if (r >= M) break;
        float4 a = (i == 0) ? acc0 : (i == 1) ? acc1 : (i == 2) ? acc2 : acc3;
        const float4 e4 = *(const float4*)(emb + types[r] * 64 + col);
        a.x += pb4.x + e4.x; a.y += pb4.y + e4.y;
        a.z += pb4.z + e4.z; a.w += pb4.w + e4.w;
        *(float4*)(C + (size_t)r * Nc + col) = a;
    }
}

// ---------------------------------------------------------------------------
// Big SGEMM: 128x128 block tile, BK=16, 256 threads, 8x8 per thread.
// ---------------------------------------------------------------------------
__global__ __launch_bounds__(256) void sgemm128_kernel(
    const float* __restrict__ A, const float* __restrict__ B,
    float* __restrict__ C, int M, int K, int Nc)
{
    __shared__ float As[16][128];
    __shared__ float Bs[16][128];

    const int tid = threadIdx.x;
    const int tx = tid & 15;
    const int ty = tid >> 4;
    const int rowBase = blockIdx.y * 128;
    const int colBase = blockIdx.x * 128;

    const int ar = tid >> 2;
    const int ak = (tid & 3) << 2;
    const int bk = tid >> 5;
    const int bn = (tid & 31) << 2;

    float acc[8][8];
    #pragma unroll
    for (int i = 0; i < 8; ++i)
        #pragma unroll
        for (int j = 0; j < 8; ++j) acc[i][j] = 0.f;

    for (int k0 = 0; k0 < K; k0 += 16) {
        #pragma unroll
        for (int h = 0; h < 2; ++h) {
            const int r = ar + h * 64;
            const int grow = rowBase + r;
            float4 av = (grow < M)
                ? *(const float4*)(A + (size_t)grow * K + k0 + ak)
                : make_float4(0.f, 0.f, 0.f, 0.f);
            As[ak + 0][r] = av.x;
            As[ak + 1][r] = av.y;
            As[ak + 2][r] = av.z;
            As[ak + 3][r] = av.w;
        }
        #pragma unroll
        for (int h = 0; h < 2; ++h) {
            const int kr = bk + h * 8;
            *(float4*)&Bs[kr][bn] =
                *(const float4*)(B + (size_t)(k0 + kr) * Nc + colBase + bn);
        }
        __syncthreads();

        #pragma unroll
        for (int kk = 0; kk < 16; ++kk) {
            float a[8], b[8];
            *(float4*)&a[0] = *(const float4*)&As[kk][ty * 4];
            *(float4*)&a[4] = *(const float4*)&As[kk][ty * 4 + 64];
            *(float4*)&b[0] = *(const float4*)&Bs[kk][tx * 4];
            *(float4*)&b[4] = *(const float4*)&Bs[kk][tx * 4 + 64];
            #pragma unroll
            for (int i = 0; i < 8; ++i)
                #pragma unroll
                for (int j = 0; j < 8; ++j)
                    acc[i][j] = fmaf(a[i], b[j], acc[i][j]);
        }
        __syncthreads();
    }

    #pragma unroll
    for (int i = 0; i < 8; ++i) {
        const int grow = rowBase + ty * 4 + (i & 3) + (i >> 2) * 64;
        if (grow < M) {
            float* crow = C + (size_t)grow * Nc + colBase;
            *(float4*)(crow + tx * 4)      = *(float4*)&acc[i][0];
            *(float4*)(crow + tx * 4 + 64) = *(float4*)&acc[i][4];
        }
    }
}

// ---------------------------------------------------------------------------
// CSR build
// ---------------------------------------------------------------------------
__global__ void init_counts_kernel(int Nn)
{
    const int i = blockIdx.x * blockDim.x + threadIdx.x;
    if (i < Nn) g_counts[i] = 1;   // self loop pre-counted
}

__global__ void hist_kernel(const int* __restrict__ dst, int E)
{
    const int i = blockIdx.x * blockDim.x + threadIdx.x;
    if (i < E) atomicAdd(&g_counts[dst[i]], 1);
}

__global__ __launch_bounds__(1024) void scan_kernel(int Nn)
{
    __shared__ int sums[1024];
    const int tid = threadIdx.x;
    const int chunk = (Nn + 1023) / 1024;
    const int lo = tid * chunk;
    const int hi = min(lo + chunk, Nn);

    int s = 0;
    for (int i = lo; i < hi; ++i) s += g_counts[i];
    sums[tid] = s;
    __syncthreads();

    #pragma unroll
    for (int off = 1; off < 1024; off <<= 1) {
        int v = (tid >= off) ? sums[tid - off] : 0;
        __syncthreads();
        sums[tid] += v;
        __syncthreads();
    }

    int run = (tid > 0) ? sums[tid - 1] : 0;
    for (int i = lo; i < hi; ++i) {
        g_rowptr[i] = run;
        g_cursor[i] = run;
        run += g_counts[i];
    }
    if (tid == 0) g_rowptr[Nn] = sums[1023];
}

__global__ void scatter_kernel(const int* __restrict__ ei, int E, int Nn)
{
    const int i = blockIdx.x * blockDim.x + threadIdx.x;
    if (i >= E + Nn) return;
    int s, d;
    if (i < E) { s = ei[i]; d = ei[E + i]; }
    else       { s = i - E; d = i - E; }
    const int pos = atomicAdd(&g_cursor[d], 1);
    g_col[pos] = s;
}

// ---------------------------------------------------------------------------
// Fused: xp (fp32) -> xp16 (fp16) conversion + attention coefficients.
// Warp per node. Lane owns 8 contiguous features; head = lane>>3.
// a_s[n][h] = <xp[n][h], att_src[h]>, a_d analogous (fp32 exact).
// ---------------------------------------------------------------------------
__global__ void convert_attn_kernel(const float* __restrict__ xp,
                                    __half* __restrict__ xp16,
                                    const float* __restrict__ att_src,
                                    const float* __restrict__ att_dst,
                                    float* __restrict__ a_s,
                                    float* __restrict__ a_d, int Nn)
{
    const int node = (blockIdx.x * blockDim.x + threadIdx.x) >> 5;
    const int lane = threadIdx.x & 31;
    if (node >= Nn) return;
    const int head = lane >> 3;

    const float* row = xp + (size_t)node * 256 + lane * 8;
    const float4 v0 = *(const float4*)(row);
    const float4 v1 = *(const float4*)(row + 4);

    // attention dot products (each 8-lane group reduces one head)
    const float* cs = att_src + lane * 8;   // att_src[head][ (lane&7)*8 .. ]
    const float* cd = att_dst + lane * 8;
    const float4 s0 = *(const float4*)(cs);
    const float4 s1 = *(const float4*)(cs + 4);
    const float4 d0 = *(const float4*)(cd);
    const float4 d1 = *(const float4*)(cd + 4);

    float s = v0.x * s0.x + v0.y * s0.y + v0.z * s0.z + v0.w * s0.w
            + v1.x * s1.x + v1.y * s1.y + v1.z * s1.z + v1.w * s1.w;
    float d = v0.x * d0.x + v0.y * d0.y + v0.z * d0.z + v0.w * d0.w
            + v1.x * d1.x + v1.y * d1.y + v1.z * d1.z + v1.w * d1.w;
    #pragma unroll
    for (int o = 4; o; o >>= 1) {
        s += __shfl_xor_sync(0xffffffffu, s, o);
        d += __shfl_xor_sync(0xffffffffu, d, o);
    }
    if ((lane & 7) == 0) {
        a_s[node * 4 + head] = s;
        a_d[node * 4 + head] = d;
    }

    // fp16 conversion (8 halves = 16B per lane)
    __half2 h[4];
    h[0] = __floats2half2_rn(v0.x, v0.y);
    h[1] = __floats2half2_rn(v0.z, v0.w);
    h[2] = __floats2half2_rn(v1.x, v1.y);
    h[3] = __floats2half2_rn(v1.z, v1.w);
    *(uint4*)(xp16 + (size_t)node * 256 + lane * 8) = *(uint4*)h;
}

// ---------------------------------------------------------------------------
// GAT aggregation (fp16 messages), ALL 4 heads per warp. head = lane>>3.
// Online segment softmax per head; fp32 accumulation.
// ---------------------------------------------------------------------------
__global__ void gat_agg4_kernel(const __half* __restrict__ xp16,
                                const float* __restrict__ a_s,
                                const float* __restrict__ a_d,
                                float* __restrict__ out, int Nn)
{
    const int node = (blockIdx.x * blockDim.x + threadIdx.x) >> 5;
    const int lane = threadIdx.x & 31;
    if (node >= Nn) return;
    const int head = lane >> 3;

    const int beg = __ldg(&g_rowptr[node]);
    const int end = __ldg(&g_rowptr[node + 1]);
    const float adh = __ldg(&a_d[node * 4 + head]);

    float m = -INFINITY;
    float dsum = 0.f;
    float acc[8];
    #pragma unroll
    for (int i = 0; i < 8; ++i) acc[i] = 0.f;

    const size_t fo = (size_t)lane * 8;

    for (int j = beg; j < end; ++j) {
        const int s = __ldg(&g_col[j]);
        float e = __ldg(&a_s[s * 4 + head]) + adh;
        e = (e > 0.f) ? e : 0.2f * e;                      // leaky_relu 0.2
        const uint4 raw = *(const uint4*)(xp16 + (size_t)s * 256 + fo);
        const float2 f0 = __half22float2(*(const __half2*)&raw.x);
        const float2 f1 = __half22float2(*(const __half2*)&raw.y);
        const float2 f2 = __half22float2(*(const __half2*)&raw.z);
        const float2 f3 = __half22float2(*(const __half2*)&raw.w);

        const float nm = fmaxf(m, e);
        const float p  = __expf(e - nm);
        const float sc = __expf(m - nm);                   // first edge: exp(-inf)=0
        dsum = dsum * sc + p;
        acc[0] = fmaf(p, f0.x, acc[0] * sc);
        acc[1] = fmaf(p, f0.y, acc[1] * sc);
        acc[2] = fmaf(p, f1.x, acc[2] * sc);
        acc[3] = fmaf(p, f1.y, acc[3] * sc);
        acc[4] = fmaf(p, f2.x, acc[4] * sc);
        acc[5] = fmaf(p, f2.y, acc[5] * sc);
        acc[6] = fmaf(p, f3.x, acc[6] * sc);
        acc[7] = fmaf(p, f3.y, acc[7] * sc);
        m = nm;
    }

    const float inv = 1.f / (dsum + 1e-16f);
    float* orow = out + (size_t)node * 256 + fo;
    float4 o0 = make_float4(acc[0] * inv, acc[1] * inv, acc[2] * inv, acc[3] * inv);
    float4 o1 = make_float4(acc[4] * inv, acc[5] * inv, acc[6] * inv, acc[7] * inv);
    *(float4*)(orow)     = o0;
    *(float4*)(orow + 4) = o1;
}

// ---------------------------------------------------------------------------
// out = relu(LN(in + bias; g, b)) over 256 features. Warp per node.
// ---------------------------------------------------------------------------
__global__ void ln_relu_256_kernel(const float* __restrict__ in,
                                   const float* __restrict__ bias,
                                   const float* __restrict__ lg,
                                   const float* __restrict__ lb,
                                   float* __restrict__ out, int Nn)
{
    const int w = (blockIdx.x * blockDim.x + threadIdx.x) >> 5;
    const int lane = threadIdx.x & 31;
    if (w >= Nn) return;
    const float* row = in + (size_t)w * 256;

    float v[8];
    float s = 0.f;
    #pragma unroll
    for (int i = 0; i < 2; ++i) {
        const float4 x4 = *(const float4*)(row + i * 128 + lane * 4);
        const float4 b4 = *(const float4*)(bias + i * 128 + lane * 4);
        v[i * 4 + 0] = x4.x + b4.x; v[i * 4 + 1] = x4.y + b4.y;
        v[i * 4 + 2] = x4.z + b4.z; v[i * 4 + 3] = x4.w + b4.w;
        s += v[i * 4 + 0] + v[i * 4 + 1] + v[i * 4 + 2] + v[i * 4 + 3];
    }
    #pragma unroll
    for (int o = 16; o; o >>= 1) s += __shfl_xor_sync(0xffffffffu, s, o);
    const float mu = s * (1.f / 256.f);

    float q = 0.f;
    #pragma unroll
    for (int i = 0; i < 8; ++i) { const float d = v[i] - mu; q += d * d; }
    #pragma unroll
    for (int o = 16; o; o >>= 1) q += __shfl_xor_sync(0xffffffffu, q, o);
    const float rinv = rsqrtf(q * (1.f / 256.f) + 1e-5f);

    float* orow = out + (size_t)w * 256;
    #pragma unroll
    for (int i = 0; i < 2; ++i) {
        const float4 g4 = *(const float4*)(lg + i * 128 + lane * 4);
        const float4 b4 = *(const float4*)(lb + i * 128 + lane * 4);
        float4 y;
        y.x = fmaxf(fmaf((v[i * 4 + 0] - mu) * rinv, g4.x, b4.x), 0.f);
        y.y = fmaxf(fmaf((v[i * 4 + 1] - mu) * rinv, g4.y, b4.y), 0.f);
        y.z = fmaxf(fmaf((v[i * 4 + 2] - mu) * rinv, g4.z, b4.z), 0.f);
        y.w = fmaxf(fmaf((v[i * 4 + 3] - mu) * rinv, g4.w, b4.w), 0.f);
        *(float4*)(orow + i * 128 + lane * 4) = y;
    }
}

// ---------------------------------------------------------------------------
// out[n][c] = relu(LN(mean_h(hraw) + bias1)) over 64 feats. Warp per node.
// ---------------------------------------------------------------------------
__global__ void combine_ln1_kernel(const float* __restrict__ hraw,
                                   const float* __restrict__ bias,
                                   const float* __restrict__ lg,
                                   const float* __restrict__ lb,
                                   float* __restrict__ out, int Nn)
{
    const int w = (blockIdx.x * blockDim.x + threadIdx.x) >> 5;
    const int lane = threadIdx.x & 31;
    if (w >= Nn) return;
    const float* base = hraw + (size_t)w * 256;
    const int c = lane * 2;

    const float2 h0 = *(const float2*)(base + c);
    const float2 h1 = *(const float2*)(base + 64 + c);
    const float2 h2 = *(const float2*)(base + 128 + c);
    const float2 h3 = *(const float2*)(base + 192 + c);
    float tx = (h0.x + h1.x + h2.x + h3.x) * 0.25f + bias[c];
    float ty = (h0.y + h1.y + h2.y + h3.y) * 0.25f + bias[c + 1];

    float s = tx + ty;
    #pragma unroll
    for (int o = 16; o; o >>= 1) s += __shfl_xor_sync(0xffffffffu, s, o);
    const float mu = s * (1.f / 64.f);

    float q = (tx - mu) * (tx - mu) + (ty - mu) * (ty - mu);
    #pragma unroll
    for (int o = 16; o; o >>= 1) q += __shfl_xor_sync(0xffffffffu, q, o);
    const float rinv = rsqrtf(q * (1.f / 64.f) + 1e-5f);

    float2 y;
    y.x = fmaxf(fmaf((tx - mu) * rinv, lg[c], lb[c]), 0.f);
    y.y = fmaxf(fmaf((ty - mu) * rinv, lg[c + 1], lb[c + 1]), 0.f);
    *(float2*)(out + (size_t)w * 64 + c) = y;
}

// ---------------------------------------------------------------------------
extern "C" void kernel_launch(void* const* d_in, const int* in_sizes, int n_in,
                              void* d_out, int out_size)
{
    const float* nf       = (const float*)d_in[0];
    const int*   types    = (const int*)  d_in[1];
    const int*   ei       = (const int*)  d_in[2];
    const float* type_emb = (const float*)d_in[3];
    const float* proj_W   = (const float*)d_in[4];
    const float* proj_b   = (const float*)d_in[5];
    const float* W0       = (const float*)d_in[6];
    const float* att_s0   = (const float*)d_in[7];
    const float* att_d0   = (const float*)d_in[8];
    const float* bias0    = (const float*)d_in[9];
    const float* ln0_g    = (const float*)d_in[10];
    const float* ln0_b    = (const float*)d_in[11];
    const float* W1       = (const float*)d_in[12];
    const float* att_s1   = (const float*)d_in[13];
    const float* att_d1   = (const float*)d_in[14];
    const float* bias1    = (const float*)d_in[15];
    const float* ln1_g    = (const float*)d_in[16];
    const float* ln1_b    = (const float*)d_in[17];
    float* out = (float*)d_out;

    const int Nn = in_sizes[1];
    const int E  = in_sizes[2] / 2;

    float *x_p, *xp_p, *h_p, *hraw_p, *as_p, *ad_p;
    __half *xp16_p;
    cudaGetSymbolAddress((void**)&x_p,    g_x);
    cudaGetSymbolAddress((void**)&xp_p,   g_xp);
    cudaGetSymbolAddress((void**)&xp16_p, g_xp16);
    cudaGetSymbolAddress((void**)&h_p,    g_h);
    cudaGetSymbolAddress((void**)&hraw_p, g_hraw);
    cudaGetSymbolAddress((void**)&as_p,   g_as);
    cudaGetSymbolAddress((void**)&ad_p,   g_ad);

    const int nodeWarpBlocks = (Nn + 7) / 8;   // 8 warps per 256-thread block

    // --- input projection (fused bias + type emb) ---
    {
        dim3 grid(1, (Nn + 63) / 64);
        sgemm_proj_kernel<<<grid, 256>>>(nf, proj_W, x_p, Nn, 64, 64,
                                         proj_b, type_emb, types);
    }

    // --- CSR build ---
    init_counts_kernel<<<(Nn + 255) / 256, 256>>>(Nn);
    hist_kernel<<<(E + 255) / 256, 256>>>(ei + E, E);
    scan_kernel<<<1, 1024>>>(Nn);
    scatter_kernel<<<(E + Nn + 255) / 256, 256>>>(ei, E, Nn);

    // --- layer 0 ---
    {
        dim3 grid(2, (Nn + 127) / 128);
        sgemm128_kernel<<<grid, 256>>>(x_p, W0, xp_p, Nn, 64, 256);
    }
    convert_attn_kernel<<<nodeWarpBlocks, 256>>>(xp_p, xp16_p, att_s0, att_d0,
                                                 as_p, ad_p, Nn);
    gat_agg4_kernel<<<nodeWarpBlocks, 256>>>(xp16_p, as_p, ad_p, hraw_p, Nn);
    ln_relu_256_kernel<<<nodeWarpBlocks, 256>>>(hraw_p, bias0, ln0_g, ln0_b, h_p, Nn);

    // --- layer 1 ---
    {
        dim3 grid(2, (Nn + 127) / 128);
        sgemm128_kernel<<<grid, 256>>>(h_p, W1, xp_p, Nn, 256, 256);
    }
    convert_attn_kernel<<<nodeWarpBlocks, 256>>>(xp_p, xp16_p, att_s1, att_d1,
                                                 as_p, ad_p, Nn);
    gat_agg4_kernel<<<nodeWarpBlocks, 256>>>(xp16_p, as_p, ad_p, hraw_p, Nn);
    combine_ln1_kernel<<<nodeWarpBlocks, 256>>>(hraw_p, bias1, ln1_g, ln1_b, out, Nn);
}

// round 4
// speedup vs baseline: 1.6617x; 1.1960x over previous
#include <cuda_runtime.h>
#include <cuda_fp16.h>
#include <cuda_bf16.h>
#include <math.h>

// ---------------------------------------------------------------------------
// TGN_GAT: 2-layer GAT (N=50000, E=800000, F=64, HID=64, HEADS=4)
// ---------------------------------------------------------------------------

#define MAXN 50000
#define MAXE 800000
#define MAXTOT (MAXE + MAXN)
#define SCAN_BLK 256
#define MAX_SCAN_BLOCKS ((MAXN + SCAN_BLK - 1) / SCAN_BLK)   // 196

__device__ float  g_x[(size_t)MAXN * 64];
__device__ float  g_xp[(size_t)MAXN * 256];
__device__ __half g_xp16[(size_t)MAXN * 256];
__device__ float  g_h[(size_t)MAXN * 256];
__device__ float  g_hraw[(size_t)MAXN * 256];
__device__ float  g_as[(size_t)MAXN * 4];
__device__ float  g_ad[(size_t)MAXN * 4];
__device__ int    g_rowptr[MAXN + 1];
__device__ int    g_cursor[MAXN];
__device__ int    g_counts[MAXN];
__device__ int    g_scanex[MAXN];          // exclusive scan within block
__device__ int    g_bsum[MAX_SCAN_BLOCKS];
__device__ int    g_boff[MAX_SCAN_BLOCKS];
__device__ int    g_col[MAXTOT];

// ---------------------------------------------------------------------------
// Projection SGEMM (64x64 tile) with fused bias + type-embedding epilogue.
// ---------------------------------------------------------------------------
__global__ __launch_bounds__(256) void sgemm_proj_kernel(
    const float* __restrict__ A, const float* __restrict__ B,
    float* __restrict__ C, int M, int K, int Nc,
    const float* __restrict__ pb, const float* __restrict__ emb,
    const int* __restrict__ types)
{
    __shared__ float As[16][65];
    __shared__ float Bs[16][64];

    const int tid = threadIdx.x;
    const int tx = tid & 15;
    const int ty = tid >> 4;
    const int rowBase = blockIdx.y * 64;
    const int colBase = blockIdx.x * 64;

    const int ar = tid >> 2;
    const int ak = (tid & 3) << 2;
    const int bk = tid >> 4;
    const int bn = (tid & 15) << 2;

    float4 acc0 = make_float4(0.f, 0.f, 0.f, 0.f);
    float4 acc1 = acc0, acc2 = acc0, acc3 = acc0;

    for (int k0 = 0; k0 < K; k0 += 16) {
        float4 av;
        const int arow = rowBase + ar;
        if (arow < M)
            av = *(const float4*)(A + (size_t)arow * K + k0 + ak);
        else
            av = make_float4(0.f, 0.f, 0.f, 0.f);
        As[ak + 0][ar] = av.x;
        As[ak + 1][ar] = av.y;
        As[ak + 2][ar] = av.z;
        As[ak + 3][ar] = av.w;

        float4 bv = *(const float4*)(B + (size_t)(k0 + bk) * Nc + colBase + bn);
        *(float4*)&Bs[bk][bn] = bv;

        __syncthreads();

        #pragma unroll
        for (int kk = 0; kk < 16; ++kk) {
            const float4 b4 = *(const float4*)&Bs[kk][tx << 2];
            const float a0 = As[kk][(ty << 2) + 0];
            const float a1 = As[kk][(ty << 2) + 1];
            const float a2 = As[kk][(ty << 2) + 2];
            const float a3 = As[kk][(ty << 2) + 3];
            acc0.x = fmaf(a0, b4.x, acc0.x); acc0.y = fmaf(a0, b4.y, acc0.y);
            acc0.z = fmaf(a0, b4.z, acc0.z); acc0.w = fmaf(a0, b4.w, acc0.w);
            acc1.x = fmaf(a1, b4.x, acc1.x); acc1.y = fmaf(a1, b4.y, acc1.y);
            acc1.z = fmaf(a1, b4.z, acc1.z); acc1.w = fmaf(a1, b4.w, acc1.w);
            acc2.x = fmaf(a2, b4.x, acc2.x); acc2.y = fmaf(a2, b4.y, acc2.y);
            acc2.z = fmaf(a2, b4.z, acc2.z); acc2.w = fmaf(a2, b4.w, acc2.w);
            acc3.x = fmaf(a3, b4.x, acc3.x); acc3.y = fmaf(a3, b4.y, acc3.y);
            acc3.w = fmaf(a3, b4.w, acc3.w); acc3.z = fmaf(a3, b4.z, acc3.z);
        }
        __syncthreads();
    }

    const int col = colBase + (tx << 2);
    const float4 pb4 = *(const float4*)(pb + col);
    const int row0 = rowBase + (ty << 2);
    #pragma unroll
    for (int i = 0; i < 4; ++i) {
        const int r = row0 + i;
        if (r >= M) break;
        float4 a = (i == 0) ? acc0 : (i == 1) ? acc1 : (i == 2) ? acc2 : acc3;
        const float4 e4 = *(const float4*)(emb + types[r] * 64 + col);
        a.x += pb4.x + e4.x; a.y += pb4.y + e4.y;
        a.z += pb4.z + e4.z; a.w += pb4.w + e4.w;
        *(float4*)(C + (size_t)r * Nc + col) = a;
    }
}

// ---------------------------------------------------------------------------
// Big SGEMM: 128x128 block tile, BK=16, 256 threads, 8x8 per thread.
// ---------------------------------------------------------------------------
__global__ __launch_bounds__(256) void sgemm128_kernel(
    const float* __restrict__ A, const float* __restrict__ B,
    float* __restrict__ C, int M, int K, int Nc)
{
    __shared__ float As[16][128];
    __shared__ float Bs[16][128];

    const int tid = threadIdx.x;
    const int tx = tid & 15;
    const int ty = tid >> 4;
    const int rowBase = blockIdx.y * 128;
    const int colBase = blockIdx.x * 128;

    const int ar = tid >> 2;
    const int ak = (tid & 3) << 2;
    const int bk = tid >> 5;
    const int bn = (tid & 31) << 2;

    float acc[8][8];
    #pragma unroll
    for (int i = 0; i < 8; ++i)
        #pragma unroll
        for (int j = 0; j < 8; ++j) acc[i][j] = 0.f;

    for (int k0 = 0; k0 < K; k0 += 16) {
        #pragma unroll
        for (int h = 0; h < 2; ++h) {
            const int r = ar + h * 64;
            const int grow = rowBase + r;
            float4 av = (grow < M)
                ? *(const float4*)(A + (size_t)grow * K + k0 + ak)
                : make_float4(0.f, 0.f, 0.f, 0.f);
            As[ak + 0][r] = av.x;
            As[ak + 1][r] = av.y;
            As[ak + 2][r] = av.z;
            As[ak + 3][r] = av.w;
        }
        #pragma unroll
        for (int h = 0; h < 2; ++h) {
            const int kr = bk + h * 8;
            *(float4*)&Bs[kr][bn] =
                *(const float4*)(B + (size_t)(k0 + kr) * Nc + colBase + bn);
        }
        __syncthreads();

        #pragma unroll
        for (int kk = 0; kk < 16; ++kk) {
            float a[8], b[8];
            *(float4*)&a[0] = *(const float4*)&As[kk][ty * 4];
            *(float4*)&a[4] = *(const float4*)&As[kk][ty * 4 + 64];
            *(float4*)&b[0] = *(const float4*)&Bs[kk][tx * 4];
            *(float4*)&b[4] = *(const float4*)&Bs[kk][tx * 4 + 64];
            #pragma unroll
            for (int i = 0; i < 8; ++i)
                #pragma unroll
                for (int j = 0; j < 8; ++j)
                    acc[i][j] = fmaf(a[i], b[j], acc[i][j]);
        }
        __syncthreads();
    }

    #pragma unroll
    for (int i = 0; i < 8; ++i) {
        const int grow = rowBase + ty * 4 + (i & 3) + (i >> 2) * 64;
        if (grow < M) {
            float* crow = C + (size_t)grow * Nc + colBase;
            *(float4*)(crow + tx * 4)      = *(float4*)&acc[i][0];
            *(float4*)(crow + tx * 4 + 64) = *(float4*)&acc[i][4];
        }
    }
}

// ---------------------------------------------------------------------------
// CSR build
// ---------------------------------------------------------------------------
__global__ void init_counts_kernel(int Nn)
{
    const int i = blockIdx.x * blockDim.x + threadIdx.x;
    if (i < Nn) g_counts[i] = 1;   // self loop pre-counted
}

__global__ void hist_kernel(const int* __restrict__ dst, int E)
{
    const int i = blockIdx.x * blockDim.x + threadIdx.x;
    if (i < E) atomicAdd(&g_counts[dst[i]], 1);
}

// Phase 1: per-block (256 elements) exclusive scan + block total.
__global__ __launch_bounds__(SCAN_BLK) void scan_p1_kernel(int Nn)
{
    __shared__ int sh[SCAN_BLK];
    const int t = threadIdx.x;
    const int i = blockIdx.x * SCAN_BLK + t;
    int v = (i < Nn) ? g_counts[i] : 0;
    sh[t] = v;
    __syncthreads();

    int inc = v;
    #pragma unroll
    for (int off = 1; off < SCAN_BLK; off <<= 1) {
        int add = (t >= off) ? sh[t - off] : 0;
        __syncthreads();
        inc += add;
        sh[t] = inc;
        __syncthreads();
    }
    if (i < Nn) g_scanex[i] = inc - v;               // exclusive within block
    if (t == SCAN_BLK - 1) g_bsum[blockIdx.x] = inc; // block total
}

// Phase 2: single block scans the block sums (nblocks <= 256).
__global__ __launch_bounds__(SCAN_BLK) void scan_p2_kernel(int nblocks, int Nn)
{
    __shared__ int sh[SCAN_BLK];
    const int t = threadIdx.x;
    int v = (t < nblocks) ? g_bsum[t] : 0;
    sh[t] = v;
    __syncthreads();

    int inc = v;
    #pragma unroll
    for (int off = 1; off < SCAN_BLK; off <<= 1) {
        int add = (t >= off) ? sh[t - off] : 0;
        __syncthreads();
        inc += add;
        sh[t] = inc;
        __syncthreads();
    }
    if (t < nblocks) g_boff[t] = inc - v;
    if (t == SCAN_BLK - 1) g_rowptr[Nn] = sh[SCAN_BLK - 1];  // grand total
}

// Phase 3: add block offsets, emit rowptr + cursor.
__global__ void scan_p3_kernel(int Nn)
{
    const int i = blockIdx.x * blockDim.x + threadIdx.x;
    if (i >= Nn) return;
    const int val = g_scanex[i] + g_boff[i >> 8];
    g_rowptr[i] = val;
    g_cursor[i] = val;
}

__global__ void scatter_kernel(const int* __restrict__ ei, int E, int Nn)
{
    const int i = blockIdx.x * blockDim.x + threadIdx.x;
    if (i >= E + Nn) return;
    int s, d;
    if (i < E) { s = ei[i]; d = ei[E + i]; }
    else       { s = i - E; d = i - E; }
    const int pos = atomicAdd(&g_cursor[d], 1);
    g_col[pos] = s;
}

// ---------------------------------------------------------------------------
// Fused: xp (fp32) -> xp16 (fp16) conversion + attention coefficients.
// ---------------------------------------------------------------------------
__global__ void convert_attn_kernel(const float* __restrict__ xp,
                                    __half* __restrict__ xp16,
                                    const float* __restrict__ att_src,
                                    const float* __restrict__ att_dst,
                                    float* __restrict__ a_s,
                                    float* __restrict__ a_d, int Nn)
{
    const int node = (blockIdx.x * blockDim.x + threadIdx.x) >> 5;
    const int lane = threadIdx.x & 31;
    if (node >= Nn) return;
    const int head = lane >> 3;

    const float* row = xp + (size_t)node * 256 + lane * 8;
    const float4 v0 = *(const float4*)(row);
    const float4 v1 = *(const float4*)(row + 4);

    const float* cs = att_src + lane * 8;
    const float* cd = att_dst + lane * 8;
    const float4 s0 = *(const float4*)(cs);
    const float4 s1 = *(const float4*)(cs + 4);
    const float4 d0 = *(const float4*)(cd);
    const float4 d1 = *(const float4*)(cd + 4);

    float s = v0.x * s0.x + v0.y * s0.y + v0.z * s0.z + v0.w * s0.w
            + v1.x * s1.x + v1.y * s1.y + v1.z * s1.z + v1.w * s1.w;
    float d = v0.x * d0.x + v0.y * d0.y + v0.z * d0.z + v0.w * d0.w
            + v1.x * d1.x + v1.y * d1.y + v1.z * d1.z + v1.w * d1.w;
    #pragma unroll
    for (int o = 4; o; o >>= 1) {
        s += __shfl_xor_sync(0xffffffffu, s, o);
        d += __shfl_xor_sync(0xffffffffu, d, o);
    }
    if ((lane & 7) == 0) {
        a_s[node * 4 + head] = s;
        a_d[node * 4 + head] = d;
    }

    __half2 h[4];
    h[0] = __floats2half2_rn(v0.x, v0.y);
    h[1] = __floats2half2_rn(v0.z, v0.w);
    h[2] = __floats2half2_rn(v1.x, v1.y);
    h[3] = __floats2half2_rn(v1.z, v1.w);
    *(uint4*)(xp16 + (size_t)node * 256 + lane * 8) = *(uint4*)h;
}

// ---------------------------------------------------------------------------
// GAT aggregation (fp16 messages), ALL 4 heads per warp. head = lane>>3.
// Two-pass softmax: cooperative max pre-pass, then independent exp+fma pass.
// ---------------------------------------------------------------------------
__global__ void gat_agg4_kernel(const __half* __restrict__ xp16,
                                const float* __restrict__ a_s,
                                const float* __restrict__ a_d,
                                float* __restrict__ out, int Nn)
{
    const int node = (blockIdx.x * blockDim.x + threadIdx.x) >> 5;
    const int lane = threadIdx.x & 31;
    if (node >= Nn) return;
    const int head = lane >> 3;
    const int lsub = lane & 7;

    const int beg = __ldg(&g_rowptr[node]);
    const int end = __ldg(&g_rowptr[node + 1]);
    const float adh = __ldg(&a_d[node * 4 + head]);

    // --- pass 1: per-head max of leaky_relu(e). 8 lanes per head stride edges.
    float mloc = -INFINITY;
    for (int j = beg + lsub; j < end; j += 8) {
        const int s = __ldg(&g_col[j]);
        float e = __ldg(&a_s[s * 4 + head]) + adh;
        e = (e > 0.f) ? e : 0.2f * e;
        mloc = fmaxf(mloc, e);
    }
    #pragma unroll
    for (int o = 1; o < 8; o <<= 1)
        mloc = fmaxf(mloc, __shfl_xor_sync(0xffffffffu, mloc, o));
    const float m = mloc;   // every node has >= 1 edge (self loop)

    // --- pass 2: accumulate. No cross-iteration dependency chains.
    float dsum = 0.f;
    float acc[8];
    #pragma unroll
    for (int i = 0; i < 8; ++i) acc[i] = 0.f;

    const size_t fo = (size_t)lane * 8;

    for (int j = beg; j < end; ++j) {
        const int s = __ldg(&g_col[j]);
        float e = __ldg(&a_s[s * 4 + head]) + adh;
        e = (e > 0.f) ? e : 0.2f * e;
        const float p = __expf(e - m);
        const uint4 raw = *(const uint4*)(xp16 + (size_t)s * 256 + fo);
        const float2 f0 = __half22float2(*(const __half2*)&raw.x);
        const float2 f1 = __half22float2(*(const __half2*)&raw.y);
        const float2 f2 = __half22float2(*(const __half2*)&raw.z);
        const float2 f3 = __half22float2(*(const __half2*)&raw.w);
        dsum += p;
        acc[0] = fmaf(p, f0.x, acc[0]);
        acc[1] = fmaf(p, f0.y, acc[1]);
        acc[2] = fmaf(p, f1.x, acc[2]);
        acc[3] = fmaf(p, f1.y, acc[3]);
        acc[4] = fmaf(p, f2.x, acc[4]);
        acc[5] = fmaf(p, f2.y, acc[5]);
        acc[6] = fmaf(p, f3.x, acc[6]);
        acc[7] = fmaf(p, f3.y, acc[7]);
    }

    const float inv = 1.f / (dsum + 1e-16f);
    float* orow = out + (size_t)node * 256 + fo;
    float4 o0 = make_float4(acc[0] * inv, acc[1] * inv, acc[2] * inv, acc[3] * inv);
    float4 o1 = make_float4(acc[4] * inv, acc[5] * inv, acc[6] * inv, acc[7] * inv);
    *(float4*)(orow)     = o0;
    *(float4*)(orow + 4) = o1;
}

// ---------------------------------------------------------------------------
// out = relu(LN(in + bias; g, b)) over 256 features. Warp per node.
// ---------------------------------------------------------------------------
__global__ void ln_relu_256_kernel(const float* __restrict__ in,
                                   const float* __restrict__ bias,
                                   const float* __restrict__ lg,
                                   const float* __restrict__ lb,
                                   float* __restrict__ out, int Nn)
{
    const int w = (blockIdx.x * blockDim.x + threadIdx.x) >> 5;
    const int lane = threadIdx.x & 31;
    if (w >= Nn) return;
    const float* row = in + (size_t)w * 256;

    float v[8];
    float s = 0.f;
    #pragma unroll
    for (int i = 0; i < 2; ++i) {
        const float4 x4 = *(const float4*)(row + i * 128 + lane * 4);
        const float4 b4 = *(const float4*)(bias + i * 128 + lane * 4);
        v[i * 4 + 0] = x4.x + b4.x; v[i * 4 + 1] = x4.y + b4.y;
        v[i * 4 + 2] = x4.z + b4.z; v[i * 4 + 3] = x4.w + b4.w;
        s += v[i * 4 + 0] + v[i * 4 + 1] + v[i * 4 + 2] + v[i * 4 + 3];
    }
    #pragma unroll
    for (int o = 16; o; o >>= 1) s += __shfl_xor_sync(0xffffffffu, s, o);
    const float mu = s * (1.f / 256.f);

    float q = 0.f;
    #pragma unroll
    for (int i = 0; i < 8; ++i) { const float d = v[i] - mu; q += d * d; }
    #pragma unroll
    for (int o = 16; o; o >>= 1) q += __shfl_xor_sync(0xffffffffu, q, o);
    const float rinv = rsqrtf(q * (1.f / 256.f) + 1e-5f);

    float* orow = out + (size_t)w * 256;
    #pragma unroll
    for (int i = 0; i < 2; ++i) {
        const float4 g4 = *(const float4*)(lg + i * 128 + lane * 4);
        const float4 b4 = *(const float4*)(lb + i * 128 + lane * 4);
        float4 y;
        y.x = fmaxf(fmaf((v[i * 4 + 0] - mu) * rinv, g4.x, b4.x), 0.f);
        y.y = fmaxf(fmaf((v[i * 4 + 1] - mu) * rinv, g4.y, b4.y), 0.f);
        y.z = fmaxf(fmaf((v[i * 4 + 2] - mu) * rinv, g4.z, b4.z), 0.f);
        y.w = fmaxf(fmaf((v[i * 4 + 3] - mu) * rinv, g4.w, b4.w), 0.f);
        *(float4*)(orow + i * 128 + lane * 4) = y;
    }
}

// ---------------------------------------------------------------------------
// out[n][c] = relu(LN(mean_h(hraw) + bias1)) over 64 feats. Warp per node.
// ---------------------------------------------------------------------------
__global__ void combine_ln1_kernel(const float* __restrict__ hraw,
                                   const float* __restrict__ bias,
                                   const float* __restrict__ lg,
                                   const float* __restrict__ lb,
                                   float* __restrict__ out, int Nn)
{
    const int w = (blockIdx.x * blockDim.x + threadIdx.x) >> 5;
    const int lane = threadIdx.x & 31;
    if (w >= Nn) return;
    const float* base = hraw + (size_t)w * 256;
    const int c = lane * 2;

    const float2 h0 = *(const float2*)(base + c);
    const float2 h1 = *(const float2*)(base + 64 + c);
    const float2 h2 = *(const float2*)(base + 128 + c);
    const float2 h3 = *(const float2*)(base + 192 + c);
    float tx = (h0.x + h1.x + h2.x + h3.x) * 0.25f + bias[c];
    float ty = (h0.y + h1.y + h2.y + h3.y) * 0.25f + bias[c + 1];

    float s = tx + ty;
    #pragma unroll
    for (int o = 16; o; o >>= 1) s += __shfl_xor_sync(0xffffffffu, s, o);
    const float mu = s * (1.f / 64.f);

    float q = (tx - mu) * (tx - mu) + (ty - mu) * (ty - mu);
    #pragma unroll
    for (int o = 16; o; o >>= 1) q += __shfl_xor_sync(0xffffffffu, q, o);
    const float rinv = rsqrtf(q * (1.f / 64.f) + 1e-5f);

    float2 y;
    y.x = fmaxf(fmaf((tx - mu) * rinv, lg[c], lb[c]), 0.f);
    y.y = fmaxf(fmaf((ty - mu) * rinv, lg[c + 1], lb[c + 1]), 0.f);
    *(float2*)(out + (size_t)w * 64 + c) = y;
}

// ---------------------------------------------------------------------------
extern "C" void kernel_launch(void* const* d_in, const int* in_sizes, int n_in,
                              void* d_out, int out_size)
{
    const float* nf       = (const float*)d_in[0];
    const int*   types    = (const int*)  d_in[1];
    const int*   ei       = (const int*)  d_in[2];
    const float* type_emb = (const float*)d_in[3];
    const float* proj_W   = (const float*)d_in[4];
    const float* proj_b   = (const float*)d_in[5];
    const float* W0       = (const float*)d_in[6];
    const float* att_s0   = (const float*)d_in[7];
    const float* att_d0   = (const float*)d_in[8];
    const float* bias0    = (const float*)d_in[9];
    const float* ln0_g    = (const float*)d_in[10];
    const float* ln0_b    = (const float*)d_in[11];
    const float* W1       = (const float*)d_in[12];
    const float* att_s1   = (const float*)d_in[13];
    const float* att_d1   = (const float*)d_in[14];
    const float* bias1    = (const float*)d_in[15];
    const float* ln1_g    = (const float*)d_in[16];
    const float* ln1_b    = (const float*)d_in[17];
    float* out = (float*)d_out;

    const int Nn = in_sizes[1];
    const int E  = in_sizes[2] / 2;

    float *x_p, *xp_p, *h_p, *hraw_p, *as_p, *ad_p;
    __half *xp16_p;
    cudaGetSymbolAddress((void**)&x_p,    g_x);
    cudaGetSymbolAddress((void**)&xp_p,   g_xp);
    cudaGetSymbolAddress((void**)&xp16_p, g_xp16);
    cudaGetSymbolAddress((void**)&h_p,    g_h);
    cudaGetSymbolAddress((void**)&hraw_p, g_hraw);
    cudaGetSymbolAddress((void**)&as_p,   g_as);
    cudaGetSymbolAddress((void**)&ad_p,   g_ad);

    const int nodeWarpBlocks = (Nn + 7) / 8;   // 8 warps per 256-thread block
    const int scanBlocks = (Nn + SCAN_BLK - 1) / SCAN_BLK;

    // --- input projection (fused bias + type emb) ---
    {
        dim3 grid(1, (Nn + 63) / 64);
        sgemm_proj_kernel<<<grid, 256>>>(nf, proj_W, x_p, Nn, 64, 64,
                                         proj_b, type_emb, types);
    }

    // --- CSR build (parallel scan) ---
    init_counts_kernel<<<(Nn + 255) / 256, 256>>>(Nn);
    hist_kernel<<<(E + 255) / 256, 256>>>(ei + E, E);
    scan_p1_kernel<<<scanBlocks, SCAN_BLK>>>(Nn);
    scan_p2_kernel<<<1, SCAN_BLK>>>(scanBlocks, Nn);
    scan_p3_kernel<<<(Nn + 255) / 256, 256>>>(Nn);
    scatter_kernel<<<(E + Nn + 255) / 256, 256>>>(ei, E, Nn);

    // --- layer 0 ---
    {
        dim3 grid(2, (Nn + 127) / 128);
        sgemm128_kernel<<<grid, 256>>>(x_p, W0, xp_p, Nn, 64, 256);
    }
    convert_attn_kernel<<<nodeWarpBlocks, 256>>>(xp_p, xp16_p, att_s0, att_d0,
                                                 as_p, ad_p, Nn);
    gat_agg4_kernel<<<nodeWarpBlocks, 256>>>(xp16_p, as_p, ad_p, hraw_p, Nn);
    ln_relu_256_kernel<<<nodeWarpBlocks, 256>>>(hraw_p, bias0, ln0_g, ln0_b, h_p, Nn);

    // --- layer 1 ---
    {
        dim3 grid(2, (Nn + 127) / 128);
        sgemm128_kernel<<<grid, 256>>>(h_p, W1, xp_p, Nn, 256, 256);
    }
    convert_attn_kernel<<<nodeWarpBlocks, 256>>>(xp_p, xp16_p, att_s1, att_d1,
                                                 as_p, ad_p, Nn);
    gat_agg4_kernel<<<nodeWarpBlocks, 256>>>(xp16_p, as_p, ad_p, hraw_p, Nn);
    combine_ln1_kernel<<<nodeWarpBlocks, 256>>>(hraw_p, bias1, ln1_g, ln1_b, out, Nn);
}

// round 5
// speedup vs baseline: 2.7061x; 1.6285x over previous
#include <cuda_runtime.h>
#include <cuda_fp16.h>
#include <cuda_bf16.h>
#include <mma.h>
#include <math.h>

using namespace nvcuda;

// ---------------------------------------------------------------------------
// TGN_GAT: 2-layer GAT (N=50000, E=800000, F=64, HID=64, HEADS=4)
// fp16 tensor-core GEMMs, fp16 message gather, fp32 accumulation everywhere.
// ---------------------------------------------------------------------------

#define MAXN 50000
#define MAXE 800000
#define MAXTOT (MAXE + MAXN)
#define SCAN_BLK 256
#define MAX_SCAN_BLOCKS ((MAXN + SCAN_BLK - 1) / SCAN_BLK)

__device__ __half g_x16[(size_t)MAXN * 64];
__device__ __half g_h16[(size_t)MAXN * 256];
__device__ __half g_xp16[(size_t)MAXN * 256];
__device__ __half g_w0h[64 * 256];
__device__ __half g_w1h[256 * 256];
__device__ float  g_hraw[(size_t)MAXN * 256];
__device__ float  g_as[(size_t)MAXN * 4];
__device__ float  g_ad[(size_t)MAXN * 4];
__device__ int    g_rowptr[MAXN + 1];
__device__ int    g_cursor[MAXN];
__device__ int    g_counts[MAXN];
__device__ int    g_scanex[MAXN];
__device__ int    g_bsum[MAX_SCAN_BLOCKS];
__device__ int    g_boff[MAX_SCAN_BLOCKS];
__device__ int    g_col[MAXTOT];

// ---------------------------------------------------------------------------
// float -> half conversion (for weight matrices)
// ---------------------------------------------------------------------------
__global__ void f2h_kernel(const float* __restrict__ in, __half* __restrict__ out, int n2)
{
    const int i = blockIdx.x * blockDim.x + threadIdx.x;
    if (i < n2) {
        const float2 v = *(const float2*)(in + i * 2);
        *(__half2*)(out + i * 2) = __floats2half2_rn(v.x, v.y);
    }
}

// ---------------------------------------------------------------------------
// Projection SGEMM (64x64 tile, fp32 math) with fused bias + type-embedding;
// writes fp16 output x16.
// ---------------------------------------------------------------------------
__global__ __launch_bounds__(256) void sgemm_proj_kernel(
    const float* __restrict__ A, const float* __restrict__ B,
    __half* __restrict__ C16, int M, int K, int Nc,
    const float* __restrict__ pb, const float* __restrict__ emb,
    const int* __restrict__ types)
{
    __shared__ float As[16][65];
    __shared__ float Bs[16][64];

    const int tid = threadIdx.x;
    const int tx = tid & 15;
    const int ty = tid >> 4;
    const int rowBase = blockIdx.y * 64;
    const int colBase = blockIdx.x * 64;

    const int ar = tid >> 2;
    const int ak = (tid & 3) << 2;
    const int bk = tid >> 4;
    const int bn = (tid & 15) << 2;

    float4 acc0 = make_float4(0.f, 0.f, 0.f, 0.f);
    float4 acc1 = acc0, acc2 = acc0, acc3 = acc0;

    for (int k0 = 0; k0 < K; k0 += 16) {
        float4 av;
        const int arow = rowBase + ar;
        if (arow < M)
            av = *(const float4*)(A + (size_t)arow * K + k0 + ak);
        else
            av = make_float4(0.f, 0.f, 0.f, 0.f);
        As[ak + 0][ar] = av.x;
        As[ak + 1][ar] = av.y;
        As[ak + 2][ar] = av.z;
        As[ak + 3][ar] = av.w;

        float4 bv = *(const float4*)(B + (size_t)(k0 + bk) * Nc + colBase + bn);
        *(float4*)&Bs[bk][bn] = bv;

        __syncthreads();

        #pragma unroll
        for (int kk = 0; kk < 16; ++kk) {
            const float4 b4 = *(const float4*)&Bs[kk][tx << 2];
            const float a0 = As[kk][(ty << 2) + 0];
            const float a1 = As[kk][(ty << 2) + 1];
            const float a2 = As[kk][(ty << 2) + 2];
            const float a3 = As[kk][(ty << 2) + 3];
            acc0.x = fmaf(a0, b4.x, acc0.x); acc0.y = fmaf(a0, b4.y, acc0.y);
            acc0.z = fmaf(a0, b4.z, acc0.z); acc0.w = fmaf(a0, b4.w, acc0.w);
            acc1.x = fmaf(a1, b4.x, acc1.x); acc1.y = fmaf(a1, b4.y, acc1.y);
            acc1.z = fmaf(a1, b4.z, acc1.z); acc1.w = fmaf(a1, b4.w, acc1.w);
            acc2.x = fmaf(a2, b4.x, acc2.x); acc2.y = fmaf(a2, b4.y, acc2.y);
            acc2.z = fmaf(a2, b4.z, acc2.z); acc2.w = fmaf(a2, b4.w, acc2.w);
            acc3.x = fmaf(a3, b4.x, acc3.x); acc3.y = fmaf(a3, b4.y, acc3.y);
            acc3.z = fmaf(a3, b4.z, acc3.z); acc3.w = fmaf(a3, b4.w, acc3.w);
        }
        __syncthreads();
    }

    const int col = colBase + (tx << 2);
    const float4 pb4 = *(const float4*)(pb + col);
    const int row0 = rowBase + (ty << 2);
    #pragma unroll
    for (int i = 0; i < 4; ++i) {
        const int r = row0 + i;
        if (r >= M) break;
        float4 a = (i == 0) ? acc0 : (i == 1) ? acc1 : (i == 2) ? acc2 : acc3;
        const float4 e4 = *(const float4*)(emb + types[r] * 64 + col);
        a.x += pb4.x + e4.x; a.y += pb4.y + e4.y;
        a.z += pb4.z + e4.z; a.w += pb4.w + e4.w;
        __half2 hh[2];
        hh[0] = __floats2half2_rn(a.x, a.y);
        hh[1] = __floats2half2_rn(a.z, a.w);
        *(uint2*)(C16 + (size_t)r * Nc + col) = *(uint2*)hh;
    }
}

// ---------------------------------------------------------------------------
// fp16 tensor-core GEMM: C16[M,N] = A16[M,K] @ B16[K,N]  (fp32 accum).
// Block tile 64x64, 4 warps (2x2), each warp 32x32 via 2x2 wmma 16x16x16.
// K % 32 == 0, N % 64 == 0.
// ---------------------------------------------------------------------------
#define HBM_ 64
#define HBN_ 64
#define HBK_ 32

__global__ __launch_bounds__(128) void hgemm_kernel(
    const __half* __restrict__ A, const __half* __restrict__ B,
    __half* __restrict__ C, int M, int K, int N)
{
    __shared__ __half As[HBM_][HBK_ + 8];
    __shared__ __half Bs[HBK_][HBN_ + 8];
    __shared__ float  Cs[HBM_][HBN_ + 8];

    const int tid = threadIdx.x;
    const int wid = tid >> 5;
    const int wr = wid >> 1;
    const int wc = wid & 1;
    const int rowBase = blockIdx.y * HBM_;
    const int colBase = blockIdx.x * HBN_;

    wmma::fragment<wmma::accumulator, 16, 16, 16, float> acc[2][2];
    #pragma unroll
    for (int i = 0; i < 2; ++i)
        #pragma unroll
        for (int j = 0; j < 2; ++j)
            wmma::fill_fragment(acc[i][j], 0.f);

    for (int k0 = 0; k0 < K; k0 += HBK_) {
        #pragma unroll
        for (int i = tid; i < HBM_ * HBK_ / 8; i += 128) {
            const int r = i >> 2;
            const int c8 = (i & 3) * 8;
            const int gr = rowBase + r;
            uint4 v = make_uint4(0u, 0u, 0u, 0u);
            if (gr < M) v = *(const uint4*)(A + (size_t)gr * K + k0 + c8);
            *(uint4*)&As[r][c8] = v;
        }
        #pragma unroll
        for (int i = tid; i < HBK_ * HBN_ / 8; i += 128) {
            const int r = i >> 3;
            const int c8 = (i & 7) * 8;
            *(uint4*)&Bs[r][c8] = *(const uint4*)(B + (size_t)(k0 + r) * N + colBase + c8);
        }
        __syncthreads();

        #pragma unroll
        for (int kk = 0; kk < HBK_; kk += 16) {
            wmma::fragment<wmma::matrix_a, 16, 16, 16, __half, wmma::row_major> af[2];
            wmma::fragment<wmma::matrix_b, 16, 16, 16, __half, wmma::row_major> bf[2];
            #pragma unroll
            for (int i = 0; i < 2; ++i)
                wmma::load_matrix_sync(af[i], &As[wr * 32 + i * 16][kk], HBK_ + 8);
            #pragma unroll
            for (int j = 0; j < 2; ++j)
                wmma::load_matrix_sync(bf[j], &Bs[kk][wc * 32 + j * 16], HBN_ + 8);
            #pragma unroll
            for (int i = 0; i < 2; ++i)
                #pragma unroll
                for (int j = 0; j < 2; ++j)
                    wmma::mma_sync(acc[i][j], af[i], bf[j], acc[i][j]);
        }
        __syncthreads();
    }

    #pragma unroll
    for (int i = 0; i < 2; ++i)
        #pragma unroll
        for (int j = 0; j < 2; ++j)
            wmma::store_matrix_sync(&Cs[wr * 32 + i * 16][wc * 32 + j * 16],
                                    acc[i][j], HBN_ + 8, wmma::mem_row_major);
    __syncthreads();

    #pragma unroll
    for (int i = tid; i < HBM_ * HBN_ / 2; i += 128) {
        const int r = i >> 5;
        const int c2 = (i & 31) * 2;
        const int gr = rowBase + r;
        if (gr < M) {
            const __half2 hv = __floats2half2_rn(Cs[r][c2], Cs[r][c2 + 1]);
            *(__half2*)(C + (size_t)gr * N + colBase + c2) = hv;
        }
    }
}

// ---------------------------------------------------------------------------
// CSR build
// ---------------------------------------------------------------------------
__global__ void init_counts_kernel(int Nn)
{
    const int i = blockIdx.x * blockDim.x + threadIdx.x;
    if (i < Nn) g_counts[i] = 1;
}

__global__ void hist_kernel(const int* __restrict__ dst, int E)
{
    const int i = blockIdx.x * blockDim.x + threadIdx.x;
    if (i < E) atomicAdd(&g_counts[dst[i]], 1);
}

__global__ __launch_bounds__(SCAN_BLK) void scan_p1_kernel(int Nn)
{
    __shared__ int sh[SCAN_BLK];
    const int t = threadIdx.x;
    const int i = blockIdx.x * SCAN_BLK + t;
    int v = (i < Nn) ? g_counts[i] : 0;
    sh[t] = v;
    __syncthreads();

    int inc = v;
    #pragma unroll
    for (int off = 1; off < SCAN_BLK; off <<= 1) {
        int add = (t >= off) ? sh[t - off] : 0;
        __syncthreads();
        inc += add;
        sh[t] = inc;
        __syncthreads();
    }
    if (i < Nn) g_scanex[i] = inc - v;
    if (t == SCAN_BLK - 1) g_bsum[blockIdx.x] = inc;
}

__global__ __launch_bounds__(SCAN_BLK) void scan_p2_kernel(int nblocks, int Nn)
{
    __shared__ int sh[SCAN_BLK];
    const int t = threadIdx.x;
    int v = (t < nblocks) ? g_bsum[t] : 0;
    sh[t] = v;
    __syncthreads();

    int inc = v;
    #pragma unroll
    for (int off = 1; off < SCAN_BLK; off <<= 1) {
        int add = (t >= off) ? sh[t - off] : 0;
        __syncthreads();
        inc += add;
        sh[t] = inc;
        __syncthreads();
    }
    if (t < nblocks) g_boff[t] = inc - v;
    if (t == SCAN_BLK - 1) g_rowptr[Nn] = sh[SCAN_BLK - 1];
}

__global__ void scan_p3_kernel(int Nn)
{
    const int i = blockIdx.x * blockDim.x + threadIdx.x;
    if (i >= Nn) return;
    const int val = g_scanex[i] + g_boff[i >> 8];
    g_rowptr[i] = val;
    g_cursor[i] = val;
}

__global__ void scatter_kernel(const int* __restrict__ ei, int E, int Nn)
{
    const int i = blockIdx.x * blockDim.x + threadIdx.x;
    if (i >= E + Nn) return;
    int s, d;
    if (i < E) { s = ei[i]; d = ei[E + i]; }
    else       { s = i - E; d = i - E; }
    const int pos = atomicAdd(&g_cursor[d], 1);
    g_col[pos] = s;
}

// ---------------------------------------------------------------------------
// Attention coefficients from fp16 xp. Warp per node; head = lane>>3.
// ---------------------------------------------------------------------------
__global__ void attn_kernel(const __half* __restrict__ xp16,
                            const float* __restrict__ att_src,
                            const float* __restrict__ att_dst,
                            float* __restrict__ a_s,
                            float* __restrict__ a_d, int Nn)
{
    const int node = (blockIdx.x * blockDim.x + threadIdx.x) >> 5;
    const int lane = threadIdx.x & 31;
    if (node >= Nn) return;
    const int head = lane >> 3;

    const uint4 raw = *(const uint4*)(xp16 + (size_t)node * 256 + lane * 8);
    const float2 f0 = __half22float2(*(const __half2*)&raw.x);
    const float2 f1 = __half22float2(*(const __half2*)&raw.y);
    const float2 f2 = __half22float2(*(const __half2*)&raw.z);
    const float2 f3 = __half22float2(*(const __half2*)&raw.w);

    const float* cs = att_src + lane * 8;
    const float* cd = att_dst + lane * 8;
    const float4 s0 = *(const float4*)(cs);
    const float4 s1 = *(const float4*)(cs + 4);
    const float4 d0 = *(const float4*)(cd);
    const float4 d1 = *(const float4*)(cd + 4);

    float s = f0.x * s0.x + f0.y * s0.y + f1.x * s0.z + f1.y * s0.w
            + f2.x * s1.x + f2.y * s1.y + f3.x * s1.z + f3.y * s1.w;
    float d = f0.x * d0.x + f0.y * d0.y + f1.x * d0.z + f1.y * d0.w
            + f2.x * d1.x + f2.y * d1.y + f3.x * d1.z + f3.y * d1.w;
    #pragma unroll
    for (int o = 4; o; o >>= 1) {
        s += __shfl_xor_sync(0xffffffffu, s, o);
        d += __shfl_xor_sync(0xffffffffu, d, o);
    }
    if ((lane & 7) == 0) {
        a_s[node * 4 + head] = s;
        a_d[node * 4 + head] = d;
    }
}

// ---------------------------------------------------------------------------
// GAT aggregation (fp16 messages), all 4 heads per warp. Two-pass softmax.
// ---------------------------------------------------------------------------
__global__ void gat_agg4_kernel(const __half* __restrict__ xp16,
                                const float* __restrict__ a_s,
                                const float* __restrict__ a_d,
                                float* __restrict__ out, int Nn)
{
    const int node = (blockIdx.x * blockDim.x + threadIdx.x) >> 5;
    const int lane = threadIdx.x & 31;
    if (node >= Nn) return;
    const int head = lane >> 3;
    const int lsub = lane & 7;

    const int beg = __ldg(&g_rowptr[node]);
    const int end = __ldg(&g_rowptr[node + 1]);
    const float adh = __ldg(&a_d[node * 4 + head]);

    float mloc = -INFINITY;
    for (int j = beg + lsub; j < end; j += 8) {
        const int s = __ldg(&g_col[j]);
        float e = __ldg(&a_s[s * 4 + head]) + adh;
        e = (e > 0.f) ? e : 0.2f * e;
        mloc = fmaxf(mloc, e);
    }
    #pragma unroll
    for (int o = 1; o < 8; o <<= 1)
        mloc = fmaxf(mloc, __shfl_xor_sync(0xffffffffu, mloc, o));
    const float m = mloc;

    float dsum = 0.f;
    float acc[8];
    #pragma unroll
    for (int i = 0; i < 8; ++i) acc[i] = 0.f;

    const size_t fo = (size_t)lane * 8;

    for (int j = beg; j < end; ++j) {
        const int s = __ldg(&g_col[j]);
        float e = __ldg(&a_s[s * 4 + head]) + adh;
        e = (e > 0.f) ? e : 0.2f * e;
        const float p = __expf(e - m);
        const uint4 raw = *(const uint4*)(xp16 + (size_t)s * 256 + fo);
        const float2 f0 = __half22float2(*(const __half2*)&raw.x);
        const float2 f1 = __half22float2(*(const __half2*)&raw.y);
        const float2 f2 = __half22float2(*(const __half2*)&raw.z);
        const float2 f3 = __half22float2(*(const __half2*)&raw.w);
        dsum += p;
        acc[0] = fmaf(p, f0.x, acc[0]);
        acc[1] = fmaf(p, f0.y, acc[1]);
        acc[2] = fmaf(p, f1.x, acc[2]);
        acc[3] = fmaf(p, f1.y, acc[3]);
        acc[4] = fmaf(p, f2.x, acc[4]);
        acc[5] = fmaf(p, f2.y, acc[5]);
        acc[6] = fmaf(p, f3.x, acc[6]);
        acc[7] = fmaf(p, f3.y, acc[7]);
    }

    const float inv = 1.f / (dsum + 1e-16f);
    float* orow = out + (size_t)node * 256 + fo;
    float4 o0 = make_float4(acc[0] * inv, acc[1] * inv, acc[2] * inv, acc[3] * inv);
    float4 o1 = make_float4(acc[4] * inv, acc[5] * inv, acc[6] * inv, acc[7] * inv);
    *(float4*)(orow)     = o0;
    *(float4*)(orow + 4) = o1;
}

// ---------------------------------------------------------------------------
// h16 = fp16(relu(LN(in + bias; g, b))) over 256 features. Warp per node.
// ---------------------------------------------------------------------------
__global__ void ln_relu_256_kernel(const float* __restrict__ in,
                                   const float* __restrict__ bias,
                                   const float* __restrict__ lg,
                                   const float* __restrict__ lb,
                                   __half* __restrict__ out16, int Nn)
{
    const int w = (blockIdx.x * blockDim.x + threadIdx.x) >> 5;
    const int lane = threadIdx.x & 31;
    if (w >= Nn) return;
    const float* row = in + (size_t)w * 256;

    float v[8];
    float s = 0.f;
    #pragma unroll
    for (int i = 0; i < 2; ++i) {
        const float4 x4 = *(const float4*)(row + i * 128 + lane * 4);
        const float4 b4 = *(const float4*)(bias + i * 128 + lane * 4);
        v[i * 4 + 0] = x4.x + b4.x; v[i * 4 + 1] = x4.y + b4.y;
        v[i * 4 + 2] = x4.z + b4.z; v[i * 4 + 3] = x4.w + b4.w;
        s += v[i * 4 + 0] + v[i * 4 + 1] + v[i * 4 + 2] + v[i * 4 + 3];
    }
    #pragma unroll
    for (int o = 16; o; o >>= 1) s += __shfl_xor_sync(0xffffffffu, s, o);
    const float mu = s * (1.f / 256.f);

    float q = 0.f;
    #pragma unroll
    for (int i = 0; i < 8; ++i) { const float d = v[i] - mu; q += d * d; }
    #pragma unroll
    for (int o = 16; o; o >>= 1) q += __shfl_xor_sync(0xffffffffu, q, o);
    const float rinv = rsqrtf(q * (1.f / 256.f) + 1e-5f);

    __half* orow = out16 + (size_t)w * 256;
    #pragma unroll
    for (int i = 0; i < 2; ++i) {
        const float4 g4 = *(const float4*)(lg + i * 128 + lane * 4);
        const float4 b4 = *(const float4*)(lb + i * 128 + lane * 4);
        float4 y;
        y.x = fmaxf(fmaf((v[i * 4 + 0] - mu) * rinv, g4.x, b4.x), 0.f);
        y.y = fmaxf(fmaf((v[i * 4 + 1] - mu) * rinv, g4.y, b4.y), 0.f);
        y.z = fmaxf(fmaf((v[i * 4 + 2] - mu) * rinv, g4.z, b4.z), 0.f);
        y.w = fmaxf(fmaf((v[i * 4 + 3] - mu) * rinv, g4.w, b4.w), 0.f);
        __half2 hh[2];
        hh[0] = __floats2half2_rn(y.x, y.y);
        hh[1] = __floats2half2_rn(y.z, y.w);
        *(uint2*)(orow + i * 128 + lane * 4) = *(uint2*)hh;
    }
}

// ---------------------------------------------------------------------------
// out[n][c] = relu(LN(mean_h(hraw) + bias1)) over 64 feats. Warp per node.
// ---------------------------------------------------------------------------
__global__ void combine_ln1_kernel(const float* __restrict__ hraw,
                                   const float* __restrict__ bias,
                                   const float* __restrict__ lg,
                                   const float* __restrict__ lb,
                                   float* __restrict__ out, int Nn)
{
    const int w = (blockIdx.x * blockDim.x + threadIdx.x) >> 5;
    const int lane = threadIdx.x & 31;
    if (w >= Nn) return;
    const float* base = hraw + (size_t)w * 256;
    const int c = lane * 2;

    const float2 h0 = *(const float2*)(base + c);
    const float2 h1 = *(const float2*)(base + 64 + c);
    const float2 h2 = *(const float2*)(base + 128 + c);
    const float2 h3 = *(const float2*)(base + 192 + c);
    float tx = (h0.x + h1.x + h2.x + h3.x) * 0.25f + bias[c];
    float ty = (h0.y + h1.y + h2.y + h3.y) * 0.25f + bias[c + 1];

    float s = tx + ty;
    #pragma unroll
    for (int o = 16; o; o >>= 1) s += __shfl_xor_sync(0xffffffffu, s, o);
    const float mu = s * (1.f / 64.f);

    float q = (tx - mu) * (tx - mu) + (ty - mu) * (ty - mu);
    #pragma unroll
    for (int o = 16; o; o >>= 1) q += __shfl_xor_sync(0xffffffffu, q, o);
    const float rinv = rsqrtf(q * (1.f / 64.f) + 1e-5f);

    float2 y;
    y.x = fmaxf(fmaf((tx - mu) * rinv, lg[c], lb[c]), 0.f);
    y.y = fmaxf(fmaf((ty - mu) * rinv, lg[c + 1], lb[c + 1]), 0.f);
    *(float2*)(out + (size_t)w * 64 + c) = y;
}

// ---------------------------------------------------------------------------
extern "C" void kernel_launch(void* const* d_in, const int* in_sizes, int n_in,
                              void* d_out, int out_size)
{
    const float* nf       = (const float*)d_in[0];
    const int*   types    = (const int*)  d_in[1];
    const int*   ei       = (const int*)  d_in[2];
    const float* type_emb = (const float*)d_in[3];
    const float* proj_W   = (const float*)d_in[4];
    const float* proj_b   = (const float*)d_in[5];
    const float* W0       = (const float*)d_in[6];
    const float* att_s0   = (const float*)d_in[7];
    const float* att_d0   = (const float*)d_in[8];
    const float* bias0    = (const float*)d_in[9];
    const float* ln0_g    = (const float*)d_in[10];
    const float* ln0_b    = (const float*)d_in[11];
    const float* W1       = (const float*)d_in[12];
    const float* att_s1   = (const float*)d_in[13];
    const float* att_d1   = (const float*)d_in[14];
    const float* bias1    = (const float*)d_in[15];
    const float* ln1_g    = (const float*)d_in[16];
    const float* ln1_b    = (const float*)d_in[17];
    float* out = (float*)d_out;

    const int Nn = in_sizes[1];
    const int E  = in_sizes[2] / 2;

    __half *x16_p, *h16_p, *xp16_p, *w0h_p, *w1h_p;
    float *hraw_p, *as_p, *ad_p;
    cudaGetSymbolAddress((void**)&x16_p,  g_x16);
    cudaGetSymbolAddress((void**)&h16_p,  g_h16);
    cudaGetSymbolAddress((void**)&xp16_p, g_xp16);
    cudaGetSymbolAddress((void**)&w0h_p,  g_w0h);
    cudaGetSymbolAddress((void**)&w1h_p,  g_w1h);
    cudaGetSymbolAddress((void**)&hraw_p, g_hraw);
    cudaGetSymbolAddress((void**)&as_p,   g_as);
    cudaGetSymbolAddress((void**)&ad_p,   g_ad);

    const int nodeWarpBlocks = (Nn + 7) / 8;
    const int scanBlocks = (Nn + SCAN_BLK - 1) / SCAN_BLK;

    // --- weight conversion (fp32 -> fp16) ---
    f2h_kernel<<<(64 * 256 / 2 + 255) / 256, 256>>>(W0, w0h_p, 64 * 256 / 2);
    f2h_kernel<<<(256 * 256 / 2 + 255) / 256, 256>>>(W1, w1h_p, 256 * 256 / 2);

    // --- input projection (fp32 math, fp16 out, fused bias + emb) ---
    {
        dim3 grid(1, (Nn + 63) / 64);
        sgemm_proj_kernel<<<grid, 256>>>(nf, proj_W, x16_p, Nn, 64, 64,
                                         proj_b, type_emb, types);
    }

    // --- CSR build ---
    init_counts_kernel<<<(Nn + 255) / 256, 256>>>(Nn);
    hist_kernel<<<(E + 255) / 256, 256>>>(ei + E, E);
    scan_p1_kernel<<<scanBlocks, SCAN_BLK>>>(Nn);
    scan_p2_kernel<<<1, SCAN_BLK>>>(scanBlocks, Nn);
    scan_p3_kernel<<<(Nn + 255) / 256, 256>>>(Nn);
    scatter_kernel<<<(E + Nn + 255) / 256, 256>>>(ei, E, Nn);

    // --- layer 0 ---
    {
        dim3 grid(256 / HBN_, (Nn + HBM_ - 1) / HBM_);
        hgemm_kernel<<<grid, 128>>>(x16_p, w0h_p, xp16_p, Nn, 64, 256);
    }
    attn_kernel<<<nodeWarpBlocks, 256>>>(xp16_p, att_s0, att_d0, as_p, ad_p, Nn);
    gat_agg4_kernel<<<nodeWarpBlocks, 256>>>(xp16_p, as_p, ad_p, hraw_p, Nn);
    ln_relu_256_kernel<<<nodeWarpBlocks, 256>>>(hraw_p, bias0, ln0_g, ln0_b, h16_p, Nn);

    // --- layer 1 ---
    {
        dim3 grid(256 / HBN_, (Nn + HBM_ - 1) / HBM_);
        hgemm_kernel<<<grid, 128>>>(h16_p, w1h_p, xp16_p, Nn, 256, 256);
    }
    attn_kernel<<<nodeWarpBlocks, 256>>>(xp16_p, att_s1, att_d1, as_p, ad_p, Nn);
    gat_agg4_kernel<<<nodeWarpBlocks, 256>>>(xp16_p, as_p, ad_p, hraw_p, Nn);
    combine_ln1_kernel<<<nodeWarpBlocks, 256>>>(hraw_p, bias1, ln1_g, ln1_b, out, Nn);
}

// round 6
// speedup vs baseline: 2.7104x; 1.0016x over previous
#include <cuda_runtime.h>
#include <cuda_fp16.h>
#include <cuda_bf16.h>
#include <mma.h>
#include <math.h>

using namespace nvcuda;

// ---------------------------------------------------------------------------
// TGN_GAT: 2-layer GAT (N=50000, E=800000, F=64, HID=64, HEADS=4)
// All GEMMs on tensor cores (fp16 in / fp32 accum), fp16 message gather.
// ---------------------------------------------------------------------------

#define MAXN 50000
#define MAXE 800000
#define MAXTOT (MAXE + MAXN)
#define SCAN_BLK 256
#define MAX_SCAN_BLOCKS ((MAXN + SCAN_BLK - 1) / SCAN_BLK)

__device__ __half g_nf16[(size_t)MAXN * 64];
__device__ __half g_x16[(size_t)MAXN * 64];
__device__ __half g_h16[(size_t)MAXN * 256];
__device__ __half g_xp16[(size_t)MAXN * 256];
__device__ __half g_pwh[64 * 64];
__device__ __half g_w0h[64 * 256];
__device__ __half g_w1h[256 * 256];
__device__ float  g_hraw[(size_t)MAXN * 256];
__device__ float  g_as[(size_t)MAXN * 4];
__device__ float  g_ad[(size_t)MAXN * 4];
__device__ int    g_rowptr[MAXN + 1];
__device__ int    g_cursor[MAXN];
__device__ int    g_counts[MAXN];
__device__ int    g_scanex[MAXN];
__device__ int    g_bsum[MAX_SCAN_BLOCKS];
__device__ int    g_boff[MAX_SCAN_BLOCKS];
__device__ int    g_col[MAXTOT];

// ---------------------------------------------------------------------------
// float -> half conversion
// ---------------------------------------------------------------------------
__global__ void f2h_kernel(const float* __restrict__ in, __half* __restrict__ out, int n2)
{
    const int i = blockIdx.x * blockDim.x + threadIdx.x;
    if (i < n2) {
        const float2 v = *(const float2*)(in + i * 2);
        *(__half2*)(out + i * 2) = __floats2half2_rn(v.x, v.y);
    }
}

// ---------------------------------------------------------------------------
// fp16 tensor-core GEMM: C16[M,N] = A16[M,K] @ B16[K,N]  (fp32 accum).
// Block tile 64x64, 4 warps (2x2), each warp 32x32 via 2x2 wmma 16x16x16.
// Optional fused epilogue: + pb[c] + emb[types[r]*64 + c]  (proj path).
// ---------------------------------------------------------------------------
#define HBM_ 64
#define HBN_ 64
#define HBK_ 32

template <bool EPI>
__global__ __launch_bounds__(128) void hgemm_kernel(
    const __half* __restrict__ A, const __half* __restrict__ B,
    __half* __restrict__ C, int M, int K, int N,
    const float* __restrict__ pb, const float* __restrict__ emb,
    const int* __restrict__ types)
{
    __shared__ __half As[HBM_][HBK_ + 8];
    __shared__ __half Bs[HBK_][HBN_ + 8];
    __shared__ float  Cs[HBM_][HBN_ + 8];

    const int tid = threadIdx.x;
    const int wid = tid >> 5;
    const int wr = wid >> 1;
    const int wc = wid & 1;
    const int rowBase = blockIdx.y * HBM_;
    const int colBase = blockIdx.x * HBN_;

    wmma::fragment<wmma::accumulator, 16, 16, 16, float> acc[2][2];
    #pragma unroll
    for (int i = 0; i < 2; ++i)
        #pragma unroll
        for (int j = 0; j < 2; ++j)
            wmma::fill_fragment(acc[i][j], 0.f);

    for (int k0 = 0; k0 < K; k0 += HBK_) {
        #pragma unroll
        for (int i = tid; i < HBM_ * HBK_ / 8; i += 128) {
            const int r = i >> 2;
            const int c8 = (i & 3) * 8;
            const int gr = rowBase + r;
            uint4 v = make_uint4(0u, 0u, 0u, 0u);
            if (gr < M) v = *(const uint4*)(A + (size_t)gr * K + k0 + c8);
            *(uint4*)&As[r][c8] = v;
        }
        #pragma unroll
        for (int i = tid; i < HBK_ * HBN_ / 8; i += 128) {
            const int r = i >> 3;
            const int c8 = (i & 7) * 8;
            *(uint4*)&Bs[r][c8] = *(const uint4*)(B + (size_t)(k0 + r) * N + colBase + c8);
        }
        __syncthreads();

        #pragma unroll
        for (int kk = 0; kk < HBK_; kk += 16) {
            wmma::fragment<wmma::matrix_a, 16, 16, 16, __half, wmma::row_major> af[2];
            wmma::fragment<wmma::matrix_b, 16, 16, 16, __half, wmma::row_major> bf[2];
            #pragma unroll
            for (int i = 0; i < 2; ++i)
                wmma::load_matrix_sync(af[i], &As[wr * 32 + i * 16][kk], HBK_ + 8);
            #pragma unroll
            for (int j = 0; j < 2; ++j)
                wmma::load_matrix_sync(bf[j], &Bs[kk][wc * 32 + j * 16], HBN_ + 8);
            #pragma unroll
            for (int i = 0; i < 2; ++i)
                #pragma unroll
                for (int j = 0; j < 2; ++j)
                    wmma::mma_sync(acc[i][j], af[i], bf[j], acc[i][j]);
        }
        __syncthreads();
    }

    #pragma unroll
    for (int i = 0; i < 2; ++i)
        #pragma unroll
        for (int j = 0; j < 2; ++j)
            wmma::store_matrix_sync(&Cs[wr * 32 + i * 16][wc * 32 + j * 16],
                                    acc[i][j], HBN_ + 8, wmma::mem_row_major);
    __syncthreads();

    #pragma unroll
    for (int i = tid; i < HBM_ * HBN_ / 2; i += 128) {
        const int r = i >> 5;
        const int c2 = (i & 31) * 2;
        const int gr = rowBase + r;
        if (gr < M) {
            float vx = Cs[r][c2];
            float vy = Cs[r][c2 + 1];
            if (EPI) {
                const int col = colBase + c2;
                const float2 p2 = *(const float2*)(pb + col);
                const float2 e2 = *(const float2*)(emb + types[gr] * 64 + col);
                vx += p2.x + e2.x;
                vy += p2.y + e2.y;
            }
            *(__half2*)(C + (size_t)gr * N + colBase + c2) = __floats2half2_rn(vx, vy);
        }
    }
}

// ---------------------------------------------------------------------------
// CSR build
// ---------------------------------------------------------------------------
__global__ void hist_kernel(const int* __restrict__ dst, int E)
{
    const int i = blockIdx.x * blockDim.x + threadIdx.x;
    if (i < E) atomicAdd(&g_counts[dst[i]], 1);
}

// Phase 1: per-block exclusive scan of (counts[i] + 1)  [+1 = self loop]
__global__ __launch_bounds__(SCAN_BLK) void scan_p1_kernel(int Nn)
{
    __shared__ int sh[SCAN_BLK];
    const int t = threadIdx.x;
    const int i = blockIdx.x * SCAN_BLK + t;
    int v = (i < Nn) ? (g_counts[i] + 1) : 0;
    sh[t] = v;
    __syncthreads();

    int inc = v;
    #pragma unroll
    for (int off = 1; off < SCAN_BLK; off <<= 1) {
        int add = (t >= off) ? sh[t - off] : 0;
        __syncthreads();
        inc += add;
        sh[t] = inc;
        __syncthreads();
    }
    if (i < Nn) g_scanex[i] = inc - v;
    if (t == SCAN_BLK - 1) g_bsum[blockIdx.x] = inc;
}

__global__ __launch_bounds__(SCAN_BLK) void scan_p2_kernel(int nblocks, int Nn)
{
    __shared__ int sh[SCAN_BLK];
    const int t = threadIdx.x;
    int v = (t < nblocks) ? g_bsum[t] : 0;
    sh[t] = v;
    __syncthreads();

    int inc = v;
    #pragma unroll
    for (int off = 1; off < SCAN_BLK; off <<= 1) {
        int add = (t >= off) ? sh[t - off] : 0;
        __syncthreads();
        inc += add;
        sh[t] = inc;
        __syncthreads();
    }
    if (t < nblocks) g_boff[t] = inc - v;
    if (t == SCAN_BLK - 1) g_rowptr[Nn] = sh[SCAN_BLK - 1];
}

__global__ void scan_p3_kernel(int Nn)
{
    const int i = blockIdx.x * blockDim.x + threadIdx.x;
    if (i >= Nn) return;
    const int val = g_scanex[i] + g_boff[i >> 8];
    g_rowptr[i] = val;
    g_cursor[i] = val;
}

__global__ void scatter_kernel(const int* __restrict__ ei, int E, int Nn)
{
    const int i = blockIdx.x * blockDim.x + threadIdx.x;
    if (i >= E + Nn) return;
    int s, d;
    if (i < E) { s = ei[i]; d = ei[E + i]; }
    else       { s = i - E; d = i - E; }
    const int pos = atomicAdd(&g_cursor[d], 1);
    g_col[pos] = s;
}

// ---------------------------------------------------------------------------
// Attention coefficients from fp16 xp. Warp per node; head = lane>>3.
// ---------------------------------------------------------------------------
__global__ void attn_kernel(const __half* __restrict__ xp16,
                            const float* __restrict__ att_src,
                            const float* __restrict__ att_dst,
                            float* __restrict__ a_s,
                            float* __restrict__ a_d, int Nn)
{
    const int node = (blockIdx.x * blockDim.x + threadIdx.x) >> 5;
    const int lane = threadIdx.x & 31;
    if (node >= Nn) return;
    const int head = lane >> 3;

    const uint4 raw = *(const uint4*)(xp16 + (size_t)node * 256 + lane * 8);
    const float2 f0 = __half22float2(*(const __half2*)&raw.x);
    const float2 f1 = __half22float2(*(const __half2*)&raw.y);
    const float2 f2 = __half22float2(*(const __half2*)&raw.z);
    const float2 f3 = __half22float2(*(const __half2*)&raw.w);

    const float* cs = att_src + lane * 8;
    const float* cd = att_dst + lane * 8;
    const float4 s0 = *(const float4*)(cs);
    const float4 s1 = *(const float4*)(cs + 4);
    const float4 d0 = *(const float4*)(cd);
    const float4 d1 = *(const float4*)(cd + 4);

    float s = f0.x * s0.x + f0.y * s0.y + f1.x * s0.z + f1.y * s0.w
            + f2.x * s1.x + f2.y * s1.y + f3.x * s1.z + f3.y * s1.w;
    float d = f0.x * d0.x + f0.y * d0.y + f1.x * d0.z + f1.y * d0.w
            + f2.x * d1.x + f2.y * d1.y + f3.x * d1.z + f3.y * d1.w;
    #pragma unroll
    for (int o = 4; o; o >>= 1) {
        s += __shfl_xor_sync(0xffffffffu, s, o);
        d += __shfl_xor_sync(0xffffffffu, d, o);
    }
    if ((lane & 7) == 0) {
        a_s[node * 4 + head] = s;
        a_d[node * 4 + head] = d;
    }
}

// ---------------------------------------------------------------------------
// GAT aggregation (fp16 messages), all 4 heads per warp. Two-pass softmax.
// Main loop manually unrolled x2 for MLP.
// ---------------------------------------------------------------------------
__global__ void gat_agg4_kernel(const __half* __restrict__ xp16,
                                const float* __restrict__ a_s,
                                const float* __restrict__ a_d,
                                float* __restrict__ out, int Nn)
{
    const int node = (blockIdx.x * blockDim.x + threadIdx.x) >> 5;
    const int lane = threadIdx.x & 31;
    if (node >= Nn) return;
    const int head = lane >> 3;
    const int lsub = lane & 7;

    const int beg = __ldg(&g_rowptr[node]);
    const int end = __ldg(&g_rowptr[node + 1]);
    const float adh = __ldg(&a_d[node * 4 + head]);

    // pass 1: per-head max
    float mloc = -INFINITY;
    for (int j = beg + lsub; j < end; j += 8) {
        const int s = __ldg(&g_col[j]);
        float e = __ldg(&a_s[s * 4 + head]) + adh;
        e = (e > 0.f) ? e : 0.2f * e;
        mloc = fmaxf(mloc, e);
    }
    #pragma unroll
    for (int o = 1; o < 8; o <<= 1)
        mloc = fmaxf(mloc, __shfl_xor_sync(0xffffffffu, mloc, o));
    const float m = mloc;

    // pass 2: accumulate, unrolled x2 for memory-level parallelism
    float dsum = 0.f;
    float acc[8];
    #pragma unroll
    for (int i = 0; i < 8; ++i) acc[i] = 0.f;

    const size_t fo = (size_t)lane * 8;

    int j = beg;
    for (; j + 2 <= end; j += 2) {
        const int s0 = __ldg(&g_col[j]);
        const int s1 = __ldg(&g_col[j + 1]);
        const float as0 = __ldg(&a_s[s0 * 4 + head]);
        const float as1 = __ldg(&a_s[s1 * 4 + head]);
        const uint4 r0 = *(const uint4*)(xp16 + (size_t)s0 * 256 + fo);
        const uint4 r1 = *(const uint4*)(xp16 + (size_t)s1 * 256 + fo);

        float e0 = as0 + adh; e0 = (e0 > 0.f) ? e0 : 0.2f * e0;
        float e1 = as1 + adh; e1 = (e1 > 0.f) ? e1 : 0.2f * e1;
        const float p0 = __expf(e0 - m);
        const float p1 = __expf(e1 - m);
        dsum += p0 + p1;

        {
            const float2 f0 = __half22float2(*(const __half2*)&r0.x);
            const float2 f1 = __half22float2(*(const __half2*)&r0.y);
            const float2 f2 = __half22float2(*(const __half2*)&r0.z);
            const float2 f3 = __half22float2(*(const __half2*)&r0.w);
            acc[0] = fmaf(p0, f0.x, acc[0]); acc[1] = fmaf(p0, f0.y, acc[1]);
            acc[2] = fmaf(p0, f1.x, acc[2]); acc[3] = fmaf(p0, f1.y, acc[3]);
            acc[4] = fmaf(p0, f2.x, acc[4]); acc[5] = fmaf(p0, f2.y, acc[5]);
            acc[6] = fmaf(p0, f3.x, acc[6]); acc[7] = fmaf(p0, f3.y, acc[7]);
        }
        {
            const float2 f0 = __half22float2(*(const __half2*)&r1.x);
            const float2 f1 = __half22float2(*(const __half2*)&r1.y);
            const float2 f2 = __half22float2(*(const __half2*)&r1.z);
            const float2 f3 = __half22float2(*(const __half2*)&r1.w);
            acc[0] = fmaf(p1, f0.x, acc[0]); acc[1] = fmaf(p1, f0.y, acc[1]);
            acc[2] = fmaf(p1, f1.x, acc[2]); acc[3] = fmaf(p1, f1.y, acc[3]);
            acc[4] = fmaf(p1, f2.x, acc[4]); acc[5] = fmaf(p1, f2.y, acc[5]);
            acc[6] = fmaf(p1, f3.x, acc[6]); acc[7] = fmaf(p1, f3.y, acc[7]);
        }
    }
    if (j < end) {
        const int s = __ldg(&g_col[j]);
        float e = __ldg(&a_s[s * 4 + head]) + adh;
        e = (e > 0.f) ? e : 0.2f * e;
        const float p = __expf(e - m);
        const uint4 raw = *(const uint4*)(xp16 + (size_t)s * 256 + fo);
        const float2 f0 = __half22float2(*(const __half2*)&raw.x);
        const float2 f1 = __half22float2(*(const __half2*)&raw.y);
        const float2 f2 = __half22float2(*(const __half2*)&raw.z);
        const float2 f3 = __half22float2(*(const __half2*)&raw.w);
        dsum += p;
        acc[0] = fmaf(p, f0.x, acc[0]); acc[1] = fmaf(p, f0.y, acc[1]);
        acc[2] = fmaf(p, f1.x, acc[2]); acc[3] = fmaf(p, f1.y, acc[3]);
        acc[4] = fmaf(p, f2.x, acc[4]); acc[5] = fmaf(p, f2.y, acc[5]);
        acc[6] = fmaf(p, f3.x, acc[6]); acc[7] = fmaf(p, f3.y, acc[7]);
    }

    const float inv = 1.f / (dsum + 1e-16f);
    float* orow = out + (size_t)node * 256 + fo;
    *(float4*)(orow)     = make_float4(acc[0] * inv, acc[1] * inv, acc[2] * inv, acc[3] * inv);
    *(float4*)(orow + 4) = make_float4(acc[4] * inv, acc[5] * inv, acc[6] * inv, acc[7] * inv);
}

// ---------------------------------------------------------------------------
// h16 = fp16(relu(LN(in + bias; g, b))) over 256 features. Warp per node.
// ---------------------------------------------------------------------------
__global__ void ln_relu_256_kernel(const float* __restrict__ in,
                                   const float* __restrict__ bias,
                                   const float* __restrict__ lg,
                                   const float* __restrict__ lb,
                                   __half* __restrict__ out16, int Nn)
{
    const int w = (blockIdx.x * blockDim.x + threadIdx.x) >> 5;
    const int lane = threadIdx.x & 31;
    if (w >= Nn) return;
    const float* row = in + (size_t)w * 256;

    float v[8];
    float s = 0.f;
    #pragma unroll
    for (int i = 0; i < 2; ++i) {
        const float4 x4 = *(const float4*)(row + i * 128 + lane * 4);
        const float4 b4 = *(const float4*)(bias + i * 128 + lane * 4);
        v[i * 4 + 0] = x4.x + b4.x; v[i * 4 + 1] = x4.y + b4.y;
        v[i * 4 + 2] = x4.z + b4.z; v[i * 4 + 3] = x4.w + b4.w;
        s += v[i * 4 + 0] + v[i * 4 + 1] + v[i * 4 + 2] + v[i * 4 + 3];
    }
    #pragma unroll
    for (int o = 16; o; o >>= 1) s += __shfl_xor_sync(0xffffffffu, s, o);
    const float mu = s * (1.f / 256.f);

    float q = 0.f;
    #pragma unroll
    for (int i = 0; i < 8; ++i) { const float d = v[i] - mu; q += d * d; }
    #pragma unroll
    for (int o = 16; o; o >>= 1) q += __shfl_xor_sync(0xffffffffu, q, o);
    const float rinv = rsqrtf(q * (1.f / 256.f) + 1e-5f);

    __half* orow = out16 + (size_t)w * 256;
    #pragma unroll
    for (int i = 0; i < 2; ++i) {
        const float4 g4 = *(const float4*)(lg + i * 128 + lane * 4);
        const float4 b4 = *(const float4*)(lb + i * 128 + lane * 4);
        float4 y;
        y.x = fmaxf(fmaf((v[i * 4 + 0] - mu) * rinv, g4.x, b4.x), 0.f);
        y.y = fmaxf(fmaf((v[i * 4 + 1] - mu) * rinv, g4.y, b4.y), 0.f);
        y.z = fmaxf(fmaf((v[i * 4 + 2] - mu) * rinv, g4.z, b4.z), 0.f);
        y.w = fmaxf(fmaf((v[i * 4 + 3] - mu) * rinv, g4.w, b4.w), 0.f);
        __half2 hh[2];
        hh[0] = __floats2half2_rn(y.x, y.y);
        hh[1] = __floats2half2_rn(y.z, y.w);
        *(uint2*)(orow + i * 128 + lane * 4) = *(uint2*)hh;
    }
}

// ---------------------------------------------------------------------------
// out[n][c] = relu(LN(mean_h(hraw) + bias1)) over 64 feats. Warp per node.
// ---------------------------------------------------------------------------
__global__ void combine_ln1_kernel(const float* __restrict__ hraw,
                                   const float* __restrict__ bias,
                                   const float* __restrict__ lg,
                                   const float* __restrict__ lb,
                                   float* __restrict__ out, int Nn)
{
    const int w = (blockIdx.x * blockDim.x + threadIdx.x) >> 5;
    const int lane = threadIdx.x & 31;
    if (w >= Nn) return;
    const float* base = hraw + (size_t)w * 256;
    const int c = lane * 2;

    const float2 h0 = *(const float2*)(base + c);
    const float2 h1 = *(const float2*)(base + 64 + c);
    const float2 h2 = *(const float2*)(base + 128 + c);
    const float2 h3 = *(const float2*)(base + 192 + c);
    float tx = (h0.x + h1.x + h2.x + h3.x) * 0.25f + bias[c];
    float ty = (h0.y + h1.y + h2.y + h3.y) * 0.25f + bias[c + 1];

    float s = tx + ty;
    #pragma unroll
    for (int o = 16; o; o >>= 1) s += __shfl_xor_sync(0xffffffffu, s, o);
    const float mu = s * (1.f / 64.f);

    float q = (tx - mu) * (tx - mu) + (ty - mu) * (ty - mu);
    #pragma unroll
    for (int o = 16; o; o >>= 1) q += __shfl_xor_sync(0xffffffffu, q, o);
    const float rinv = rsqrtf(q * (1.f / 64.f) + 1e-5f);

    float2 y;
    y.x = fmaxf(fmaf((tx - mu) * rinv, lg[c], lb[c]), 0.f);
    y.y = fmaxf(fmaf((ty - mu) * rinv, lg[c + 1], lb[c + 1]), 0.f);
    *(float2*)(out + (size_t)w * 64 + c) = y;
}

// ---------------------------------------------------------------------------
extern "C" void kernel_launch(void* const* d_in, const int* in_sizes, int n_in,
                              void* d_out, int out_size)
{
    const float* nf       = (const float*)d_in[0];
    const int*   types    = (const int*)  d_in[1];
    const int*   ei       = (const int*)  d_in[2];
    const float* type_emb = (const float*)d_in[3];
    const float* proj_W   = (const float*)d_in[4];
    const float* proj_b   = (const float*)d_in[5];
    const float* W0       = (const float*)d_in[6];
    const float* att_s0   = (const float*)d_in[7];
    const float* att_d0   = (const float*)d_in[8];
    const float* bias0    = (const float*)d_in[9];
    const float* ln0_g    = (const float*)d_in[10];
    const float* ln0_b    = (const float*)d_in[11];
    const float* W1       = (const float*)d_in[12];
    const float* att_s1   = (const float*)d_in[13];
    const float* att_d1   = (const float*)d_in[14];
    const float* bias1    = (const float*)d_in[15];
    const float* ln1_g    = (const float*)d_in[16];
    const float* ln1_b    = (const float*)d_in[17];
    float* out = (float*)d_out;

    const int Nn = in_sizes[1];
    const int E  = in_sizes[2] / 2;

    __half *nf16_p, *x16_p, *h16_p, *xp16_p, *pwh_p, *w0h_p, *w1h_p;
    float *hraw_p, *as_p, *ad_p;
    int *counts_p;
    cudaGetSymbolAddress((void**)&nf16_p, g_nf16);
    cudaGetSymbolAddress((void**)&x16_p,  g_x16);
    cudaGetSymbolAddress((void**)&h16_p,  g_h16);
    cudaGetSymbolAddress((void**)&xp16_p, g_xp16);
    cudaGetSymbolAddress((void**)&pwh_p,  g_pwh);
    cudaGetSymbolAddress((void**)&w0h_p,  g_w0h);
    cudaGetSymbolAddress((void**)&w1h_p,  g_w1h);
    cudaGetSymbolAddress((void**)&hraw_p, g_hraw);
    cudaGetSymbolAddress((void**)&as_p,   g_as);
    cudaGetSymbolAddress((void**)&ad_p,   g_ad);
    cudaGetSymbolAddress((void**)&counts_p, g_counts);

    const int nodeWarpBlocks = (Nn + 7) / 8;
    const int scanBlocks = (Nn + SCAN_BLK - 1) / SCAN_BLK;

    // --- conversions (fp32 -> fp16) ---
    f2h_kernel<<<(64 * 64 / 2 + 255) / 256, 256>>>(proj_W, pwh_p, 64 * 64 / 2);
    f2h_kernel<<<(64 * 256 / 2 + 255) / 256, 256>>>(W0, w0h_p, 64 * 256 / 2);
    f2h_kernel<<<(256 * 256 / 2 + 255) / 256, 256>>>(W1, w1h_p, 256 * 256 / 2);
    f2h_kernel<<<(Nn * 32 + 255) / 256, 256>>>(nf, nf16_p, Nn * 32);

    // --- CSR build (overlaps with projection on same stream) ---
    cudaMemsetAsync(counts_p, 0, (size_t)Nn * sizeof(int));
    hist_kernel<<<(E + 255) / 256, 256>>>(ei + E, E);

    // --- input projection on tensor cores, fused bias + type-emb ---
    {
        dim3 grid(1, (Nn + HBM_ - 1) / HBM_);
        hgemm_kernel<true><<<grid, 128>>>(nf16_p, pwh_p, x16_p, Nn, 64, 64,
                                          proj_b, type_emb, types);
    }

    scan_p1_kernel<<<scanBlocks, SCAN_BLK>>>(Nn);
    scan_p2_kernel<<<1, SCAN_BLK>>>(scanBlocks, Nn);
    scan_p3_kernel<<<(Nn + 255) / 256, 256>>>(Nn);
    scatter_kernel<<<(E + Nn + 255) / 256, 256>>>(ei, E, Nn);

    // --- layer 0 ---
    {
        dim3 grid(256 / HBN_, (Nn + HBM_ - 1) / HBM_);
        hgemm_kernel<false><<<grid, 128>>>(x16_p, w0h_p, xp16_p, Nn, 64, 256,
                                           nullptr, nullptr, nullptr);
    }
    attn_kernel<<<nodeWarpBlocks, 256>>>(xp16_p, att_s0, att_d0, as_p, ad_p, Nn);
    gat_agg4_kernel<<<nodeWarpBlocks, 256>>>(xp16_p, as_p, ad_p, hraw_p, Nn);
    ln_relu_256_kernel<<<nodeWarpBlocks, 256>>>(hraw_p, bias0, ln0_g, ln0_b, h16_p, Nn);

    // --- layer 1 ---
    {
        dim3 grid(256 / HBN_, (Nn + HBM_ - 1) / HBM_);
        hgemm_kernel<false><<<grid, 128>>>(h16_p, w1h_p, xp16_p, Nn, 256, 256,
                                           nullptr, nullptr, nullptr);
    }
    attn_kernel<<<nodeWarpBlocks, 256>>>(xp16_p, att_s1, att_d1, as_p, ad_p, Nn);
    gat_agg4_kernel<<<nodeWarpBlocks, 256>>>(xp16_p, as_p, ad_p, hraw_p, Nn);
    combine_ln1_kernel<<<nodeWarpBlocks, 256>>>(hraw_p, bias1, ln1_g, ln1_b, out, Nn);
}

// round 7
// speedup vs baseline: 2.7750x; 1.0239x over previous
#include <cuda_runtime.h>
#include <cuda_fp16.h>
#include <cuda_bf16.h>
#include <mma.h>
#include <math.h>

using namespace nvcuda;

// ---------------------------------------------------------------------------
// TGN_GAT: 2-layer GAT (N=50000, E=800000, F=64, HID=64, HEADS=4)
// All GEMMs on tensor cores (fp16 in / fp32 accum), fp16 message gather.
// ---------------------------------------------------------------------------

#define MAXN 50000
#define MAXE 800000
#define MAXTOT (MAXE + MAXN)
#define SCAN_BLK 256
#define MAX_SCAN_BLOCKS ((MAXN + SCAN_BLK - 1) / SCAN_BLK)

__device__ __half g_nf16[(size_t)MAXN * 64];
__device__ __half g_x16[(size_t)MAXN * 64];
__device__ __half g_h16[(size_t)MAXN * 256];
__device__ __half g_xp16[(size_t)MAXN * 256];
__device__ __half g_pwh[64 * 64];
__device__ __half g_w0h[64 * 256];
__device__ __half g_w1h[256 * 256];
__device__ float  g_hraw[(size_t)MAXN * 256];
__device__ float  g_as[(size_t)MAXN * 4];
__device__ float  g_ad[(size_t)MAXN * 4];
__device__ int    g_rowptr[MAXN + 1];
__device__ int    g_cursor[MAXN];
__device__ int    g_counts[MAXN];
__device__ int    g_scanex[MAXN];
__device__ int    g_bsum[MAX_SCAN_BLOCKS];
__device__ int    g_boff[MAX_SCAN_BLOCKS];
__device__ int    g_col[MAXTOT];

// ---------------------------------------------------------------------------
// float -> half conversion
// ---------------------------------------------------------------------------
__global__ void f2h_kernel(const float* __restrict__ in, __half* __restrict__ out, int n2)
{
    const int i = blockIdx.x * blockDim.x + threadIdx.x;
    if (i < n2) {
        const float2 v = *(const float2*)(in + i * 2);
        *(__half2*)(out + i * 2) = __floats2half2_rn(v.x, v.y);
    }
}

// ---------------------------------------------------------------------------
// fp16 tensor-core GEMM: C16[M,N] = A16[M,K] @ B16[K,N]  (fp32 accum).
// Block tile 64x64, 4 warps (2x2), each warp 32x32 via 2x2 wmma 16x16x16.
// Optional fused epilogue: + pb[c] + emb[types[r]*64 + c]  (proj path).
// ---------------------------------------------------------------------------
#define HBM_ 64
#define HBN_ 64
#define HBK_ 32

template <bool EPI>
__global__ __launch_bounds__(128) void hgemm_kernel(
    const __half* __restrict__ A, const __half* __restrict__ B,
    __half* __restrict__ C, int M, int K, int N,
    const float* __restrict__ pb, const float* __restrict__ emb,
    const int* __restrict__ types)
{
    __shared__ __half As[HBM_][HBK_ + 8];
    __shared__ __half Bs[HBK_][HBN_ + 8];
    __shared__ float  Cs[HBM_][HBN_ + 8];

    const int tid = threadIdx.x;
    const int wid = tid >> 5;
    const int wr = wid >> 1;
    const int wc = wid & 1;
    const int rowBase = blockIdx.y * HBM_;
    const int colBase = blockIdx.x * HBN_;

    wmma::fragment<wmma::accumulator, 16, 16, 16, float> acc[2][2];
    #pragma unroll
    for (int i = 0; i < 2; ++i)
        #pragma unroll
        for (int j = 0; j < 2; ++j)
            wmma::fill_fragment(acc[i][j], 0.f);

    for (int k0 = 0; k0 < K; k0 += HBK_) {
        #pragma unroll
        for (int i = tid; i < HBM_ * HBK_ / 8; i += 128) {
            const int r = i >> 2;
            const int c8 = (i & 3) * 8;
            const int gr = rowBase + r;
            uint4 v = make_uint4(0u, 0u, 0u, 0u);
            if (gr < M) v = *(const uint4*)(A + (size_t)gr * K + k0 + c8);
            *(uint4*)&As[r][c8] = v;
        }
        #pragma unroll
        for (int i = tid; i < HBK_ * HBN_ / 8; i += 128) {
            const int r = i >> 3;
            const int c8 = (i & 7) * 8;
            *(uint4*)&Bs[r][c8] = *(const uint4*)(B + (size_t)(k0 + r) * N + colBase + c8);
        }
        __syncthreads();

        #pragma unroll
        for (int kk = 0; kk < HBK_; kk += 16) {
            wmma::fragment<wmma::matrix_a, 16, 16, 16, __half, wmma::row_major> af[2];
            wmma::fragment<wmma::matrix_b, 16, 16, 16, __half, wmma::row_major> bf[2];
            #pragma unroll
            for (int i = 0; i < 2; ++i)
                wmma::load_matrix_sync(af[i], &As[wr * 32 + i * 16][kk], HBK_ + 8);
            #pragma unroll
            for (int j = 0; j < 2; ++j)
                wmma::load_matrix_sync(bf[j], &Bs[kk][wc * 32 + j * 16], HBN_ + 8);
            #pragma unroll
            for (int i = 0; i < 2; ++i)
                #pragma unroll
                for (int j = 0; j < 2; ++j)
                    wmma::mma_sync(acc[i][j], af[i], bf[j], acc[i][j]);
        }
        __syncthreads();
    }

    #pragma unroll
    for (int i = 0; i < 2; ++i)
        #pragma unroll
        for (int j = 0; j < 2; ++j)
            wmma::store_matrix_sync(&Cs[wr * 32 + i * 16][wc * 32 + j * 16],
                                    acc[i][j], HBN_ + 8, wmma::mem_row_major);
    __syncthreads();

    #pragma unroll
    for (int i = tid; i < HBM_ * HBN_ / 2; i += 128) {
        const int r = i >> 5;
        const int c2 = (i & 31) * 2;
        const int gr = rowBase + r;
        if (gr < M) {
            float vx = Cs[r][c2];
            float vy = Cs[r][c2 + 1];
            if (EPI) {
                const int col = colBase + c2;
                const float2 p2 = *(const float2*)(pb + col);
                const float2 e2 = *(const float2*)(emb + types[gr] * 64 + col);
                vx += p2.x + e2.x;
                vy += p2.y + e2.y;
            }
            *(__half2*)(C + (size_t)gr * N + colBase + c2) = __floats2half2_rn(vx, vy);
        }
    }
}

// ---------------------------------------------------------------------------
// CSR build
// ---------------------------------------------------------------------------
__global__ void hist_kernel(const int* __restrict__ dst, int E)
{
    const int i = blockIdx.x * blockDim.x + threadIdx.x;
    if (i < E) atomicAdd(&g_counts[dst[i]], 1);
}

// Phase 1: per-block exclusive scan of (counts[i] + 1)  [+1 = self loop]
__global__ __launch_bounds__(SCAN_BLK) void scan_p1_kernel(int Nn)
{
    __shared__ int sh[SCAN_BLK];
    const int t = threadIdx.x;
    const int i = blockIdx.x * SCAN_BLK + t;
    int v = (i < Nn) ? (g_counts[i] + 1) : 0;
    sh[t] = v;
    __syncthreads();

    int inc = v;
    #pragma unroll
    for (int off = 1; off < SCAN_BLK; off <<= 1) {
        int add = (t >= off) ? sh[t - off] : 0;
        __syncthreads();
        inc += add;
        sh[t] = inc;
        __syncthreads();
    }
    if (i < Nn) g_scanex[i] = inc - v;
    if (t == SCAN_BLK - 1) g_bsum[blockIdx.x] = inc;
}

__global__ __launch_bounds__(SCAN_BLK) void scan_p2_kernel(int nblocks, int Nn)
{
    __shared__ int sh[SCAN_BLK];
    const int t = threadIdx.x;
    int v = (t < nblocks) ? g_bsum[t] : 0;
    sh[t] = v;
    __syncthreads();

    int inc = v;
    #pragma unroll
    for (int off = 1; off < SCAN_BLK; off <<= 1) {
        int add = (t >= off) ? sh[t - off] : 0;
        __syncthreads();
        inc += add;
        sh[t] = inc;
        __syncthreads();
    }
    if (t < nblocks) g_boff[t] = inc - v;
    if (t == SCAN_BLK - 1) g_rowptr[Nn] = sh[SCAN_BLK - 1];
}

__global__ void scan_p3_kernel(int Nn)
{
    const int i = blockIdx.x * blockDim.x + threadIdx.x;
    if (i >= Nn) return;
    const int val = g_scanex[i] + g_boff[i >> 8];
    g_rowptr[i] = val;
    g_cursor[i] = val;
}

__global__ void scatter_kernel(const int* __restrict__ ei, int E, int Nn)
{
    const int i = blockIdx.x * blockDim.x + threadIdx.x;
    if (i >= E + Nn) return;
    int s, d;
    if (i < E) { s = ei[i]; d = ei[E + i]; }
    else       { s = i - E; d = i - E; }
    const int pos = atomicAdd(&g_cursor[d], 1);
    g_col[pos] = s;
}

// ---------------------------------------------------------------------------
// Attention coefficients from fp16 xp. Warp per node; head = lane>>3.
// ---------------------------------------------------------------------------
__global__ void attn_kernel(const __half* __restrict__ xp16,
                            const float* __restrict__ att_src,
                            const float* __restrict__ att_dst,
                            float* __restrict__ a_s,
                            float* __restrict__ a_d, int Nn)
{
    const int node = (blockIdx.x * blockDim.x + threadIdx.x) >> 5;
    const int lane = threadIdx.x & 31;
    if (node >= Nn) return;
    const int head = lane >> 3;

    const uint4 raw = *(const uint4*)(xp16 + (size_t)node * 256 + lane * 8);
    const float2 f0 = __half22float2(*(const __half2*)&raw.x);
    const float2 f1 = __half22float2(*(const __half2*)&raw.y);
    const float2 f2 = __half22float2(*(const __half2*)&raw.z);
    const float2 f3 = __half22float2(*(const __half2*)&raw.w);

    const float* cs = att_src + lane * 8;
    const float* cd = att_dst + lane * 8;
    const float4 s0 = *(const float4*)(cs);
    const float4 s1 = *(const float4*)(cs + 4);
    const float4 d0 = *(const float4*)(cd);
    const float4 d1 = *(const float4*)(cd + 4);

    float s = f0.x * s0.x + f0.y * s0.y + f1.x * s0.z + f1.y * s0.w
            + f2.x * s1.x + f2.y * s1.y + f3.x * s1.z + f3.y * s1.w;
    float d = f0.x * d0.x + f0.y * d0.y + f1.x * d0.z + f1.y * d0.w
            + f2.x * d1.x + f2.y * d1.y + f3.x * d1.z + f3.y * d1.w;
    #pragma unroll
    for (int o = 4; o; o >>= 1) {
        s += __shfl_xor_sync(0xffffffffu, s, o);
        d += __shfl_xor_sync(0xffffffffu, d, o);
    }
    if ((lane & 7) == 0) {
        a_s[node * 4 + head] = s;
        a_d[node * 4 + head] = d;
    }
}

// ---------------------------------------------------------------------------
// GAT aggregation (fp16 messages), all 4 heads per warp. Two-pass softmax.
// Main loop manually unrolled x2 for MLP.
// ---------------------------------------------------------------------------
__global__ void gat_agg4_kernel(const __half* __restrict__ xp16,
                                const float* __restrict__ a_s,
                                const float* __restrict__ a_d,
                                float* __restrict__ out, int Nn)
{
    const int node = (blockIdx.x * blockDim.x + threadIdx.x) >> 5;
    const int lane = threadIdx.x & 31;
    if (node >= Nn) return;
    const int head = lane >> 3;
    const int lsub = lane & 7;

    const int beg = __ldg(&g_rowptr[node]);
    const int end = __ldg(&g_rowptr[node + 1]);
    const float adh = __ldg(&a_d[node * 4 + head]);

    // pass 1: per-head max
    float mloc = -INFINITY;
    for (int j = beg + lsub; j < end; j += 8) {
        const int s = __ldg(&g_col[j]);
        float e = __ldg(&a_s[s * 4 + head]) + adh;
        e = (e > 0.f) ? e : 0.2f * e;
        mloc = fmaxf(mloc, e);
    }
    #pragma unroll
    for (int o = 1; o < 8; o <<= 1)
        mloc = fmaxf(mloc, __shfl_xor_sync(0xffffffffu, mloc, o));
    const float m = mloc;

    // pass 2: accumulate, unrolled x2 for memory-level parallelism
    float dsum = 0.f;
    float acc[8];
    #pragma unroll
    for (int i = 0; i < 8; ++i) acc[i] = 0.f;

    const size_t fo = (size_t)lane * 8;

    int j = beg;
    for (; j + 2 <= end; j += 2) {
        const int s0 = __ldg(&g_col[j]);
        const int s1 = __ldg(&g_col[j + 1]);
        const float as0 = __ldg(&a_s[s0 * 4 + head]);
        const float as1 = __ldg(&a_s[s1 * 4 + head]);
        const uint4 r0 = *(const uint4*)(xp16 + (size_t)s0 * 256 + fo);
        const uint4 r1 = *(const uint4*)(xp16 + (size_t)s1 * 256 + fo);

        float e0 = as0 + adh; e0 = (e0 > 0.f) ? e0 : 0.2f * e0;
        float e1 = as1 + adh; e1 = (e1 > 0.f) ? e1 : 0.2f * e1;
        const float p0 = __expf(e0 - m);
        const float p1 = __expf(e1 - m);
        dsum += p0 + p1;

        {
            const float2 f0 = __half22float2(*(const __half2*)&r0.x);
            const float2 f1 = __half22float2(*(const __half2*)&r0.y);
            const float2 f2 = __half22float2(*(const __half2*)&r0.z);
            const float2 f3 = __half22float2(*(const __half2*)&r0.w);
            acc[0] = fmaf(p0, f0.x, acc[0]); acc[1] = fmaf(p0, f0.y, acc[1]);
            acc[2] = fmaf(p0, f1.x, acc[2]); acc[3] = fmaf(p0, f1.y, acc[3]);
            acc[4] = fmaf(p0, f2.x, acc[4]); acc[5] = fmaf(p0, f2.y, acc[5]);
            acc[6] = fmaf(p0, f3.x, acc[6]); acc[7] = fmaf(p0, f3.y, acc[7]);
        }
        {
            const float2 f0 = __half22float2(*(const __half2*)&r1.x);
            const float2 f1 = __half22float2(*(const __half2*)&r1.y);
            const float2 f2 = __half22float2(*(const __half2*)&r1.z);
            const float2 f3 = __half22float2(*(const __half2*)&r1.w);
            acc[0] = fmaf(p1, f0.x, acc[0]); acc[1] = fmaf(p1, f0.y, acc[1]);
            acc[2] = fmaf(p1, f1.x, acc[2]); acc[3] = fmaf(p1, f1.y, acc[3]);
            acc[4] = fmaf(p1, f2.x, acc[4]); acc[5] = fmaf(p1, f2.y, acc[5]);
            acc[6] = fmaf(p1, f3.x, acc[6]); acc[7] = fmaf(p1, f3.y, acc[7]);
        }
    }
    if (j < end) {
        const int s = __ldg(&g_col[j]);
        float e = __ldg(&a_s[s * 4 + head]) + adh;
        e = (e > 0.f) ? e : 0.2f * e;
        const float p = __expf(e - m);
        const uint4 raw = *(const uint4*)(xp16 + (size_t)s * 256 + fo);
        const float2 f0 = __half22float2(*(const __half2*)&raw.x);
        const float2 f1 = __half22float2(*(const __half2*)&raw.y);
        const float2 f2 = __half22float2(*(const __half2*)&raw.z);
        const float2 f3 = __half22float2(*(const __half2*)&raw.w);
        dsum += p;
        acc[0] = fmaf(p, f0.x, acc[0]); acc[1] = fmaf(p, f0.y, acc[1]);
        acc[2] = fmaf(p, f1.x, acc[2]); acc[3] = fmaf(p, f1.y, acc[3]);
        acc[4] = fmaf(p, f2.x, acc[4]); acc[5] = fmaf(p, f2.y, acc[5]);
        acc[6] = fmaf(p, f3.x, acc[6]); acc[7] = fmaf(p, f3.y, acc[7]);
    }

    const float inv = 1.f / (dsum + 1e-16f);
    float* orow = out + (size_t)node * 256 + fo;
    *(float4*)(orow)     = make_float4(acc[0] * inv, acc[1] * inv, acc[2] * inv, acc[3] * inv);
    *(float4*)(orow + 4) = make_float4(acc[4] * inv, acc[5] * inv, acc[6] * inv, acc[7] * inv);
}

// ---------------------------------------------------------------------------
// h16 = fp16(relu(LN(in + bias; g, b))) over 256 features. Warp per node.
// ---------------------------------------------------------------------------
__global__ void ln_relu_256_kernel(const float* __restrict__ in,
                                   const float* __restrict__ bias,
                                   const float* __restrict__ lg,
                                   const float* __restrict__ lb,
                                   __half* __restrict__ out16, int Nn)
{
    const int w = (blockIdx.x * blockDim.x + threadIdx.x) >> 5;
    const int lane = threadIdx.x & 31;
    if (w >= Nn) return;
    const float* row = in + (size_t)w * 256;

    float v[8];
    float s = 0.f;
    #pragma unroll
    for (int i = 0; i < 2; ++i) {
        const float4 x4 = *(const float4*)(row + i * 128 + lane * 4);
        const float4 b4 = *(const float4*)(bias + i * 128 + lane * 4);
        v[i * 4 + 0] = x4.x + b4.x; v[i * 4 + 1] = x4.y + b4.y;
        v[i * 4 + 2] = x4.z + b4.z; v[i * 4 + 3] = x4.w + b4.w;
        s += v[i * 4 + 0] + v[i * 4 + 1] + v[i * 4 + 2] + v[i * 4 + 3];
    }
    #pragma unroll
    for (int o = 16; o; o >>= 1) s += __shfl_xor_sync(0xffffffffu, s, o);
    const float mu = s * (1.f / 256.f);

    float q = 0.f;
    #pragma unroll
    for (int i = 0; i < 8; ++i) { const float d = v[i] - mu; q += d * d; }
    #pragma unroll
    for (int o = 16; o; o >>= 1) q += __shfl_xor_sync(0xffffffffu, q, o);
    const float rinv = rsqrtf(q * (1.f / 256.f) + 1e-5f);

    __half* orow = out16 + (size_t)w * 256;
    #pragma unroll
    for (int i = 0; i < 2; ++i) {
        const float4 g4 = *(const float4*)(lg + i * 128 + lane * 4);
        const float4 b4 = *(const float4*)(lb + i * 128 + lane * 4);
        float4 y;
        y.x = fmaxf(fmaf((v[i * 4 + 0] - mu) * rinv, g4.x, b4.x), 0.f);
        y.y = fmaxf(fmaf((v[i * 4 + 1] - mu) * rinv, g4.y, b4.y), 0.f);
        y.z = fmaxf(fmaf((v[i * 4 + 2] - mu) * rinv, g4.z, b4.z), 0.f);
        y.w = fmaxf(fmaf((v[i * 4 + 3] - mu) * rinv, g4.w, b4.w), 0.f);
        __half2 hh[2];
        hh[0] = __floats2half2_rn(y.x, y.y);
        hh[1] = __floats2half2_rn(y.z, y.w);
        *(uint2*)(orow + i * 128 + lane * 4) = *(uint2*)hh;
    }
}

// ---------------------------------------------------------------------------
// out[n][c] = relu(LN(mean_h(hraw) + bias1)) over 64 feats. Warp per node.
// ---------------------------------------------------------------------------
__global__ void combine_ln1_kernel(const float* __restrict__ hraw,
                                   const float* __restrict__ bias,
                                   const float* __restrict__ lg,
                                   const float* __restrict__ lb,
                                   float* __restrict__ out, int Nn)
{
    const int w = (blockIdx.x * blockDim.x + threadIdx.x) >> 5;
    const int lane = threadIdx.x & 31;
    if (w >= Nn) return;
    const float* base = hraw + (size_t)w * 256;
    const int c = lane * 2;

    const float2 h0 = *(const float2*)(base + c);
    const float2 h1 = *(const float2*)(base + 64 + c);
    const float2 h2 = *(const float2*)(base + 128 + c);
    const float2 h3 = *(const float2*)(base + 192 + c);
    float tx = (h0.x + h1.x + h2.x + h3.x) * 0.25f + bias[c];
    float ty = (h0.y + h1.y + h2.y + h3.y) * 0.25f + bias[c + 1];

    float s = tx + ty;
    #pragma unroll
    for (int o = 16; o; o >>= 1) s += __shfl_xor_sync(0xffffffffu, s, o);
    const float mu = s * (1.f / 64.f);

    float q = (tx - mu) * (tx - mu) + (ty - mu) * (ty - mu);
    #pragma unroll
    for (int o = 16; o; o >>= 1) q += __shfl_xor_sync(0xffffffffu, q, o);
    const float rinv = rsqrtf(q * (1.f / 64.f) + 1e-5f);

    float2 y;
    y.x = fmaxf(fmaf((tx - mu) * rinv, lg[c], lb[c]), 0.f);
    y.y = fmaxf(fmaf((ty - mu) * rinv, lg[c + 1], lb[c + 1]), 0.f);
    *(float2*)(out + (size_t)w * 64 + c) = y;
}

// ---------------------------------------------------------------------------
extern "C" void kernel_launch(void* const* d_in, const int* in_sizes, int n_in,
                              void* d_out, int out_size)
{
    const float* nf       = (const float*)d_in[0];
    const int*   types    = (const int*)  d_in[1];
    const int*   ei       = (const int*)  d_in[2];
    const float* type_emb = (const float*)d_in[3];
    const float* proj_W   = (const float*)d_in[4];
    const float* proj_b   = (const float*)d_in[5];
    const float* W0       = (const float*)d_in[6];
    const float* att_s0   = (const float*)d_in[7];
    const float* att_d0   = (const float*)d_in[8];
    const float* bias0    = (const float*)d_in[9];
    const float* ln0_g    = (const float*)d_in[10];
    const float* ln0_b    = (const float*)d_in[11];
    const float* W1       = (const float*)d_in[12];
    const float* att_s1   = (const float*)d_in[13];
    const float* att_d1   = (const float*)d_in[14];
    const float* bias1    = (const float*)d_in[15];
    const float* ln1_g    = (const float*)d_in[16];
    const float* ln1_b    = (const float*)d_in[17];
    float* out = (float*)d_out;

    const int Nn = in_sizes[1];
    const int E  = in_sizes[2] / 2;

    __half *nf16_p, *x16_p, *h16_p, *xp16_p, *pwh_p, *w0h_p, *w1h_p;
    float *hraw_p, *as_p, *ad_p;
    int *counts_p;
    cudaGetSymbolAddress((void**)&nf16_p, g_nf16);
    cudaGetSymbolAddress((void**)&x16_p,  g_x16);
    cudaGetSymbolAddress((void**)&h16_p,  g_h16);
    cudaGetSymbolAddress((void**)&xp16_p, g_xp16);
    cudaGetSymbolAddress((void**)&pwh_p,  g_pwh);
    cudaGetSymbolAddress((void**)&w0h_p,  g_w0h);
    cudaGetSymbolAddress((void**)&w1h_p,  g_w1h);
    cudaGetSymbolAddress((void**)&hraw_p, g_hraw);
    cudaGetSymbolAddress((void**)&as_p,   g_as);
    cudaGetSymbolAddress((void**)&ad_p,   g_ad);
    cudaGetSymbolAddress((void**)&counts_p, g_counts);

    const int nodeWarpBlocks = (Nn + 7) / 8;
    const int scanBlocks = (Nn + SCAN_BLK - 1) / SCAN_BLK;

    // --- conversions (fp32 -> fp16) ---
    f2h_kernel<<<(64 * 64 / 2 + 255) / 256, 256>>>(proj_W, pwh_p, 64 * 64 / 2);
    f2h_kernel<<<(64 * 256 / 2 + 255) / 256, 256>>>(W0, w0h_p, 64 * 256 / 2);
    f2h_kernel<<<(256 * 256 / 2 + 255) / 256, 256>>>(W1, w1h_p, 256 * 256 / 2);
    f2h_kernel<<<(Nn * 32 + 255) / 256, 256>>>(nf, nf16_p, Nn * 32);

    // --- CSR build (overlaps with projection on same stream) ---
    cudaMemsetAsync(counts_p, 0, (size_t)Nn * sizeof(int));
    hist_kernel<<<(E + 255) / 256, 256>>>(ei + E, E);

    // --- input projection on tensor cores, fused bias + type-emb ---
    {
        dim3 grid(1, (Nn + HBM_ - 1) / HBM_);
        hgemm_kernel<true><<<grid, 128>>>(nf16_p, pwh_p, x16_p, Nn, 64, 64,
                                          proj_b, type_emb, types);
    }

    scan_p1_kernel<<<scanBlocks, SCAN_BLK>>>(Nn);
    scan_p2_kernel<<<1, SCAN_BLK>>>(scanBlocks, Nn);
    scan_p3_kernel<<<(Nn + 255) / 256, 256>>>(Nn);
    scatter_kernel<<<(E + Nn + 255) / 256, 256>>>(ei, E, Nn);

    // --- layer 0 ---
    {
        dim3 grid(256 / HBN_, (Nn + HBM_ - 1) / HBM_);
        hgemm_kernel<false><<<grid, 128>>>(x16_p, w0h_p, xp16_p, Nn, 64, 256,
                                           nullptr, nullptr, nullptr);
    }
    attn_kernel<<<nodeWarpBlocks, 256>>>(xp16_p, att_s0, att_d0, as_p, ad_p, Nn);
    gat_agg4_kernel<<<nodeWarpBlocks, 256>>>(xp16_p, as_p, ad_p, hraw_p, Nn);
    ln_relu_256_kernel<<<nodeWarpBlocks, 256>>>(hraw_p, bias0, ln0_g, ln0_b, h16_p, Nn);

    // --- layer 1 ---
    {
        dim3 grid(256 / HBN_, (Nn + HBM_ - 1) / HBM_);
        hgemm_kernel<false><<<grid, 128>>>(h16_p, w1h_p, xp16_p, Nn, 256, 256,
                                           nullptr, nullptr, nullptr);
    }
    attn_kernel<<<nodeWarpBlocks, 256>>>(xp16_p, att_s1, att_d1, as_p, ad_p, Nn);
    gat_agg4_kernel<<<nodeWarpBlocks, 256>>>(xp16_p, as_p, ad_p, hraw_p, Nn);
    combine_ln1_kernel<<<nodeWarpBlocks, 256>>>(hraw_p, bias1, ln1_g, ln1_b, out, Nn);
}

// round 8
// speedup vs baseline: 2.7773x; 1.0008x over previous
#include <cuda_runtime.h>
#include <cuda_fp16.h>
#include <cuda_bf16.h>
#include <mma.h>
#include <math.h>

using namespace nvcuda;

// ---------------------------------------------------------------------------
// TGN_GAT: 2-layer GAT (N=50000, E=800000, F=64, HID=64, HEADS=4)
// All GEMMs on tensor cores (fp16 in / fp32 accum), fp16 message gather.
// ---------------------------------------------------------------------------

#define MAXN 50000
#define MAXE 800000
#define MAXTOT (MAXE + MAXN)
#define SCAN_BLK 256
#define MAX_SCAN_BLOCKS ((MAXN + SCAN_BLK - 1) / SCAN_BLK)

__device__ __half g_nf16[(size_t)MAXN * 64];
__device__ __half g_x16[(size_t)MAXN * 64];
__device__ __half g_h16[(size_t)MAXN * 256];
__device__ __half g_xp16[(size_t)MAXN * 256];
__device__ __half g_pwh[64 * 64];
__device__ __half g_w0h[64 * 256];
__device__ __half g_w1h[256 * 256];
__device__ float  g_hraw[(size_t)MAXN * 256];
__device__ float  g_as[(size_t)MAXN * 4];
__device__ float  g_ad[(size_t)MAXN * 4];
__device__ int    g_rowptr[MAXN + 1];
__device__ int    g_cursor[MAXN];
__device__ int    g_counts[MAXN];
__device__ int    g_scanex[MAXN];
__device__ int    g_bsum[MAX_SCAN_BLOCKS];
__device__ int    g_boff[MAX_SCAN_BLOCKS];
__device__ int    g_col[MAXTOT];

// ---------------------------------------------------------------------------
// float -> half conversion
// ---------------------------------------------------------------------------
__global__ void f2h_kernel(const float* __restrict__ in, __half* __restrict__ out, int n2)
{
    const int i = blockIdx.x * blockDim.x + threadIdx.x;
    if (i < n2) {
        const float2 v = *(const float2*)(in + i * 2);
        *(__half2*)(out + i * 2) = __floats2half2_rn(v.x, v.y);
    }
}

// ---------------------------------------------------------------------------
// fp16 tensor-core GEMM: C16[M,N] = A16[M,K] @ B16[K,N]  (fp32 accum).
// Block tile 64x64, 4 warps (2x2), each warp 32x32 via 2x2 wmma 16x16x16.
// Optional fused epilogue: + pb[c] + emb[types[r]*64 + c]  (proj path).
// ---------------------------------------------------------------------------
#define HBM_ 64
#define HBN_ 64
#define HBK_ 32

template <bool EPI>
__global__ __launch_bounds__(128) void hgemm_kernel(
    const __half* __restrict__ A, const __half* __restrict__ B,
    __half* __restrict__ C, int M, int K, int N,
    const float* __restrict__ pb, const float* __restrict__ emb,
    const int* __restrict__ types)
{
    __shared__ __half As[HBM_][HBK_ + 8];
    __shared__ __half Bs[HBK_][HBN_ + 8];
    __shared__ float  Cs[HBM_][HBN_ + 8];

    const int tid = threadIdx.x;
    const int wid = tid >> 5;
    const int wr = wid >> 1;
    const int wc = wid & 1;
    const int rowBase = blockIdx.y * HBM_;
    const int colBase = blockIdx.x * HBN_;

    wmma::fragment<wmma::accumulator, 16, 16, 16, float> acc[2][2];
    #pragma unroll
    for (int i = 0; i < 2; ++i)
        #pragma unroll
        for (int j = 0; j < 2; ++j)
            wmma::fill_fragment(acc[i][j], 0.f);

    for (int k0 = 0; k0 < K; k0 += HBK_) {
        #pragma unroll
        for (int i = tid; i < HBM_ * HBK_ / 8; i += 128) {
            const int r = i >> 2;
            const int c8 = (i & 3) * 8;
            const int gr = rowBase + r;
            uint4 v = make_uint4(0u, 0u, 0u, 0u);
            if (gr < M) v = *(const uint4*)(A + (size_t)gr * K + k0 + c8);
            *(uint4*)&As[r][c8] = v;
        }
        #pragma unroll
        for (int i = tid; i < HBK_ * HBN_ / 8; i += 128) {
            const int r = i >> 3;
            const int c8 = (i & 7) * 8;
            *(uint4*)&Bs[r][c8] = *(const uint4*)(B + (size_t)(k0 + r) * N + colBase + c8);
        }
        __syncthreads();

        #pragma unroll
        for (int kk = 0; kk < HBK_; kk += 16) {
            wmma::fragment<wmma::matrix_a, 16, 16, 16, __half, wmma::row_major> af[2];
            wmma::fragment<wmma::matrix_b, 16, 16, 16, __half, wmma::row_major> bf[2];
            #pragma unroll
            for (int i = 0; i < 2; ++i)
                wmma::load_matrix_sync(af[i], &As[wr * 32 + i * 16][kk], HBK_ + 8);
            #pragma unroll
            for (int j = 0; j < 2; ++j)
                wmma::load_matrix_sync(bf[j], &Bs[kk][wc * 32 + j * 16], HBN_ + 8);
            #pragma unroll
            for (int i = 0; i < 2; ++i)
                #pragma unroll
                for (int j = 0; j < 2; ++j)
                    wmma::mma_sync(acc[i][j], af[i], bf[j], acc[i][j]);
        }
        __syncthreads();
    }

    #pragma unroll
    for (int i = 0; i < 2; ++i)
        #pragma unroll
        for (int j = 0; j < 2; ++j)
            wmma::store_matrix_sync(&Cs[wr * 32 + i * 16][wc * 32 + j * 16],
                                    acc[i][j], HBN_ + 8, wmma::mem_row_major);
    __syncthreads();

    #pragma unroll
    for (int i = tid; i < HBM_ * HBN_ / 2; i += 128) {
        const int r = i >> 5;
        const int c2 = (i & 31) * 2;
        const int gr = rowBase + r;
        if (gr < M) {
            float vx = Cs[r][c2];
            float vy = Cs[r][c2 + 1];
            if (EPI) {
                const int col = colBase + c2;
                const float2 p2 = *(const float2*)(pb + col);
                const float2 e2 = *(const float2*)(emb + types[gr] * 64 + col);
                vx += p2.x + e2.x;
                vy += p2.y + e2.y;
            }
            *(__half2*)(C + (size_t)gr * N + colBase + c2) = __floats2half2_rn(vx, vy);
        }
    }
}

// ---------------------------------------------------------------------------
// CSR build
// ---------------------------------------------------------------------------
__global__ void hist_kernel(const int* __restrict__ dst, int E)
{
    const int i = blockIdx.x * blockDim.x + threadIdx.x;
    if (i < E) atomicAdd(&g_counts[dst[i]], 1);
}

// Phase 1: per-block exclusive scan of (counts[i] + 1)  [+1 = self loop]
__global__ __launch_bounds__(SCAN_BLK) void scan_p1_kernel(int Nn)
{
    __shared__ int sh[SCAN_BLK];
    const int t = threadIdx.x;
    const int i = blockIdx.x * SCAN_BLK + t;
    int v = (i < Nn) ? (g_counts[i] + 1) : 0;
    sh[t] = v;
    __syncthreads();

    int inc = v;
    #pragma unroll
    for (int off = 1; off < SCAN_BLK; off <<= 1) {
        int add = (t >= off) ? sh[t - off] : 0;
        __syncthreads();
        inc += add;
        sh[t] = inc;
        __syncthreads();
    }
    if (i < Nn) g_scanex[i] = inc - v;
    if (t == SCAN_BLK - 1) g_bsum[blockIdx.x] = inc;
}

__global__ __launch_bounds__(SCAN_BLK) void scan_p2_kernel(int nblocks, int Nn)
{
    __shared__ int sh[SCAN_BLK];
    const int t = threadIdx.x;
    int v = (t < nblocks) ? g_bsum[t] : 0;
    sh[t] = v;
    __syncthreads();

    int inc = v;
    #pragma unroll
    for (int off = 1; off < SCAN_BLK; off <<= 1) {
        int add = (t >= off) ? sh[t - off] : 0;
        __syncthreads();
        inc += add;
        sh[t] = inc;
        __syncthreads();
    }
    if (t < nblocks) g_boff[t] = inc - v;
    if (t == SCAN_BLK - 1) g_rowptr[Nn] = sh[SCAN_BLK - 1];
}

__global__ void scan_p3_kernel(int Nn)
{
    const int i = blockIdx.x * blockDim.x + threadIdx.x;
    if (i >= Nn) return;
    const int val = g_scanex[i] + g_boff[i >> 8];
    g_rowptr[i] = val;
    g_cursor[i] = val;
}

__global__ void scatter_kernel(const int* __restrict__ ei, int E, int Nn)
{
    const int i = blockIdx.x * blockDim.x + threadIdx.x;
    if (i >= E + Nn) return;
    int s, d;
    if (i < E) { s = ei[i]; d = ei[E + i]; }
    else       { s = i - E; d = i - E; }
    const int pos = atomicAdd(&g_cursor[d], 1);
    g_col[pos] = s;
}

// ---------------------------------------------------------------------------
// Attention coefficients from fp16 xp. Warp per node; head = lane>>3.
// ---------------------------------------------------------------------------
__global__ void attn_kernel(const __half* __restrict__ xp16,
                            const float* __restrict__ att_src,
                            const float* __restrict__ att_dst,
                            float* __restrict__ a_s,
                            float* __restrict__ a_d, int Nn)
{
    const int node = (blockIdx.x * blockDim.x + threadIdx.x) >> 5;
    const int lane = threadIdx.x & 31;
    if (node >= Nn) return;
    const int head = lane >> 3;

    const uint4 raw = *(const uint4*)(xp16 + (size_t)node * 256 + lane * 8);
    const float2 f0 = __half22float2(*(const __half2*)&raw.x);
    const float2 f1 = __half22float2(*(const __half2*)&raw.y);
    const float2 f2 = __half22float2(*(const __half2*)&raw.z);
    const float2 f3 = __half22float2(*(const __half2*)&raw.w);

    const float* cs = att_src + lane * 8;
    const float* cd = att_dst + lane * 8;
    const float4 s0 = *(const float4*)(cs);
    const float4 s1 = *(const float4*)(cs + 4);
    const float4 d0 = *(const float4*)(cd);
    const float4 d1 = *(const float4*)(cd + 4);

    float s = f0.x * s0.x + f0.y * s0.y + f1.x * s0.z + f1.y * s0.w
            + f2.x * s1.x + f2.y * s1.y + f3.x * s1.z + f3.y * s1.w;
    float d = f0.x * d0.x + f0.y * d0.y + f1.x * d0.z + f1.y * d0.w
            + f2.x * d1.x + f2.y * d1.y + f3.x * d1.z + f3.y * d1.w;
    #pragma unroll
    for (int o = 4; o; o >>= 1) {
        s += __shfl_xor_sync(0xffffffffu, s, o);
        d += __shfl_xor_sync(0xffffffffu, d, o);
    }
    if ((lane & 7) == 0) {
        a_s[node * 4 + head] = s;
        a_d[node * 4 + head] = d;
    }
}

// ---------------------------------------------------------------------------
// GAT aggregation (fp16 messages), all 4 heads per warp. Two-pass softmax.
// Main loop manually unrolled x2 for MLP.
// ---------------------------------------------------------------------------
__global__ void gat_agg4_kernel(const __half* __restrict__ xp16,
                                const float* __restrict__ a_s,
                                const float* __restrict__ a_d,
                                float* __restrict__ out, int Nn)
{
    const int node = (blockIdx.x * blockDim.x + threadIdx.x) >> 5;
    const int lane = threadIdx.x & 31;
    if (node >= Nn) return;
    const int head = lane >> 3;
    const int lsub = lane & 7;

    const int beg = __ldg(&g_rowptr[node]);
    const int end = __ldg(&g_rowptr[node + 1]);
    const float adh = __ldg(&a_d[node * 4 + head]);

    // pass 1: per-head max
    float mloc = -INFINITY;
    for (int j = beg + lsub; j < end; j += 8) {
        const int s = __ldg(&g_col[j]);
        float e = __ldg(&a_s[s * 4 + head]) + adh;
        e = (e > 0.f) ? e : 0.2f * e;
        mloc = fmaxf(mloc, e);
    }
    #pragma unroll
    for (int o = 1; o < 8; o <<= 1)
        mloc = fmaxf(mloc, __shfl_xor_sync(0xffffffffu, mloc, o));
    const float m = mloc;

    // pass 2: accumulate, unrolled x2 for memory-level parallelism
    float dsum = 0.f;
    float acc[8];
    #pragma unroll
    for (int i = 0; i < 8; ++i) acc[i] = 0.f;

    const size_t fo = (size_t)lane * 8;

    int j = beg;
    for (; j + 2 <= end; j += 2) {
        const int s0 = __ldg(&g_col[j]);
        const int s1 = __ldg(&g_col[j + 1]);
        const float as0 = __ldg(&a_s[s0 * 4 + head]);
        const float as1 = __ldg(&a_s[s1 * 4 + head]);
        const uint4 r0 = *(const uint4*)(xp16 + (size_t)s0 * 256 + fo);
        const uint4 r1 = *(const uint4*)(xp16 + (size_t)s1 * 256 + fo);

        float e0 = as0 + adh; e0 = (e0 > 0.f) ? e0 : 0.2f * e0;
        float e1 = as1 + adh; e1 = (e1 > 0.f) ? e1 : 0.2f * e1;
        const float p0 = __expf(e0 - m);
        const float p1 = __expf(e1 - m);
        dsum += p0 + p1;

        {
            const float2 f0 = __half22float2(*(const __half2*)&r0.x);
            const float2 f1 = __half22float2(*(const __half2*)&r0.y);
            const float2 f2 = __half22float2(*(const __half2*)&r0.z);
            const float2 f3 = __half22float2(*(const __half2*)&r0.w);
            acc[0] = fmaf(p0, f0.x, acc[0]); acc[1] = fmaf(p0, f0.y, acc[1]);
            acc[2] = fmaf(p0, f1.x, acc[2]); acc[3] = fmaf(p0, f1.y, acc[3]);
            acc[4] = fmaf(p0, f2.x, acc[4]); acc[5] = fmaf(p0, f2.y, acc[5]);
            acc[6] = fmaf(p0, f3.x, acc[6]); acc[7] = fmaf(p0, f3.y, acc[7]);
        }
        {
            const float2 f0 = __half22float2(*(const __half2*)&r1.x);
            const float2 f1 = __half22float2(*(const __half2*)&r1.y);
            const float2 f2 = __half22float2(*(const __half2*)&r1.z);
            const float2 f3 = __half22float2(*(const __half2*)&r1.w);
            acc[0] = fmaf(p1, f0.x, acc[0]); acc[1] = fmaf(p1, f0.y, acc[1]);
            acc[2] = fmaf(p1, f1.x, acc[2]); acc[3] = fmaf(p1, f1.y, acc[3]);
            acc[4] = fmaf(p1, f2.x, acc[4]); acc[5] = fmaf(p1, f2.y, acc[5]);
            acc[6] = fmaf(p1, f3.x, acc[6]); acc[7] = fmaf(p1, f3.y, acc[7]);
        }
    }
    if (j < end) {
        const int s = __ldg(&g_col[j]);
        float e = __ldg(&a_s[s * 4 + head]) + adh;
        e = (e > 0.f) ? e : 0.2f * e;
        const float p = __expf(e - m);
        const uint4 raw = *(const uint4*)(xp16 + (size_t)s * 256 + fo);
        const float2 f0 = __half22float2(*(const __half2*)&raw.x);
        const float2 f1 = __half22float2(*(const __half2*)&raw.y);
        const float2 f2 = __half22float2(*(const __half2*)&raw.z);
        const float2 f3 = __half22float2(*(const __half2*)&raw.w);
        dsum += p;
        acc[0] = fmaf(p, f0.x, acc[0]); acc[1] = fmaf(p, f0.y, acc[1]);
        acc[2] = fmaf(p, f1.x, acc[2]); acc[3] = fmaf(p, f1.y, acc[3]);
        acc[4] = fmaf(p, f2.x, acc[4]); acc[5] = fmaf(p, f2.y, acc[5]);
        acc[6] = fmaf(p, f3.x, acc[6]); acc[7] = fmaf(p, f3.y, acc[7]);
    }

    const float inv = 1.f / (dsum + 1e-16f);
    float* orow = out + (size_t)node * 256 + fo;
    *(float4*)(orow)     = make_float4(acc[0] * inv, acc[1] * inv, acc[2] * inv, acc[3] * inv);
    *(float4*)(orow + 4) = make_float4(acc[4] * inv, acc[5] * inv, acc[6] * inv, acc[7] * inv);
}

// ---------------------------------------------------------------------------
// h16 = fp16(relu(LN(in + bias; g, b))) over 256 features. Warp per node.
// ---------------------------------------------------------------------------
__global__ void ln_relu_256_kernel(const float* __restrict__ in,
                                   const float* __restrict__ bias,
                                   const float* __restrict__ lg,
                                   const float* __restrict__ lb,
                                   __half* __restrict__ out16, int Nn)
{
    const int w = (blockIdx.x * blockDim.x + threadIdx.x) >> 5;
    const int lane = threadIdx.x & 31;
    if (w >= Nn) return;
    const float* row = in + (size_t)w * 256;

    float v[8];
    float s = 0.f;
    #pragma unroll
    for (int i = 0; i < 2; ++i) {
        const float4 x4 = *(const float4*)(row + i * 128 + lane * 4);
        const float4 b4 = *(const float4*)(bias + i * 128 + lane * 4);
        v[i * 4 + 0] = x4.x + b4.x; v[i * 4 + 1] = x4.y + b4.y;
        v[i * 4 + 2] = x4.z + b4.z; v[i * 4 + 3] = x4.w + b4.w;
        s += v[i * 4 + 0] + v[i * 4 + 1] + v[i * 4 + 2] + v[i * 4 + 3];
    }
    #pragma unroll
    for (int o = 16; o; o >>= 1) s += __shfl_xor_sync(0xffffffffu, s, o);
    const float mu = s * (1.f / 256.f);

    float q = 0.f;
    #pragma unroll
    for (int i = 0; i < 8; ++i) { const float d = v[i] - mu; q += d * d; }
    #pragma unroll
    for (int o = 16; o; o >>= 1) q += __shfl_xor_sync(0xffffffffu, q, o);
    const float rinv = rsqrtf(q * (1.f / 256.f) + 1e-5f);

    __half* orow = out16 + (size_t)w * 256;
    #pragma unroll
    for (int i = 0; i < 2; ++i) {
        const float4 g4 = *(const float4*)(lg + i * 128 + lane * 4);
        const float4 b4 = *(const float4*)(lb + i * 128 + lane * 4);
        float4 y;
        y.x = fmaxf(fmaf((v[i * 4 + 0] - mu) * rinv, g4.x, b4.x), 0.f);
        y.y = fmaxf(fmaf((v[i * 4 + 1] - mu) * rinv, g4.y, b4.y), 0.f);
        y.z = fmaxf(fmaf((v[i * 4 + 2] - mu) * rinv, g4.z, b4.z), 0.f);
        y.w = fmaxf(fmaf((v[i * 4 + 3] - mu) * rinv, g4.w, b4.w), 0.f);
        __half2 hh[2];
        hh[0] = __floats2half2_rn(y.x, y.y);
        hh[1] = __floats2half2_rn(y.z, y.w);
        *(uint2*)(orow + i * 128 + lane * 4) = *(uint2*)hh;
    }
}

// ---------------------------------------------------------------------------
// out[n][c] = relu(LN(mean_h(hraw) + bias1)) over 64 feats. Warp per node.
// ---------------------------------------------------------------------------
__global__ void combine_ln1_kernel(const float* __restrict__ hraw,
                                   const float* __restrict__ bias,
                                   const float* __restrict__ lg,
                                   const float* __restrict__ lb,
                                   float* __restrict__ out, int Nn)
{
    const int w = (blockIdx.x * blockDim.x + threadIdx.x) >> 5;
    const int lane = threadIdx.x & 31;
    if (w >= Nn) return;
    const float* base = hraw + (size_t)w * 256;
    const int c = lane * 2;

    const float2 h0 = *(const float2*)(base + c);
    const float2 h1 = *(const float2*)(base + 64 + c);
    const float2 h2 = *(const float2*)(base + 128 + c);
    const float2 h3 = *(const float2*)(base + 192 + c);
    float tx = (h0.x + h1.x + h2.x + h3.x) * 0.25f + bias[c];
    float ty = (h0.y + h1.y + h2.y + h3.y) * 0.25f + bias[c + 1];

    float s = tx + ty;
    #pragma unroll
    for (int o = 16; o; o >>= 1) s += __shfl_xor_sync(0xffffffffu, s, o);
    const float mu = s * (1.f / 64.f);

    float q = (tx - mu) * (tx - mu) + (ty - mu) * (ty - mu);
    #pragma unroll
    for (int o = 16; o; o >>= 1) q += __shfl_xor_sync(0xffffffffu, q, o);
    const float rinv = rsqrtf(q * (1.f / 64.f) + 1e-5f);

    float2 y;
    y.x = fmaxf(fmaf((tx - mu) * rinv, lg[c], lb[c]), 0.f);
    y.y = fmaxf(fmaf((ty - mu) * rinv, lg[c + 1], lb[c + 1]), 0.f);
    *(float2*)(out + (size_t)w * 64 + c) = y;
}

// ---------------------------------------------------------------------------
extern "C" void kernel_launch(void* const* d_in, const int* in_sizes, int n_in,
                              void* d_out, int out_size)
{
    const float* nf       = (const float*)d_in[0];
    const int*   types    = (const int*)  d_in[1];
    const int*   ei       = (const int*)  d_in[2];
    const float* type_emb = (const float*)d_in[3];
    const float* proj_W   = (const float*)d_in[4];
    const float* proj_b   = (const float*)d_in[5];
    const float* W0       = (const float*)d_in[6];
    const float* att_s0   = (const float*)d_in[7];
    const float* att_d0   = (const float*)d_in[8];
    const float* bias0    = (const float*)d_in[9];
    const float* ln0_g    = (const float*)d_in[10];
    const float* ln0_b    = (const float*)d_in[11];
    const float* W1       = (const float*)d_in[12];
    const float* att_s1   = (const float*)d_in[13];
    const float* att_d1   = (const float*)d_in[14];
    const float* bias1    = (const float*)d_in[15];
    const float* ln1_g    = (const float*)d_in[16];
    const float* ln1_b    = (const float*)d_in[17];
    float* out = (float*)d_out;

    const int Nn = in_sizes[1];
    const int E  = in_sizes[2] / 2;

    __half *nf16_p, *x16_p, *h16_p, *xp16_p, *pwh_p, *w0h_p, *w1h_p;
    float *hraw_p, *as_p, *ad_p;
    int *counts_p;
    cudaGetSymbolAddress((void**)&nf16_p, g_nf16);
    cudaGetSymbolAddress((void**)&x16_p,  g_x16);
    cudaGetSymbolAddress((void**)&h16_p,  g_h16);
    cudaGetSymbolAddress((void**)&xp16_p, g_xp16);
    cudaGetSymbolAddress((void**)&pwh_p,  g_pwh);
    cudaGetSymbolAddress((void**)&w0h_p,  g_w0h);
    cudaGetSymbolAddress((void**)&w1h_p,  g_w1h);
    cudaGetSymbolAddress((void**)&hraw_p, g_hraw);
    cudaGetSymbolAddress((void**)&as_p,   g_as);
    cudaGetSymbolAddress((void**)&ad_p,   g_ad);
    cudaGetSymbolAddress((void**)&counts_p, g_counts);

    const int nodeWarpBlocks = (Nn + 7) / 8;
    const int scanBlocks = (Nn + SCAN_BLK - 1) / SCAN_BLK;

    // --- conversions (fp32 -> fp16) ---
    f2h_kernel<<<(64 * 64 / 2 + 255) / 256, 256>>>(proj_W, pwh_p, 64 * 64 / 2);
    f2h_kernel<<<(64 * 256 / 2 + 255) / 256, 256>>>(W0, w0h_p, 64 * 256 / 2);
    f2h_kernel<<<(256 * 256 / 2 + 255) / 256, 256>>>(W1, w1h_p, 256 * 256 / 2);
    f2h_kernel<<<(Nn * 32 + 255) / 256, 256>>>(nf, nf16_p, Nn * 32);

    // --- CSR build (overlaps with projection on same stream) ---
    cudaMemsetAsync(counts_p, 0, (size_t)Nn * sizeof(int));
    hist_kernel<<<(E + 255) / 256, 256>>>(ei + E, E);

    // --- input projection on tensor cores, fused bias + type-emb ---
    {
        dim3 grid(1, (Nn + HBM_ - 1) / HBM_);
        hgemm_kernel<true><<<grid, 128>>>(nf16_p, pwh_p, x16_p, Nn, 64, 64,
                                          proj_b, type_emb, types);
    }

    scan_p1_kernel<<<scanBlocks, SCAN_BLK>>>(Nn);
    scan_p2_kernel<<<1, SCAN_BLK>>>(scanBlocks, Nn);
    scan_p3_kernel<<<(Nn + 255) / 256, 256>>>(Nn);
    scatter_kernel<<<(E + Nn + 255) / 256, 256>>>(ei, E, Nn);

    // --- layer 0 ---
    {
        dim3 grid(256 / HBN_, (Nn + HBM_ - 1) / HBM_);
        hgemm_kernel<false><<<grid, 128>>>(x16_p, w0h_p, xp16_p, Nn, 64, 256,
                                           nullptr, nullptr, nullptr);
    }
    attn_kernel<<<nodeWarpBlocks, 256>>>(xp16_p, att_s0, att_d0, as_p, ad_p, Nn);
    gat_agg4_kernel<<<nodeWarpBlocks, 256>>>(xp16_p, as_p, ad_p, hraw_p, Nn);
    ln_relu_256_kernel<<<nodeWarpBlocks, 256>>>(hraw_p, bias0, ln0_g, ln0_b, h16_p, Nn);

    // --- layer 1 ---
    {
        dim3 grid(256 / HBN_, (Nn + HBM_ - 1) / HBM_);
        hgemm_kernel<false><<<grid, 128>>>(h16_p, w1h_p, xp16_p, Nn, 256, 256,
                                           nullptr, nullptr, nullptr);
    }
    attn_kernel<<<nodeWarpBlocks, 256>>>(xp16_p, att_s1, att_d1, as_p, ad_p, Nn);
    gat_agg4_kernel<<<nodeWarpBlocks, 256>>>(xp16_p, as_p, ad_p, hraw_p, Nn);
    combine_ln1_kernel<<<nodeWarpBlocks, 256>>>(hraw_p, bias1, ln1_g, ln1_b, out, Nn);
}

// round 9
// speedup vs baseline: 3.0166x; 1.0862x over previous
#include <cuda_runtime.h>
#include <cuda_fp16.h>
#include <cuda_bf16.h>
#include <mma.h>
#include <math.h>

using namespace nvcuda;

// ---------------------------------------------------------------------------
// TGN_GAT: 2-layer GAT (N=50000, E=800000, F=64, HID=64, HEADS=4)
// Tensor-core GEMMs with fused attention-coefficient epilogue;
// aggregation fused with LayerNorm stages. fp16 storage, fp32 accumulation.
// ---------------------------------------------------------------------------

#define MAXN 50000
#define MAXE 800000
#define MAXTOT (MAXE + MAXN)
#define SCAN_BLK 256
#define MAX_SCAN_BLOCKS ((MAXN + SCAN_BLK - 1) / SCAN_BLK)

__device__ __half g_x16[(size_t)MAXN * 64];
__device__ __half g_h16[(size_t)MAXN * 256];
__device__ __half g_xp16[(size_t)MAXN * 256];
__device__ __half g_pwh[64 * 64];
__device__ __half g_w0h[64 * 256];
__device__ __half g_w1h[256 * 256];
__device__ float  g_as[(size_t)MAXN * 4];
__device__ float  g_ad[(size_t)MAXN * 4];
__device__ int    g_rowptr[MAXN + 1];
__device__ int    g_cursor[MAXN];
__device__ int    g_counts[MAXN];
__device__ int    g_scanex[MAXN];
__device__ int    g_bsum[MAX_SCAN_BLOCKS];
__device__ int    g_boff[MAX_SCAN_BLOCKS];
__device__ int    g_col[MAXTOT];

// ---------------------------------------------------------------------------
__global__ void f2h_kernel(const float* __restrict__ in, __half* __restrict__ out, int n2)
{
    const int i = blockIdx.x * blockDim.x + threadIdx.x;
    if (i < n2) {
        const float2 v = *(const float2*)(in + i * 2);
        *(__half2*)(out + i * 2) = __floats2half2_rn(v.x, v.y);
    }
}

// ---------------------------------------------------------------------------
// fp16 tensor-core GEMM, 64x64 tile, 4 warps, fp32 accum.
// A32:  A is fp32, converted while staging to smem (proj path).
// EPI:  += pb[c] + emb[types[r]*64+c]  (proj path, N==64).
// ATTN: N==256, gridDim.x==4; block-col == head. Epilogue computes
//       a_s[r][head] = <tile_row, att_src[head]>, a_d likewise.
// ---------------------------------------------------------------------------
#define HBM_ 64
#define HBN_ 64
#define HBK_ 32

template <bool A32, bool EPI, bool ATTN>
__global__ __launch_bounds__(128) void hgemm_kernel(
    const void* __restrict__ Av, const __half* __restrict__ B,
    __half* __restrict__ C, int M, int K, int N,
    const float* __restrict__ pb, const float* __restrict__ emb,
    const int* __restrict__ types,
    const float* __restrict__ att_src, const float* __restrict__ att_dst,
    float* __restrict__ a_s, float* __restrict__ a_d)
{
    __shared__ __half As[HBM_][HBK_ + 8];
    __shared__ __half Bs[HBK_][HBN_ + 8];
    __shared__ float  Cs[HBM_][HBN_ + 8];

    const int tid = threadIdx.x;
    const int wid = tid >> 5;
    const int wr = wid >> 1;
    const int wc = wid & 1;
    const int rowBase = blockIdx.y * HBM_;
    const int colBase = blockIdx.x * HBN_;

    wmma::fragment<wmma::accumulator, 16, 16, 16, float> acc[2][2];
    #pragma unroll
    for (int i = 0; i < 2; ++i)
        #pragma unroll
        for (int j = 0; j < 2; ++j)
            wmma::fill_fragment(acc[i][j], 0.f);

    for (int k0 = 0; k0 < K; k0 += HBK_) {
        #pragma unroll
        for (int i = tid; i < HBM_ * HBK_ / 8; i += 128) {
            const int r = i >> 2;
            const int c8 = (i & 3) * 8;
            const int gr = rowBase + r;
            if (A32) {
                const float* Af = (const float*)Av;
                float4 f0 = make_float4(0.f, 0.f, 0.f, 0.f), f1 = f0;
                if (gr < M) {
                    f0 = *(const float4*)(Af + (size_t)gr * K + k0 + c8);
                    f1 = *(const float4*)(Af + (size_t)gr * K + k0 + c8 + 4);
                }
                __half2 hh[4];
                hh[0] = __floats2half2_rn(f0.x, f0.y);
                hh[1] = __floats2half2_rn(f0.z, f0.w);
                hh[2] = __floats2half2_rn(f1.x, f1.y);
                hh[3] = __floats2half2_rn(f1.z, f1.w);
                *(uint4*)&As[r][c8] = *(uint4*)hh;
            } else {
                const __half* Ah = (const __half*)Av;
                uint4 v = make_uint4(0u, 0u, 0u, 0u);
                if (gr < M) v = *(const uint4*)(Ah + (size_t)gr * K + k0 + c8);
                *(uint4*)&As[r][c8] = v;
            }
        }
        #pragma unroll
        for (int i = tid; i < HBK_ * HBN_ / 8; i += 128) {
            const int r = i >> 3;
            const int c8 = (i & 7) * 8;
            *(uint4*)&Bs[r][c8] = *(const uint4*)(B + (size_t)(k0 + r) * N + colBase + c8);
        }
        __syncthreads();

        #pragma unroll
        for (int kk = 0; kk < HBK_; kk += 16) {
            wmma::fragment<wmma::matrix_a, 16, 16, 16, __half, wmma::row_major> af[2];
            wmma::fragment<wmma::matrix_b, 16, 16, 16, __half, wmma::row_major> bf[2];
            #pragma unroll
            for (int i = 0; i < 2; ++i)
                wmma::load_matrix_sync(af[i], &As[wr * 32 + i * 16][kk], HBK_ + 8);
            #pragma unroll
            for (int j = 0; j < 2; ++j)
                wmma::load_matrix_sync(bf[j], &Bs[kk][wc * 32 + j * 16], HBN_ + 8);
            #pragma unroll
            for (int i = 0; i < 2; ++i)
                #pragma unroll
                for (int j = 0; j < 2; ++j)
                    wmma::mma_sync(acc[i][j], af[i], bf[j], acc[i][j]);
        }
        __syncthreads();
    }

    #pragma unroll
    for (int i = 0; i < 2; ++i)
        #pragma unroll
        for (int j = 0; j < 2; ++j)
            wmma::store_matrix_sync(&Cs[wr * 32 + i * 16][wc * 32 + j * 16],
                                    acc[i][j], HBN_ + 8, wmma::mem_row_major);
    __syncthreads();

    // fp16 store (+ optional bias/emb)
    #pragma unroll
    for (int i = tid; i < HBM_ * HBN_ / 2; i += 128) {
        const int r = i >> 5;
        const int c2 = (i & 31) * 2;
        const int gr = rowBase + r;
        if (gr < M) {
            float vx = Cs[r][c2];
            float vy = Cs[r][c2 + 1];
            if (EPI) {
                const int col = colBase + c2;
                const float2 p2 = *(const float2*)(pb + col);
                const float2 e2 = *(const float2*)(emb + types[gr] * 64 + col);
                vx += p2.x + e2.x;
                vy += p2.y + e2.y;
            }
            *(__half2*)(C + (size_t)gr * N + colBase + c2) = __floats2half2_rn(vx, vy);
        }
    }

    // fused attention-coefficient epilogue: block col == head
    if (ATTN) {
        const int head = blockIdx.x;
        const int r = tid >> 1;            // 0..63
        const int c0 = (tid & 1) * 32;     // 0 or 32
        const float* asrc = att_src + head * 64 + c0;
        const float* adst = att_dst + head * 64 + c0;
        float ps = 0.f, pd = 0.f;
        #pragma unroll 8
        for (int c = 0; c < 32; ++c) {
            const float v = Cs[r][c0 + c];
            ps = fmaf(v, asrc[c], ps);
            pd = fmaf(v, adst[c], pd);
        }
        ps += __shfl_xor_sync(0xffffffffu, ps, 1);
        pd += __shfl_xor_sync(0xffffffffu, pd, 1);
        const int gr = rowBase + r;
        if ((tid & 1) == 0 && gr < M) {
            a_s[gr * 4 + head] = ps;
            a_d[gr * 4 + head] = pd;
        }
    }
}

// ---------------------------------------------------------------------------
// CSR build
// ---------------------------------------------------------------------------
__global__ void hist_kernel(const int* __restrict__ dst, int E)
{
    const int i = blockIdx.x * blockDim.x + threadIdx.x;
    if (i < E) atomicAdd(&g_counts[dst[i]], 1);
}

__global__ __launch_bounds__(SCAN_BLK) void scan_p1_kernel(int Nn)
{
    __shared__ int sh[SCAN_BLK];
    const int t = threadIdx.x;
    const int i = blockIdx.x * SCAN_BLK + t;
    int v = (i < Nn) ? (g_counts[i] + 1) : 0;   // +1 = self loop
    sh[t] = v;
    __syncthreads();

    int inc = v;
    #pragma unroll
    for (int off = 1; off < SCAN_BLK; off <<= 1) {
        int add = (t >= off) ? sh[t - off] : 0;
        __syncthreads();
        inc += add;
        sh[t] = inc;
        __syncthreads();
    }
    if (i < Nn) g_scanex[i] = inc - v;
    if (t == SCAN_BLK - 1) g_bsum[blockIdx.x] = inc;
}

__global__ __launch_bounds__(SCAN_BLK) void scan_p2_kernel(int nblocks, int Nn)
{
    __shared__ int sh[SCAN_BLK];
    const int t = threadIdx.x;
    int v = (t < nblocks) ? g_bsum[t] : 0;
    sh[t] = v;
    __syncthreads();

    int inc = v;
    #pragma unroll
    for (int off = 1; off < SCAN_BLK; off <<= 1) {
        int add = (t >= off) ? sh[t - off] : 0;
        __syncthreads();
        inc += add;
        sh[t] = inc;
        __syncthreads();
    }
    if (t < nblocks) g_boff[t] = inc - v;
    if (t == SCAN_BLK - 1) g_rowptr[Nn] = sh[SCAN_BLK - 1];
}

__global__ void scan_p3_kernel(int Nn)
{
    const int i = blockIdx.x * blockDim.x + threadIdx.x;
    if (i >= Nn) return;
    const int val = g_scanex[i] + g_boff[i >> 8];
    g_rowptr[i] = val;
    g_cursor[i] = val;
}

__global__ void scatter_kernel(const int* __restrict__ ei, int E, int Nn)
{
    const int i = blockIdx.x * blockDim.x + threadIdx.x;
    if (i >= E + Nn) return;
    int s, d;
    if (i < E) { s = ei[i]; d = ei[E + i]; }
    else       { s = i - E; d = i - E; }
    const int pos = atomicAdd(&g_cursor[d], 1);
    g_col[pos] = s;
}

// ---------------------------------------------------------------------------
// Shared gather body: per-warp two-pass softmax aggregation over incoming
// edges; leaves normalized features (8 per lane) in y[].
// ---------------------------------------------------------------------------
__device__ __forceinline__ void agg_body(
    const __half* __restrict__ xp16, const float* __restrict__ a_s,
    const float adh, const int beg, const int end,
    const int head, const int lsub, const size_t fo, float* y)
{
    // pass 1: per-head max
    float mloc = -INFINITY;
    for (int j = beg + lsub; j < end; j += 8) {
        const int s = __ldg(&g_col[j]);
        float e = __ldg(&a_s[s * 4 + head]) + adh;
        e = (e > 0.f) ? e : 0.2f * e;
        mloc = fmaxf(mloc, e);
    }
    #pragma unroll
    for (int o = 1; o < 8; o <<= 1)
        mloc = fmaxf(mloc, __shfl_xor_sync(0xffffffffu, mloc, o));
    const float m = mloc;

    // pass 2: accumulate, unrolled x2
    float dsum = 0.f;
    float acc[8];
    #pragma unroll
    for (int i = 0; i < 8; ++i) acc[i] = 0.f;

    int j = beg;
    for (; j + 2 <= end; j += 2) {
        const int s0 = __ldg(&g_col[j]);
        const int s1 = __ldg(&g_col[j + 1]);
        const float as0 = __ldg(&a_s[s0 * 4 + head]);
        const float as1 = __ldg(&a_s[s1 * 4 + head]);
        const uint4 r0 = *(const uint4*)(xp16 + (size_t)s0 * 256 + fo);
        const uint4 r1 = *(const uint4*)(xp16 + (size_t)s1 * 256 + fo);

        float e0 = as0 + adh; e0 = (e0 > 0.f) ? e0 : 0.2f * e0;
        float e1 = as1 + adh; e1 = (e1 > 0.f) ? e1 : 0.2f * e1;
        const float p0 = __expf(e0 - m);
        const float p1 = __expf(e1 - m);
        dsum += p0 + p1;
        {
            const float2 f0 = __half22float2(*(const __half2*)&r0.x);
            const float2 f1 = __half22float2(*(const __half2*)&r0.y);
            const float2 f2 = __half22float2(*(const __half2*)&r0.z);
            const float2 f3 = __half22float2(*(const __half2*)&r0.w);
            acc[0] = fmaf(p0, f0.x, acc[0]); acc[1] = fmaf(p0, f0.y, acc[1]);
            acc[2] = fmaf(p0, f1.x, acc[2]); acc[3] = fmaf(p0, f1.y, acc[3]);
            acc[4] = fmaf(p0, f2.x, acc[4]); acc[5] = fmaf(p0, f2.y, acc[5]);
            acc[6] = fmaf(p0, f3.x, acc[6]); acc[7] = fmaf(p0, f3.y, acc[7]);
        }
        {
            const float2 f0 = __half22float2(*(const __half2*)&r1.x);
            const float2 f1 = __half22float2(*(const __half2*)&r1.y);
            const float2 f2 = __half22float2(*(const __half2*)&r1.z);
            const float2 f3 = __half22float2(*(const __half2*)&r1.w);
            acc[0] = fmaf(p1, f0.x, acc[0]); acc[1] = fmaf(p1, f0.y, acc[1]);
            acc[2] = fmaf(p1, f1.x, acc[2]); acc[3] = fmaf(p1, f1.y, acc[3]);
            acc[4] = fmaf(p1, f2.x, acc[4]); acc[5] = fmaf(p1, f2.y, acc[5]);
            acc[6] = fmaf(p1, f3.x, acc[6]); acc[7] = fmaf(p1, f3.y, acc[7]);
        }
    }
    if (j < end) {
        const int s = __ldg(&g_col[j]);
        float e = __ldg(&a_s[s * 4 + head]) + adh;
        e = (e > 0.f) ? e : 0.2f * e;
        const float p = __expf(e - m);
        const uint4 raw = *(const uint4*)(xp16 + (size_t)s * 256 + fo);
        const float2 f0 = __half22float2(*(const __half2*)&raw.x);
        const float2 f1 = __half22float2(*(const __half2*)&raw.y);
        const float2 f2 = __half22float2(*(const __half2*)&raw.z);
        const float2 f3 = __half22float2(*(const __half2*)&raw.w);
        dsum += p;
        acc[0] = fmaf(p, f0.x, acc[0]); acc[1] = fmaf(p, f0.y, acc[1]);
        acc[2] = fmaf(p, f1.x, acc[2]); acc[3] = fmaf(p, f1.y, acc[3]);
        acc[4] = fmaf(p, f2.x, acc[4]); acc[5] = fmaf(p, f2.y, acc[5]);
        acc[6] = fmaf(p, f3.x, acc[6]); acc[7] = fmaf(p, f3.y, acc[7]);
    }

    const float inv = 1.f / (dsum + 1e-16f);
    #pragma unroll
    for (int i = 0; i < 8; ++i) y[i] = acc[i] * inv;
}

// ---------------------------------------------------------------------------
// Layer 0: aggregation + bias + LN(256) + relu -> h16 (fp16). Warp per node.
// ---------------------------------------------------------------------------
__global__ void gat_agg_ln0_kernel(const __half* __restrict__ xp16,
                                   const float* __restrict__ a_s,
                                   const float* __restrict__ a_d,
                                   const float* __restrict__ bias,
                                   const float* __restrict__ lg,
                                   const float* __restrict__ lb,
                                   __half* __restrict__ out16, int Nn)
{
    const int node = (blockIdx.x * blockDim.x + threadIdx.x) >> 5;
    const int lane = threadIdx.x & 31;
    if (node >= Nn) return;
    const int head = lane >> 3;
    const size_t fo = (size_t)lane * 8;

    const int beg = __ldg(&g_rowptr[node]);
    const int end = __ldg(&g_rowptr[node + 1]);
    const float adh = __ldg(&a_d[node * 4 + head]);

    float y[8];
    agg_body(xp16, a_s, adh, beg, end, head, lane & 7, fo, y);

    // + bias
    const float4 b0 = *(const float4*)(bias + fo);
    const float4 b1 = *(const float4*)(bias + fo + 4);
    y[0] += b0.x; y[1] += b0.y; y[2] += b0.z; y[3] += b0.w;
    y[4] += b1.x; y[5] += b1.y; y[6] += b1.z; y[7] += b1.w;

    // LN over 256 (each lane holds 8 distinct features)
    float s = 0.f;
    #pragma unroll
    for (int i = 0; i < 8; ++i) s += y[i];
    #pragma unroll
    for (int o = 16; o; o >>= 1) s += __shfl_xor_sync(0xffffffffu, s, o);
    const float mu = s * (1.f / 256.f);

    float q = 0.f;
    #pragma unroll
    for (int i = 0; i < 8; ++i) { const float d = y[i] - mu; q += d * d; }
    #pragma unroll
    for (int o = 16; o; o >>= 1) q += __shfl_xor_sync(0xffffffffu, q, o);
    const float rinv = rsqrtf(q * (1.f / 256.f) + 1e-5f);

    const float4 g0 = *(const float4*)(lg + fo);
    const float4 g1 = *(const float4*)(lg + fo + 4);
    const float4 lb0 = *(const float4*)(lb + fo);
    const float4 lb1 = *(const float4*)(lb + fo + 4);

    float z[8];
    z[0] = fmaxf(fmaf((y[0] - mu) * rinv, g0.x, lb0.x), 0.f);
    z[1] = fmaxf(fmaf((y[1] - mu) * rinv, g0.y, lb0.y), 0.f);
    z[2] = fmaxf(fmaf((y[2] - mu) * rinv, g0.z, lb0.z), 0.f);
    z[3] = fmaxf(fmaf((y[3] - mu) * rinv, g0.w, lb0.w), 0.f);
    z[4] = fmaxf(fmaf((y[4] - mu) * rinv, g1.x, lb1.x), 0.f);
    z[5] = fmaxf(fmaf((y[5] - mu) * rinv, g1.y, lb1.y), 0.f);
    z[6] = fmaxf(fmaf((y[6] - mu) * rinv, g1.z, lb1.z), 0.f);
    z[7] = fmaxf(fmaf((y[7] - mu) * rinv, g1.w, lb1.w), 0.f);

    __half2 hh[4];
    hh[0] = __floats2half2_rn(z[0], z[1]);
    hh[1] = __floats2half2_rn(z[2], z[3]);
    hh[2] = __floats2half2_rn(z[4], z[5]);
    hh[3] = __floats2half2_rn(z[6], z[7]);
    *(uint4*)(out16 + (size_t)node * 256 + fo) = *(uint4*)hh;
}

// ---------------------------------------------------------------------------
// Layer 1: aggregation + head-mean + bias + LN(64) + relu -> out (fp32).
// Lanes l, l^8, l^16, l^24 hold the same feature slice of heads 0..3.
// ---------------------------------------------------------------------------
__global__ void gat_agg_ln1_kernel(const __half* __restrict__ xp16,
                                   const float* __restrict__ a_s,
                                   const float* __restrict__ a_d,
                                   const float* __restrict__ bias,
                                   const float* __restrict__ lg,
                                   const float* __restrict__ lb,
                                   float* __restrict__ out, int Nn)
{
    const int node = (blockIdx.x * blockDim.x + threadIdx.x) >> 5;
    const int lane = threadIdx.x & 31;
    if (node >= Nn) return;
    const int head = lane >> 3;
    const int lsub = lane & 7;
    const size_t fo = (size_t)lane * 8;

    const int beg = __ldg(&g_rowptr[node]);
    const int end = __ldg(&g_rowptr[node + 1]);
    const float adh = __ldg(&a_d[node * 4 + head]);

    float y[8];
    agg_body(xp16, a_s, adh, beg, end, head, lsub, fo, y);

    // mean over heads: sum across lanes {l, l^8, l^16, l^24}, then *0.25 + bias
    const float4 bb0 = *(const float4*)(bias + lsub * 8);
    const float4 bb1 = *(const float4*)(bias + lsub * 8 + 4);
    float w[8];
    #pragma unroll
    for (int i = 0; i < 8; ++i) {
        float v = y[i];
        v += __shfl_xor_sync(0xffffffffu, v, 8);
        v += __shfl_xor_sync(0xffffffffu, v, 16);
        w[i] = v * 0.25f;
    }
    w[0] += bb0.x; w[1] += bb0.y; w[2] += bb0.z; w[3] += bb0.w;
    w[4] += bb1.x; w[5] += bb1.y; w[6] += bb1.z; w[7] += bb1.w;

    // LN over 64 (features replicated 4x across the warp -> scale by 1/4)
    float s = 0.f;
    #pragma unroll
    for (int i = 0; i < 8; ++i) s += w[i];
    #pragma unroll
    for (int o = 16; o; o >>= 1) s += __shfl_xor_sync(0xffffffffu, s, o);
    const float mu = s * (1.f / 256.f);        // (4 * 64)

    float q = 0.f;
    #pragma unroll
    for (int i = 0; i < 8; ++i) { const float d = w[i] - mu; q += d * d; }
    #pragma unroll
    for (int o = 16; o; o >>= 1) q += __shfl_xor_sync(0xffffffffu, q, o);
    const float rinv = rsqrtf(q * (1.f / 256.f) + 1e-5f);

    if (lane < 8) {
        const float4 g0 = *(const float4*)(lg + lsub * 8);
        const float4 g1 = *(const float4*)(lg + lsub * 8 + 4);
        const float4 lb0 = *(const float4*)(lb + lsub * 8);
        const float4 lb1 = *(const float4*)(lb + lsub * 8 + 4);
        float4 o0, o1;
        o0.x = fmaxf(fmaf((w[0] - mu) * rinv, g0.x, lb0.x), 0.f);
        o0.y = fmaxf(fmaf((w[1] - mu) * rinv, g0.y, lb0.y), 0.f);
        o0.z = fmaxf(fmaf((w[2] - mu) * rinv, g0.z, lb0.z), 0.f);
        o0.w = fmaxf(fmaf((w[3] - mu) * rinv, g0.w, lb0.w), 0.f);
        o1.x = fmaxf(fmaf((w[4] - mu) * rinv, g1.x, lb1.x), 0.f);
        o1.y = fmaxf(fmaf((w[5] - mu) * rinv, g1.y, lb1.y), 0.f);
        o1.z = fmaxf(fmaf((w[6] - mu) * rinv, g1.z, lb1.z), 0.f);
        o1.w = fmaxf(fmaf((w[7] - mu) * rinv, g1.w, lb1.w), 0.f);
        float* orow = out + (size_t)node * 64 + lsub * 8;
        *(float4*)(orow)     = o0;
        *(float4*)(orow + 4) = o1;
    }
}

// ---------------------------------------------------------------------------
extern "C" void kernel_launch(void* const* d_in, const int* in_sizes, int n_in,
                              void* d_out, int out_size)
{
    const float* nf       = (const float*)d_in[0];
    const int*   types    = (const int*)  d_in[1];
    const int*   ei       = (const int*)  d_in[2];
    const float* type_emb = (const float*)d_in[3];
    const float* proj_W   = (const float*)d_in[4];
    const float* proj_b   = (const float*)d_in[5];
    const float* W0       = (const float*)d_in[6];
    const float* att_s0   = (const float*)d_in[7];
    const float* att_d0   = (const float*)d_in[8];
    const float* bias0    = (const float*)d_in[9];
    const float* ln0_g    = (const float*)d_in[10];
    const float* ln0_b    = (const float*)d_in[11];
    const float* W1       = (const float*)d_in[12];
    const float* att_s1   = (const float*)d_in[13];
    const float* att_d1   = (const float*)d_in[14];
    const float* bias1    = (const float*)d_in[15];
    const float* ln1_g    = (const float*)d_in[16];
    const float* ln1_b    = (const float*)d_in[17];
    float* out = (float*)d_out;

    const int Nn = in_sizes[1];
    const int E  = in_sizes[2] / 2;

    __half *x16_p, *h16_p, *xp16_p, *pwh_p, *w0h_p, *w1h_p;
    float *as_p, *ad_p;
    int *counts_p;
    cudaGetSymbolAddress((void**)&x16_p,  g_x16);
    cudaGetSymbolAddress((void**)&h16_p,  g_h16);
    cudaGetSymbolAddress((void**)&xp16_p, g_xp16);
    cudaGetSymbolAddress((void**)&pwh_p,  g_pwh);
    cudaGetSymbolAddress((void**)&w0h_p,  g_w0h);
    cudaGetSymbolAddress((void**)&w1h_p,  g_w1h);
    cudaGetSymbolAddress((void**)&as_p,   g_as);
    cudaGetSymbolAddress((void**)&ad_p,   g_ad);
    cudaGetSymbolAddress((void**)&counts_p, g_counts);

    const int nodeWarpBlocks = (Nn + 7) / 8;
    const int scanBlocks = (Nn + SCAN_BLK - 1) / SCAN_BLK;

    // --- weight conversions (fp32 -> fp16) ---
    f2h_kernel<<<(64 * 64 / 2 + 255) / 256, 256>>>(proj_W, pwh_p, 64 * 64 / 2);
    f2h_kernel<<<(64 * 256 / 2 + 255) / 256, 256>>>(W0, w0h_p, 64 * 256 / 2);
    f2h_kernel<<<(256 * 256 / 2 + 255) / 256, 256>>>(W1, w1h_p, 256 * 256 / 2);

    // --- CSR build ---
    cudaMemsetAsync(counts_p, 0, (size_t)Nn * sizeof(int));
    hist_kernel<<<(E + 255) / 256, 256>>>(ei + E, E);

    // --- input projection (fp32 A converted inline, fused bias + type emb) ---
    {
        dim3 grid(1, (Nn + HBM_ - 1) / HBM_);
        hgemm_kernel<true, true, false><<<grid, 128>>>(
            nf, pwh_p, x16_p, Nn, 64, 64,
            proj_b, type_emb, types, nullptr, nullptr, nullptr, nullptr);
    }

    scan_p1_kernel<<<scanBlocks, SCAN_BLK>>>(Nn);
    scan_p2_kernel<<<1, SCAN_BLK>>>(scanBlocks, Nn);
    scan_p3_kernel<<<(Nn + 255) / 256, 256>>>(Nn);
    scatter_kernel<<<(E + Nn + 255) / 256, 256>>>(ei, E, Nn);

    // --- layer 0: GEMM + fused attn epilogue, then agg + LN + relu -> h16 ---
    {
        dim3 grid(4, (Nn + HBM_ - 1) / HBM_);
        hgemm_kernel<false, false, true><<<grid, 128>>>(
            x16_p, w0h_p, xp16_p, Nn, 64, 256,
            nullptr, nullptr, nullptr, att_s0, att_d0, as_p, ad_p);
    }
    gat_agg_ln0_kernel<<<nodeWarpBlocks, 256>>>(xp16_p, as_p, ad_p,
                                                bias0, ln0_g, ln0_b, h16_p, Nn);

    // --- layer 1: GEMM + fused attn, then agg + head-mean + LN -> out ---
    {
        dim3 grid(4, (Nn + HBM_ - 1) / HBM_);
        hgemm_kernel<false, false, true><<<grid, 128>>>(
            h16_p, w1h_p, xp16_p, Nn, 256, 256,
            nullptr, nullptr, nullptr, att_s1, att_d1, as_p, ad_p);
    }
    gat_agg_ln1_kernel<<<nodeWarpBlocks, 256>>>(xp16_p, as_p, ad_p,
                                                bias1, ln1_g, ln1_b, out, Nn);
}